// round 6
// baseline (speedup 1.0000x reference)
#include <cuda_runtime.h>
#include <cuda_bf16.h>
#include <math.h>
#include <stdint.h>

#define Bb 8
#define Nn 2048
#define Ee 32
#define Hc 128
#define Sc 256
#define Tt 12
#define NEL (Bb*Ee*Nn)
#define ALPHA 0.05f
#define EPSV 1e-5f
#define CRS 8

typedef unsigned long long u64;

// ---------------- packed fp32x2 helpers (for SIMT convs) ----------------
__device__ __forceinline__ u64 splat2(float a) {
    u64 d; asm("mov.b64 %0, {%1, %1};" : "=l"(d) : "f"(a)); return d;
}
__device__ __forceinline__ void upk2(u64 v, float& lo, float& hi) {
    asm("mov.b64 {%0, %1}, %2;" : "=f"(lo), "=f"(hi) : "l"(v));
}
__device__ __forceinline__ u64 fma2(u64 a, u64 b, u64 c) {
    u64 d; asm("fma.rn.f32x2 %0, %1, %2, %3;" : "=l"(d) : "l"(a), "l"(b), "l"(c)); return d;
}

// ---------------- warp-level bf16 MMA (baseline PTX, works on sm_103) --------
__device__ __forceinline__ void hmma(float4& d, uint32_t a0, uint32_t a1, uint32_t a2,
                                     uint32_t a3, uint32_t b0, uint32_t b1) {
    asm volatile(
        "mma.sync.aligned.m16n8k16.row.col.f32.bf16.bf16.f32 "
        "{%0,%1,%2,%3}, {%4,%5,%6,%7}, {%8,%9}, {%0,%1,%2,%3};"
        : "+f"(d.x), "+f"(d.y), "+f"(d.z), "+f"(d.w)
        : "r"(a0), "r"(a1), "r"(a2), "r"(a3), "r"(b0), "r"(b1));
}

// ---------------- device scratch ----------------
__device__ float g_x[NEL];
__device__ float g_xacc[NEL];
__device__ float g_h1[NEL];
__device__ float g_h2[NEL];
__device__ float g_hid[Bb*Hc*Nn];
__device__ float g_hid2[Bb*Hc*Nn];
__device__ float g_skip[Bb*Sc*Nn];
__device__ float g_rs_s[Nn];
__device__ float g_rs_d[Bb*Nn];
__device__ float g_cs_d[Bb*Nn];
__device__ float g_csp[CRS][Bb*Nn];
__device__ float g_stats[Bb*2];
// bf16 split copies of adjacency (hi + lo), plus transposed version for g2
__device__ __nv_bfloat16 g_Ahi[Bb*Nn*Nn];
__device__ __nv_bfloat16 g_Alo[Bb*Nn*Nn];
__device__ __nv_bfloat16 g_AThi[Bb*Nn*Nn];
__device__ __nv_bfloat16 g_ATlo[Bb*Nn*Nn];
__device__ __nv_bfloat16 g_Shi[Nn*Nn];
__device__ __nv_bfloat16 g_Slo[Nn*Nn];

struct Srcs { const float* p[8]; };

__device__ __forceinline__ void bsplit(float a, __nv_bfloat16& h, __nv_bfloat16& l) {
    h = __float2bfloat16(a);
    l = __float2bfloat16(a - __bfloat162float(h));
}
__device__ __forceinline__ uint32_t bpack(__nv_bfloat16 a, __nv_bfloat16 b) {
    __nv_bfloat162 t; t.x = a; t.y = b;
    return *reinterpret_cast<uint32_t*>(&t);
}

// ---------------- helpers ----------------
__device__ __forceinline__ float blockReduceSum(float v) {
    __shared__ float sh[32];
    int lane = threadIdx.x & 31, wid = threadIdx.x >> 5;
    #pragma unroll
    for (int o = 16; o; o >>= 1) v += __shfl_down_sync(0xffffffffu, v, o);
    __syncthreads();
    if (lane == 0) sh[wid] = v;
    __syncthreads();
    int nw = blockDim.x >> 5;
    v = (threadIdx.x < nw) ? sh[threadIdx.x] : 0.f;
    if (wid == 0) {
        #pragma unroll
        for (int o = 16; o; o >>= 1) v += __shfl_down_sync(0xffffffffu, v, o);
    }
    return v;
}

__global__ void copyk(float* __restrict__ dst, const float* __restrict__ src, int n) {
    int i = blockIdx.x * 256 + threadIdx.x;
    if (i < n) dst[i] = src[i];
}

// ---------------- prep: degree sums, bf16 conversion, transpose --------------
__global__ void rowsum_static(const float* __restrict__ S) {
    int v = blockIdx.x;
    float s = 0.f;
    for (int w = threadIdx.x; w < Nn; w += 256) s += S[(size_t)v * Nn + w];
    s = blockReduceSum(s);
    if (threadIdx.x == 0) g_rs_s[v] = s + 1.0f;
}

__global__ void rowsum_dy(const float* __restrict__ A) {
    int b = blockIdx.y, v = blockIdx.x;
    const float* row = A + ((size_t)b * Nn + v) * Nn;
    float s = 0.f;
    for (int w = threadIdx.x; w < Nn; w += 256) s += row[w];
    s = blockReduceSum(s);
    if (threadIdx.x == 0) g_rs_d[b * Nn + v] = s + 1.0f;
}

__global__ void colsum_dy(const float* __restrict__ A) {
    int b = blockIdx.y, z = blockIdx.z;
    int c = blockIdx.x * 256 + threadIdx.x;
    const float* Ab = A + (size_t)b * Nn * Nn + (size_t)(z * (Nn / CRS)) * Nn + c;
    float s = 0.f;
    #pragma unroll 8
    for (int r = 0; r < Nn / CRS; r++) s += Ab[(size_t)r * Nn];
    g_csp[z][b * Nn + c] = s;
}

__global__ void colsum_fin() {
    int i = blockIdx.x * 256 + threadIdx.x;
    float s = 1.0f;
    #pragma unroll
    for (int z = 0; z < CRS; z++) s += g_csp[z][i];
    g_cs_d[i] = s;
}

// f32 -> bf16 hi/lo split (element-wise, float4 granularity)
__global__ void cvtA_k(const float* __restrict__ A, __nv_bfloat16* __restrict__ hi,
                       __nv_bfloat16* __restrict__ lo, int n4) {
    int i = blockIdx.x * 256 + threadIdx.x;
    if (i >= n4) return;
    float4 a = ((const float4*)A)[i];
    __nv_bfloat16 h0, h1, h2, h3, l0, l1, l2, l3;
    bsplit(a.x, h0, l0); bsplit(a.y, h1, l1); bsplit(a.z, h2, l2); bsplit(a.w, h3, l3);
    ((uint2*)hi)[i] = make_uint2(bpack(h0, h1), bpack(h2, h3));
    ((uint2*)lo)[i] = make_uint2(bpack(l0, l1), bpack(l2, l3));
}

// transpose + split: AT[b][r][c] = A[b][c][r]
__global__ void transA_k(const float* __restrict__ A) {
    __shared__ float t[32][33];
    int b = blockIdx.z;
    int v0 = blockIdx.x * 32, w0 = blockIdx.y * 32;
    int tx = threadIdx.x, ty = threadIdx.y;
    for (int i = ty; i < 32; i += 8)
        t[i][tx] = A[((size_t)b * Nn + v0 + i) * Nn + w0 + tx];
    __syncthreads();
    for (int i = ty; i < 32; i += 8) {
        float a = t[tx][i];   // = A[b, v0+tx, w0+i]
        __nv_bfloat16 h, l; bsplit(a, h, l);
        size_t o = ((size_t)b * Nn + w0 + i) * Nn + v0 + tx;
        g_AThi[o] = h;
        g_ATlo[o] = l;
    }
}

// ---------------- HMMA SpMM with fused mixprop hop epilogue ------------------
// D[v,c] = sum_w M[v,w]*h[c,w] (M given as bf16 hi/lo, 3-term product), then
// hout = ALPHA*x + (1-ALPHA)*(D + hin)/den.
// Block: 128 threads (4 warps). Tile 64v x 32c. Warp: 16v x 32c. K chunk 64.
#define AP 72   // smem pitch in bf16 units
__global__ void __launch_bounds__(128) spmm_mma(
        const __nv_bfloat16* __restrict__ Ahi, const __nv_bfloat16* __restrict__ Alo,
        size_t aBStride,
        const float* __restrict__ hin, const float* __restrict__ xin,
        const float* __restrict__ den, int denB, float* __restrict__ hout) {
    __shared__ __nv_bfloat16 sAh[64 * AP];
    __shared__ __nv_bfloat16 sAl[64 * AP];
    __shared__ __nv_bfloat16 sHh[32 * AP];
    __shared__ __nv_bfloat16 sHl[32 * AP];

    const int tid = threadIdx.x, wid = tid >> 5, lane = tid & 31;
    const int g = lane >> 2, tg = lane & 3;
    const int vt = blockIdx.x, b = blockIdx.y;
    const int v0 = vt * 64;

    const __nv_bfloat16* Ah = Ahi + (size_t)b * aBStride;
    const __nv_bfloat16* Al = Alo + (size_t)b * aBStride;
    const float* hb = hin + (size_t)b * Ee * Nn;

    float4 acc[4] = {};   // per-warp: 4 n-tiles of 16v x 8c

    for (int ch = 0; ch < 32; ch++) {
        const int w0 = ch * 64;
        // --- stage A hi/lo: 64v x 64w bf16, 8 bf16 per unit, 512 units/array ---
        #pragma unroll
        for (int r = 0; r < 4; r++) {
            int t = tid + r * 128;
            int row = t >> 3, u = t & 7;
            size_t gi = (size_t)(v0 + row) * Nn + w0 + u * 8;
            *(uint4*)&sAh[row * AP + u * 8] = *(const uint4*)(Ah + gi);
            *(uint4*)&sAl[row * AP + u * 8] = *(const uint4*)(Al + gi);
        }
        // --- stage H hi/lo: 32c x 64w, convert f32 -> split on the fly ---
        #pragma unroll
        for (int r = 0; r < 2; r++) {
            int t = tid + r * 128;
            int c = t >> 3, u = t & 7;
            const float* hp = hb + (size_t)c * Nn + w0 + u * 8;
            float4 f0 = *(const float4*)(hp);
            float4 f1 = *(const float4*)(hp + 4);
            __nv_bfloat16 h[8], l[8];
            bsplit(f0.x, h[0], l[0]); bsplit(f0.y, h[1], l[1]);
            bsplit(f0.z, h[2], l[2]); bsplit(f0.w, h[3], l[3]);
            bsplit(f1.x, h[4], l[4]); bsplit(f1.y, h[5], l[5]);
            bsplit(f1.z, h[6], l[6]); bsplit(f1.w, h[7], l[7]);
            uint4 ph = make_uint4(bpack(h[0], h[1]), bpack(h[2], h[3]),
                                  bpack(h[4], h[5]), bpack(h[6], h[7]));
            uint4 pl = make_uint4(bpack(l[0], l[1]), bpack(l[2], l[3]),
                                  bpack(l[4], l[5]), bpack(l[6], l[7]));
            *(uint4*)&sHh[c * AP + u * 8] = ph;
            *(uint4*)&sHl[c * AP + u * 8] = pl;
        }
        __syncthreads();
        // --- compute: 4 k16 steps ---
        #pragma unroll
        for (int ks = 0; ks < 4; ks++) {
            const int k0 = ks * 16;
            const int ra = wid * 16;   // warp's v rows within tile
            uint32_t ah0 = *(const uint32_t*)&sAh[(ra + g) * AP + k0 + 2 * tg];
            uint32_t ah1 = *(const uint32_t*)&sAh[(ra + 8 + g) * AP + k0 + 2 * tg];
            uint32_t ah2 = *(const uint32_t*)&sAh[(ra + g) * AP + k0 + 8 + 2 * tg];
            uint32_t ah3 = *(const uint32_t*)&sAh[(ra + 8 + g) * AP + k0 + 8 + 2 * tg];
            uint32_t al0 = *(const uint32_t*)&sAl[(ra + g) * AP + k0 + 2 * tg];
            uint32_t al1 = *(const uint32_t*)&sAl[(ra + 8 + g) * AP + k0 + 2 * tg];
            uint32_t al2 = *(const uint32_t*)&sAl[(ra + g) * AP + k0 + 8 + 2 * tg];
            uint32_t al3 = *(const uint32_t*)&sAl[(ra + 8 + g) * AP + k0 + 8 + 2 * tg];
            #pragma unroll
            for (int nt = 0; nt < 4; nt++) {
                int hr = nt * 8 + g;
                uint32_t bh0 = *(const uint32_t*)&sHh[hr * AP + k0 + 2 * tg];
                uint32_t bh1 = *(const uint32_t*)&sHh[hr * AP + k0 + 8 + 2 * tg];
                uint32_t bl0 = *(const uint32_t*)&sHl[hr * AP + k0 + 2 * tg];
                uint32_t bl1 = *(const uint32_t*)&sHl[hr * AP + k0 + 8 + 2 * tg];
                hmma(acc[nt], ah0, ah1, ah2, ah3, bh0, bh1);  // hi*hi
                hmma(acc[nt], ah0, ah1, ah2, ah3, bl0, bl1);  // hi*lo
                hmma(acc[nt], al0, al1, al2, al3, bh0, bh1);  // lo*hi
            }
        }
        __syncthreads();
    }

    // --- fused epilogue: hout = ALPHA*x + (1-ALPHA)*(D + hin)/den ---
    const int vlo = v0 + wid * 16 + g;
    const int vhi = vlo + 8;
    const float dn_lo = den[denB * b + vlo];
    const float dn_hi = den[denB * b + vhi];
    const float* xb = xin + (size_t)b * Ee * Nn;
    float* ob = hout + (size_t)b * Ee * Nn;
    #pragma unroll
    for (int nt = 0; nt < 4; nt++) {
        int c0 = nt * 8 + 2 * tg;
        size_t i00 = (size_t)c0 * Nn + vlo;
        size_t i01 = (size_t)(c0 + 1) * Nn + vlo;
        size_t i10 = (size_t)c0 * Nn + vhi;
        size_t i11 = (size_t)(c0 + 1) * Nn + vhi;
        ob[i00] = ALPHA * xb[i00] + (1.0f - ALPHA) * ((acc[nt].x + hb[i00]) / dn_lo);
        ob[i01] = ALPHA * xb[i01] + (1.0f - ALPHA) * ((acc[nt].y + hb[i01]) / dn_lo);
        ob[i10] = ALPHA * xb[i10] + (1.0f - ALPHA) * ((acc[nt].z + hb[i10]) / dn_hi);
        ob[i11] = ALPHA * xb[i11] + (1.0f - ALPHA) * ((acc[nt].w + hb[i11]) / dn_hi);
    }
}

// ---------------- generic 1x1 conv (channel-mix GEMM), f32x2 packed ----------
__global__ void conv1x1_k(Srcs srcs, int inBStride,
                          const float* __restrict__ W, const float* __restrict__ bias,
                          int M, int K, float* __restrict__ out, int outBStride, int accFlag) {
    __shared__ float Ws[16 * 68];
    __shared__ float Ins[16 * 68];
    const int tid = threadIdx.x;
    const int tx = tid & 15, ty = tid >> 4;
    const int col0 = blockIdx.x * 64;
    const int b = col0 / Nn, n0 = col0 % Nn;
    const int m0 = blockIdx.y * 64;

    u64 accP[4][2] = {};

    for (int k0 = 0; k0 < K; k0 += 16) {
        for (int t = tid; t < 1024; t += 256) {
            int m = t >> 4, kk = t & 15;
            Ws[kk * 68 + m] = (m0 + m < M) ? W[(size_t)(m0 + m) * K + k0 + kk] : 0.f;
        }
        for (int t = tid; t < 1024; t += 256) {
            int kk = t >> 6, n = t & 63;
            int c = k0 + kk;
            Ins[kk * 68 + n] = srcs.p[c >> 5][(size_t)b * inBStride + (size_t)(c & 31) * Nn + n0 + n];
        }
        __syncthreads();
        #pragma unroll
        for (int kk = 0; kk < 16; kk++) {
            float4 wv = *(const float4*)&Ws[kk * 68 + ty * 4];
            u64 ip0 = *(const u64*)&Ins[kk * 68 + tx * 4];
            u64 ip1 = *(const u64*)&Ins[kk * 68 + tx * 4 + 2];
            float wa[4] = {wv.x, wv.y, wv.z, wv.w};
            #pragma unroll
            for (int u = 0; u < 4; u++) {
                u64 wp = splat2(wa[u]);
                accP[u][0] = fma2(wp, ip0, accP[u][0]);
                accP[u][1] = fma2(wp, ip1, accP[u][1]);
            }
        }
        __syncthreads();
    }
    #pragma unroll
    for (int u = 0; u < 4; u++) {
        int m = m0 + ty * 4 + u;
        if (m >= M) break;
        float bm = bias[m];
        float4 r;
        upk2(accP[u][0], r.x, r.y);
        upk2(accP[u][1], r.z, r.w);
        r.x += bm; r.y += bm; r.z += bm; r.w += bm;
        float* dst = &out[(size_t)b * outBStride + (size_t)m * Nn + n0 + tx * 4];
        if (accFlag) {
            float4 o = *(float4*)dst;
            r.x += o.x; r.y += o.y; r.z += o.z; r.w += o.w;
        }
        *(float4*)dst = r;
    }
}

// ---------------- gated TCN unit ----------------
__global__ void gated_conv_k(Srcs srcs, int inBStride,
                             const float* __restrict__ Wf, const float* __restrict__ bf,
                             const float* __restrict__ Wg, const float* __restrict__ bg,
                             float* __restrict__ out) {
    __shared__ float Wfs[16 * 68];
    __shared__ float Wgs[16 * 68];
    __shared__ float Ins[16 * 68];
    const int tid = threadIdx.x;
    const int tx = tid & 15, ty = tid >> 4;
    const int col0 = blockIdx.x * 64;
    const int b = col0 / Nn, n0 = col0 % Nn;
    const int m0 = blockIdx.y * 64;

    u64 accF[4][2] = {};
    u64 accG[4][2] = {};

    for (int k0 = 0; k0 < Hc; k0 += 16) {
        for (int t = tid; t < 1024; t += 256) {
            int m = t >> 4, kk = t & 15;
            Wfs[kk * 68 + m] = Wf[(size_t)(m0 + m) * Hc + k0 + kk];
            Wgs[kk * 68 + m] = Wg[(size_t)(m0 + m) * Hc + k0 + kk];
        }
        for (int t = tid; t < 1024; t += 256) {
            int kk = t >> 6, n = t & 63;
            int c = k0 + kk;
            Ins[kk * 68 + n] = srcs.p[c >> 5][(size_t)b * inBStride + (size_t)(c & 31) * Nn + n0 + n];
        }
        __syncthreads();
        #pragma unroll
        for (int kk = 0; kk < 16; kk++) {
            float4 fv = *(const float4*)&Wfs[kk * 68 + ty * 4];
            float4 gv = *(const float4*)&Wgs[kk * 68 + ty * 4];
            u64 ip0 = *(const u64*)&Ins[kk * 68 + tx * 4];
            u64 ip1 = *(const u64*)&Ins[kk * 68 + tx * 4 + 2];
            float fa[4] = {fv.x, fv.y, fv.z, fv.w};
            float ga[4] = {gv.x, gv.y, gv.z, gv.w};
            #pragma unroll
            for (int u = 0; u < 4; u++) {
                u64 fp = splat2(fa[u]);
                u64 gp = splat2(ga[u]);
                accF[u][0] = fma2(fp, ip0, accF[u][0]);
                accF[u][1] = fma2(fp, ip1, accF[u][1]);
                accG[u][0] = fma2(gp, ip0, accG[u][0]);
                accG[u][1] = fma2(gp, ip1, accG[u][1]);
            }
        }
        __syncthreads();
    }
    #pragma unroll
    for (int u = 0; u < 4; u++) {
        int m = m0 + ty * 4 + u;
        float bfm = bf[m], bgm = bg[m];
        float ff[4], gg[4];
        upk2(accF[u][0], ff[0], ff[1]);
        upk2(accF[u][1], ff[2], ff[3]);
        upk2(accG[u][0], gg[0], gg[1]);
        upk2(accG[u][1], gg[2], gg[3]);
        float4 r;
        float f, s;
        f = tanhf(ff[0] + bfm); s = 1.f / (1.f + expf(-(gg[0] + bgm))); r.x = f * s;
        f = tanhf(ff[1] + bfm); s = 1.f / (1.f + expf(-(gg[1] + bgm))); r.y = f * s;
        f = tanhf(ff[2] + bfm); s = 1.f / (1.f + expf(-(gg[2] + bgm))); r.z = f * s;
        f = tanhf(ff[3] + bfm); s = 1.f / (1.f + expf(-(gg[3] + bgm))); r.w = f * s;
        *(float4*)&out[(size_t)b * Hc * Nn + (size_t)m * Nn + n0 + tx * 4] = r;
    }
}

// ---------------- layernorm ----------------
__global__ void ln_stats_k() {
    int b = blockIdx.x;
    const float* xp = g_xacc + (size_t)b * Ee * Nn;
    float s = 0.f, s2 = 0.f;
    for (int i = threadIdx.x; i < Ee * Nn; i += blockDim.x) {
        float v = xp[i];
        s += v; s2 += v * v;
    }
    float ts = blockReduceSum(s);
    float ts2 = blockReduceSum(s2);
    if (threadIdx.x == 0) {
        float inv = 1.0f / (Ee * Nn);
        float mu = ts * inv;
        g_stats[b * 2] = mu;
        g_stats[b * 2 + 1] = ts2 * inv - mu * mu;
    }
}

__global__ void ln_apply_k(const float* __restrict__ w, const float* __restrict__ bparm) {
    int i = blockIdx.x * 256 + threadIdx.x;
    if (i >= NEL) return;
    int b = i / (Ee * Nn);
    int cn = i % (Ee * Nn);
    float mu = g_stats[b * 2];
    float var = g_stats[b * 2 + 1];
    float val = (g_xacc[i] - mu) * rsqrtf(var + EPSV) * w[cn] + bparm[cn];
    g_x[i] = fmaxf(val, 0.f);
}

// ---------------- host orchestration ----------------
extern "C" void kernel_launch(void* const* d_in, const int* in_sizes, int n_in,
                              void* d_out, int out_size) {
    (void)in_sizes; (void)n_in; (void)out_size;
    const float* in_x  = (const float*)d_in[0];
    const float* dyG   = (const float*)d_in[1];
    const float* stG   = (const float*)d_in[2];
    const float* spE   = (const float*)d_in[3];
    const float* tdE   = (const float*)d_in[4];
    const float* twE   = (const float*)d_in[5];
    const float* encWf = (const float*)d_in[6];
    const float* encbf = (const float*)d_in[7];
    const float* encWg = (const float*)d_in[8];
    const float* encbg = (const float*)d_in[9];
    const float* skW   = (const float*)d_in[10];
    const float* skb   = (const float*)d_in[11];
    const float* nw    = (const float*)d_in[12];
    const float* nb    = (const float*)d_in[13];
    const float* gW[3] = {(const float*)d_in[14], (const float*)d_in[16], (const float*)d_in[18]};
    const float* gb[3] = {(const float*)d_in[15], (const float*)d_in[17], (const float*)d_in[19]};
    const float* seW   = (const float*)d_in[20];
    const float* seb   = (const float*)d_in[21];
    const float* eW    = (const float*)d_in[22];
    const float* eb    = (const float*)d_in[23];
    float* outp = (float*)d_out;

    float *px, *pxacc, *ph1, *ph2, *phid, *phid2, *pskip, *prss, *prsd, *pcsd;
    cudaGetSymbolAddress((void**)&px,    g_x);
    cudaGetSymbolAddress((void**)&pxacc, g_xacc);
    cudaGetSymbolAddress((void**)&ph1,   g_h1);
    cudaGetSymbolAddress((void**)&ph2,   g_h2);
    cudaGetSymbolAddress((void**)&phid,  g_hid);
    cudaGetSymbolAddress((void**)&phid2, g_hid2);
    cudaGetSymbolAddress((void**)&pskip, g_skip);
    cudaGetSymbolAddress((void**)&prss,  g_rs_s);
    cudaGetSymbolAddress((void**)&prsd,  g_rs_d);
    cudaGetSymbolAddress((void**)&pcsd,  g_cs_d);
    __nv_bfloat16 *pAhi, *pAlo, *pAThi, *pATlo, *pShi, *pSlo;
    cudaGetSymbolAddress((void**)&pAhi,  g_Ahi);
    cudaGetSymbolAddress((void**)&pAlo,  g_Alo);
    cudaGetSymbolAddress((void**)&pAThi, g_AThi);
    cudaGetSymbolAddress((void**)&pATlo, g_ATlo);
    cudaGetSymbolAddress((void**)&pShi,  g_Shi);
    cudaGetSymbolAddress((void**)&pSlo,  g_Slo);

    // prep: copy x, degree sums, bf16 conversion + transpose of adjacency
    copyk<<<NEL / 256, 256>>>(px, in_x, NEL);
    rowsum_static<<<Nn, 256>>>(stG);
    rowsum_dy<<<dim3(Nn, Bb), 256>>>(dyG);
    colsum_dy<<<dim3(Nn / 256, Bb, CRS), 256>>>(dyG);
    colsum_fin<<<Bb * Nn / 256, 256>>>();
    cvtA_k<<<(Bb * Nn * Nn / 4 + 255) / 256, 256>>>(dyG, pAhi, pAlo, Bb * Nn * Nn / 4);
    cvtA_k<<<(Nn * Nn / 4 + 255) / 256, 256>>>(stG, pShi, pSlo, Nn * Nn / 4);
    transA_k<<<dim3(Nn / 32, Nn / 32, Bb), dim3(32, 8)>>>(dyG);

    const dim3 convGrid(Bb * Nn / 64, 1);
    const dim3 spmmGrid(Nn / 64, Bb);
    for (int i = 0; i < 3; i++) {
        // ---- TCN chain ----
        Srcs s1; s1.p[0] = px; s1.p[1] = spE; s1.p[2] = tdE; s1.p[3] = twE;
        gated_conv_k<<<dim3(Bb * Nn / 64, 2), 256>>>(s1, Ee * Nn,
            encWf + (size_t)(i * 2 + 0) * Hc * Hc, encbf + (i * 2 + 0) * Hc,
            encWg + (size_t)(i * 2 + 0) * Hc * Hc, encbg + (i * 2 + 0) * Hc, phid);
        Srcs s2; for (int s = 0; s < 4; s++) s2.p[s] = phid + (size_t)s * 32 * Nn;
        gated_conv_k<<<dim3(Bb * Nn / 64, 2), 256>>>(s2, Hc * Nn,
            encWf + (size_t)(i * 2 + 1) * Hc * Hc, encbf + (i * 2 + 1) * Hc,
            encWg + (size_t)(i * 2 + 1) * Hc * Hc, encbg + (i * 2 + 1) * Hc, phid2);
        // ---- skip += skip_W @ hidden ----
        Srcs s3; for (int s = 0; s < 4; s++) s3.p[s] = phid2 + (size_t)s * 32 * Nn;
        conv1x1_k<<<dim3(Bb * Nn / 64, 4), 256>>>(s3, Hc * Nn,
            skW + (size_t)i * Sc * Hc, skb + i * Sc, Sc, Hc, pskip, Sc * Nn, i > 0);
        // ---- mixprops ----
        copyk<<<NEL / 256, 256>>>(pxacc, px, NEL);
        for (int g = 0; g < 3; g++) {
            const __nv_bfloat16* Ah = (g == 0) ? pShi : (g == 1 ? pAhi : pAThi);
            const __nv_bfloat16* Al = (g == 0) ? pSlo : (g == 1 ? pAlo : pATlo);
            size_t abst = (g == 0) ? 0 : (size_t)Nn * Nn;
            const float* den = (g == 0) ? prss : (g == 1 ? prsd : pcsd);
            int denB = (g == 0) ? 0 : Nn;
            spmm_mma<<<spmmGrid, 128>>>(Ah, Al, abst, px, px, den, denB, ph1);
            spmm_mma<<<spmmGrid, 128>>>(Ah, Al, abst, ph1, px, den, denB, ph2);
            Srcs sm; sm.p[0] = px; sm.p[1] = ph1; sm.p[2] = ph2;
            conv1x1_k<<<convGrid, 256>>>(sm, Ee * Nn,
                gW[g] + (size_t)i * Ee * 96, gb[g] + i * Ee, Ee, 96, pxacc, Ee * Nn, 1);
        }
        // ---- layernorm + relu -> new x ----
        ln_stats_k<<<Bb, 1024>>>();
        ln_apply_k<<<NEL / 256, 256>>>(nw + (size_t)i * Ee * Nn, nb + (size_t)i * Ee * Nn);
    }
    // ---- skip end + output ----
    Srcs se; se.p[0] = px;
    conv1x1_k<<<dim3(Bb * Nn / 64, 4), 256>>>(se, Ee * Nn, seW, seb, Sc, Ee, pskip, Sc * Nn, 1);
    Srcs send; for (int s = 0; s < 8; s++) send.p[s] = pskip + (size_t)s * 32 * Nn;
    conv1x1_k<<<convGrid, 256>>>(send, Sc * Nn, eW, eb, Tt, Sc, outp, Tt * Nn, 0);
}

// round 7
// speedup vs baseline: 1.4412x; 1.4412x over previous
#include <cuda_runtime.h>
#include <cuda_bf16.h>
#include <math.h>
#include <stdint.h>

#define Bb 8
#define Nn 2048
#define Ee 32
#define Hc 128
#define Sc 256
#define Tt 12
#define NEL (Bb*Ee*Nn)
#define ALPHA 0.05f
#define EPSV 1e-5f
#define CRS 8
#define AP 72   // smem pitch in bf16 units (144B: conflict-free for ldmatrix)

typedef unsigned long long u64;

// ---------------- packed fp32x2 helpers (for SIMT convs) ----------------
__device__ __forceinline__ u64 splat2(float a) {
    u64 d; asm("mov.b64 %0, {%1, %1};" : "=l"(d) : "f"(a)); return d;
}
__device__ __forceinline__ void upk2(u64 v, float& lo, float& hi) {
    asm("mov.b64 {%0, %1}, %2;" : "=f"(lo), "=f"(hi) : "l"(v));
}
__device__ __forceinline__ u64 fma2(u64 a, u64 b, u64 c) {
    u64 d; asm("fma.rn.f32x2 %0, %1, %2, %3;" : "=l"(d) : "l"(a), "l"(b), "l"(c)); return d;
}

// ---------------- warp-level bf16 MMA + ldmatrix ----------------
__device__ __forceinline__ void hmma(float4& d, uint32_t a0, uint32_t a1, uint32_t a2,
                                     uint32_t a3, uint32_t b0, uint32_t b1) {
    asm volatile(
        "mma.sync.aligned.m16n8k16.row.col.f32.bf16.bf16.f32 "
        "{%0,%1,%2,%3}, {%4,%5,%6,%7}, {%8,%9}, {%0,%1,%2,%3};"
        : "+f"(d.x), "+f"(d.y), "+f"(d.z), "+f"(d.w)
        : "r"(a0), "r"(a1), "r"(a2), "r"(a3), "r"(b0), "r"(b1));
}
__device__ __forceinline__ void ldm4(uint32_t& r0, uint32_t& r1, uint32_t& r2, uint32_t& r3,
                                     uint32_t addr) {
    asm volatile("ldmatrix.sync.aligned.m8n8.x4.shared.b16 {%0,%1,%2,%3}, [%4];"
        : "=r"(r0), "=r"(r1), "=r"(r2), "=r"(r3) : "r"(addr));
}
__device__ __forceinline__ uint32_t smem_u32(const void* p) {
    uint32_t a;
    asm("{ .reg .u64 t; cvta.to.shared.u64 t, %1; cvt.u32.u64 %0, t; }" : "=r"(a) : "l"(p));
    return a;
}

// ---------------- device scratch ----------------
__device__ float g_x[NEL];
__device__ float g_xacc[NEL];
__device__ float g_h1[NEL];
__device__ float g_h2[NEL];
__device__ float g_hid[Bb*Hc*Nn];
__device__ float g_hid2[Bb*Hc*Nn];
__device__ float g_skip[Bb*Sc*Nn];
__device__ float g_rs_s[Nn];
__device__ float g_rs_d[Bb*Nn];
__device__ float g_cs_d[Bb*Nn];
__device__ float g_csp[CRS][Bb*Nn];
__device__ float g_stats[Bb*2];
__device__ __nv_bfloat16 g_Ahi[Bb*Nn*Nn];
__device__ __nv_bfloat16 g_Alo[Bb*Nn*Nn];
__device__ __nv_bfloat16 g_AThi[Bb*Nn*Nn];
__device__ __nv_bfloat16 g_ATlo[Bb*Nn*Nn];
__device__ __nv_bfloat16 g_Shi[Nn*Nn];
__device__ __nv_bfloat16 g_Slo[Nn*Nn];
__device__ __nv_bfloat16 g_hHi[NEL];
__device__ __nv_bfloat16 g_hLo[NEL];

struct Srcs { const float* p[8]; };

__device__ __forceinline__ void bsplit(float a, __nv_bfloat16& h, __nv_bfloat16& l) {
    h = __float2bfloat16(a);
    l = __float2bfloat16(a - __bfloat162float(h));
}
__device__ __forceinline__ uint32_t bpack(__nv_bfloat16 a, __nv_bfloat16 b) {
    __nv_bfloat162 t; t.x = a; t.y = b;
    return *reinterpret_cast<uint32_t*>(&t);
}

// ---------------- helpers ----------------
__device__ __forceinline__ float blockReduceSum(float v) {
    __shared__ float sh[32];
    int lane = threadIdx.x & 31, wid = threadIdx.x >> 5;
    #pragma unroll
    for (int o = 16; o; o >>= 1) v += __shfl_down_sync(0xffffffffu, v, o);
    __syncthreads();
    if (lane == 0) sh[wid] = v;
    __syncthreads();
    int nw = blockDim.x >> 5;
    v = (threadIdx.x < nw) ? sh[threadIdx.x] : 0.f;
    if (wid == 0) {
        #pragma unroll
        for (int o = 16; o; o >>= 1) v += __shfl_down_sync(0xffffffffu, v, o);
    }
    return v;
}

__global__ void copyk(float* __restrict__ dst, const float* __restrict__ src, int n) {
    int i = blockIdx.x * 256 + threadIdx.x;
    if (i < n) dst[i] = src[i];
}

// ---------------- prep kernels ----------------
__global__ void rowsum_static(const float* __restrict__ S) {
    int v = blockIdx.x;
    float s = 0.f;
    for (int w = threadIdx.x; w < Nn; w += 256) s += S[(size_t)v * Nn + w];
    s = blockReduceSum(s);
    if (threadIdx.x == 0) g_rs_s[v] = s + 1.0f;
}

__global__ void rowsum_dy(const float* __restrict__ A) {
    int b = blockIdx.y, v = blockIdx.x;
    const float* row = A + ((size_t)b * Nn + v) * Nn;
    float s = 0.f;
    for (int w = threadIdx.x; w < Nn; w += 256) s += row[w];
    s = blockReduceSum(s);
    if (threadIdx.x == 0) g_rs_d[b * Nn + v] = s + 1.0f;
}

__global__ void colsum_dy(const float* __restrict__ A) {
    int b = blockIdx.y, z = blockIdx.z;
    int c = blockIdx.x * 256 + threadIdx.x;
    const float* Ab = A + (size_t)b * Nn * Nn + (size_t)(z * (Nn / CRS)) * Nn + c;
    float s = 0.f;
    #pragma unroll 8
    for (int r = 0; r < Nn / CRS; r++) s += Ab[(size_t)r * Nn];
    g_csp[z][b * Nn + c] = s;
}

__global__ void colsum_fin() {
    int i = blockIdx.x * 256 + threadIdx.x;
    float s = 1.0f;
    #pragma unroll
    for (int z = 0; z < CRS; z++) s += g_csp[z][i];
    g_cs_d[i] = s;
}

__global__ void cvtA_k(const float* __restrict__ A, __nv_bfloat16* __restrict__ hi,
                       __nv_bfloat16* __restrict__ lo, int n4) {
    int i = blockIdx.x * 256 + threadIdx.x;
    if (i >= n4) return;
    float4 a = ((const float4*)A)[i];
    __nv_bfloat16 h0, h1, h2, h3, l0, l1, l2, l3;
    bsplit(a.x, h0, l0); bsplit(a.y, h1, l1); bsplit(a.z, h2, l2); bsplit(a.w, h3, l3);
    ((uint2*)hi)[i] = make_uint2(bpack(h0, h1), bpack(h2, h3));
    ((uint2*)lo)[i] = make_uint2(bpack(l0, l1), bpack(l2, l3));
}

__global__ void transA_k(const float* __restrict__ A) {
    __shared__ float t[32][33];
    int b = blockIdx.z;
    int v0 = blockIdx.x * 32, w0 = blockIdx.y * 32;
    int tx = threadIdx.x, ty = threadIdx.y;
    for (int i = ty; i < 32; i += 8)
        t[i][tx] = A[((size_t)b * Nn + v0 + i) * Nn + w0 + tx];
    __syncthreads();
    for (int i = ty; i < 32; i += 8) {
        float a = t[tx][i];
        __nv_bfloat16 h, l; bsplit(a, h, l);
        size_t o = ((size_t)b * Nn + w0 + i) * Nn + v0 + tx;
        g_AThi[o] = h;
        g_ATlo[o] = l;
    }
}

// split h (fp32) -> bf16 hi/lo, whole tensor
__global__ void hsplit_k(const float* __restrict__ h) {
    int i = blockIdx.x * 256 + threadIdx.x;
    if (i >= NEL / 4) return;
    float4 a = ((const float4*)h)[i];
    __nv_bfloat16 h0, h1, h2, h3, l0, l1, l2, l3;
    bsplit(a.x, h0, l0); bsplit(a.y, h1, l1); bsplit(a.z, h2, l2); bsplit(a.w, h3, l3);
    ((uint2*)g_hHi)[i] = make_uint2(bpack(h0, h1), bpack(h2, h3));
    ((uint2*)g_hLo)[i] = make_uint2(bpack(l0, l1), bpack(l2, l3));
}

// ---------------- HMMA SpMM with fused mixprop hop epilogue ------------------
// D[v,c] = sum_w M[v,w]*h[c,w] (bf16 hi/lo 3-term), then
// hout = ALPHA*x + (1-ALPHA)*(D + hin)/den.
// Block 256 threads (8 warps), tile 64v x 32c; warp = 16v x 16c. K chunk 64.
// Register-prefetched staging + ldmatrix fragment loads.
__global__ void __launch_bounds__(256) spmm_mma(
        const __nv_bfloat16* __restrict__ Ahi, const __nv_bfloat16* __restrict__ Alo,
        size_t aBStride,
        const float* __restrict__ hin, const float* __restrict__ xin,
        const float* __restrict__ den, int denB, float* __restrict__ hout) {
    __shared__ __nv_bfloat16 sAh[64 * AP];
    __shared__ __nv_bfloat16 sAl[64 * AP];
    __shared__ __nv_bfloat16 sHh[32 * AP];
    __shared__ __nv_bfloat16 sHl[32 * AP];

    const int tid = threadIdx.x, wid = tid >> 5, lane = tid & 31;
    const int g = lane >> 2, tg = lane & 3;
    const int vt = blockIdx.x, b = blockIdx.y;
    const int v0 = vt * 64;
    const int warpV = (wid >> 1) * 16;        // warp's v offset in tile
    const int c0w = (wid & 1) * 16;           // warp's c offset

    const __nv_bfloat16* Ah = Ahi + (size_t)b * aBStride;
    const __nv_bfloat16* Al = Alo + (size_t)b * aBStride;
    const __nv_bfloat16* Hh = g_hHi + (size_t)b * Ee * Nn;
    const __nv_bfloat16* Hl = g_hLo + (size_t)b * Ee * Nn;
    const float* hb = hin + (size_t)b * Ee * Nn;

    // ldmatrix per-lane source addresses (bytes, shared state space)
    const uint32_t sAh_u = smem_u32(sAh), sAl_u = smem_u32(sAl);
    const uint32_t sHh_u = smem_u32(sHh), sHl_u = smem_u32(sHl);
    const int rowA = warpV + (lane & 15);
    const int khA  = (lane >> 4) * 8;
    const uint32_t offA = (uint32_t)(rowA * AP + khA) * 2;
    const int rowB = c0w + (lane & 7) + ((lane >> 4) & 1) * 8;
    const int khB  = ((lane >> 3) & 1) * 8;
    const uint32_t offB = (uint32_t)(rowB * AP + khB) * 2;

    float4 acc[2] = {};                       // [nt]: 16v x 8c each

    // staging decomposition: A: 512 uint4 (2/thread), H: 256 uint4 (1/thread)
    int ar0 = tid >> 3,           au0 = tid & 7;
    int ar1 = (tid + 256) >> 3,   au1 = tid & 7;
    int hc  = tid >> 3,           hu = tid & 7;

    uint4 pAh0, pAh1, pAl0, pAl1, pHh, pHl;
    {
        const int w0 = 0;
        pAh0 = *(const uint4*)(Ah + (size_t)(v0 + ar0) * Nn + w0 + au0 * 8);
        pAh1 = *(const uint4*)(Ah + (size_t)(v0 + ar1) * Nn + w0 + au1 * 8);
        pAl0 = *(const uint4*)(Al + (size_t)(v0 + ar0) * Nn + w0 + au0 * 8);
        pAl1 = *(const uint4*)(Al + (size_t)(v0 + ar1) * Nn + w0 + au1 * 8);
        pHh  = *(const uint4*)(Hh + (size_t)hc * Nn + w0 + hu * 8);
        pHl  = *(const uint4*)(Hl + (size_t)hc * Nn + w0 + hu * 8);
    }

    for (int ch = 0; ch < 32; ch++) {
        __syncthreads();
        *(uint4*)&sAh[ar0 * AP + au0 * 8] = pAh0;
        *(uint4*)&sAh[ar1 * AP + au1 * 8] = pAh1;
        *(uint4*)&sAl[ar0 * AP + au0 * 8] = pAl0;
        *(uint4*)&sAl[ar1 * AP + au1 * 8] = pAl1;
        *(uint4*)&sHh[hc * AP + hu * 8] = pHh;
        *(uint4*)&sHl[hc * AP + hu * 8] = pHl;
        if (ch < 31) {
            const int w0 = (ch + 1) * 64;
            pAh0 = *(const uint4*)(Ah + (size_t)(v0 + ar0) * Nn + w0 + au0 * 8);
            pAh1 = *(const uint4*)(Ah + (size_t)(v0 + ar1) * Nn + w0 + au1 * 8);
            pAl0 = *(const uint4*)(Al + (size_t)(v0 + ar0) * Nn + w0 + au0 * 8);
            pAl1 = *(const uint4*)(Al + (size_t)(v0 + ar1) * Nn + w0 + au1 * 8);
            pHh  = *(const uint4*)(Hh + (size_t)hc * Nn + w0 + hu * 8);
            pHl  = *(const uint4*)(Hl + (size_t)hc * Nn + w0 + hu * 8);
        }
        __syncthreads();
        #pragma unroll
        for (int ks = 0; ks < 4; ks++) {
            const uint32_t ko = ks * 32;     // 16 bf16 = 32 bytes
            uint32_t ah0, ah1, ah2, ah3, al0, al1, al2, al3;
            uint32_t bh00, bh01, bh10, bh11, bl00, bl01, bl10, bl11;
            ldm4(ah0, ah1, ah2, ah3, sAh_u + offA + ko);
            ldm4(al0, al1, al2, al3, sAl_u + offA + ko);
            ldm4(bh00, bh01, bh10, bh11, sHh_u + offB + ko);
            ldm4(bl00, bl01, bl10, bl11, sHl_u + offB + ko);
            hmma(acc[0], ah0, ah1, ah2, ah3, bh00, bh01);
            hmma(acc[0], ah0, ah1, ah2, ah3, bl00, bl01);
            hmma(acc[0], al0, al1, al2, al3, bh00, bh01);
            hmma(acc[1], ah0, ah1, ah2, ah3, bh10, bh11);
            hmma(acc[1], ah0, ah1, ah2, ah3, bl10, bl11);
            hmma(acc[1], al0, al1, al2, al3, bh10, bh11);
        }
    }

    // fused epilogue
    const int vlo = v0 + warpV + g;
    const int vhi = vlo + 8;
    const float dn_lo = den[denB * b + vlo];
    const float dn_hi = den[denB * b + vhi];
    const float* xb = xin + (size_t)b * Ee * Nn;
    float* ob = hout + (size_t)b * Ee * Nn;
    #pragma unroll
    for (int nt = 0; nt < 2; nt++) {
        int c0 = c0w + nt * 8 + 2 * tg;
        size_t i00 = (size_t)c0 * Nn + vlo;
        size_t i01 = (size_t)(c0 + 1) * Nn + vlo;
        size_t i10 = (size_t)c0 * Nn + vhi;
        size_t i11 = (size_t)(c0 + 1) * Nn + vhi;
        ob[i00] = ALPHA * xb[i00] + (1.0f - ALPHA) * ((acc[nt].x + hb[i00]) / dn_lo);
        ob[i01] = ALPHA * xb[i01] + (1.0f - ALPHA) * ((acc[nt].y + hb[i01]) / dn_lo);
        ob[i10] = ALPHA * xb[i10] + (1.0f - ALPHA) * ((acc[nt].z + hb[i10]) / dn_hi);
        ob[i11] = ALPHA * xb[i11] + (1.0f - ALPHA) * ((acc[nt].w + hb[i11]) / dn_hi);
    }
}

// ---------------- generic 1x1 conv (channel-mix GEMM), f32x2 packed ----------
__global__ void conv1x1_k(Srcs srcs, int inBStride,
                          const float* __restrict__ W, const float* __restrict__ bias,
                          int M, int K, float* __restrict__ out, int outBStride, int accFlag) {
    __shared__ float Ws[16 * 68];
    __shared__ float Ins[16 * 68];
    const int tid = threadIdx.x;
    const int tx = tid & 15, ty = tid >> 4;
    const int col0 = blockIdx.x * 64;
    const int b = col0 / Nn, n0 = col0 % Nn;
    const int m0 = blockIdx.y * 64;

    u64 accP[4][2] = {};

    for (int k0 = 0; k0 < K; k0 += 16) {
        for (int t = tid; t < 1024; t += 256) {
            int m = t >> 4, kk = t & 15;
            Ws[kk * 68 + m] = (m0 + m < M) ? W[(size_t)(m0 + m) * K + k0 + kk] : 0.f;
        }
        for (int t = tid; t < 1024; t += 256) {
            int kk = t >> 6, n = t & 63;
            int c = k0 + kk;
            Ins[kk * 68 + n] = srcs.p[c >> 5][(size_t)b * inBStride + (size_t)(c & 31) * Nn + n0 + n];
        }
        __syncthreads();
        #pragma unroll
        for (int kk = 0; kk < 16; kk++) {
            float4 wv = *(const float4*)&Ws[kk * 68 + ty * 4];
            u64 ip0 = *(const u64*)&Ins[kk * 68 + tx * 4];
            u64 ip1 = *(const u64*)&Ins[kk * 68 + tx * 4 + 2];
            float wa[4] = {wv.x, wv.y, wv.z, wv.w};
            #pragma unroll
            for (int u = 0; u < 4; u++) {
                u64 wp = splat2(wa[u]);
                accP[u][0] = fma2(wp, ip0, accP[u][0]);
                accP[u][1] = fma2(wp, ip1, accP[u][1]);
            }
        }
        __syncthreads();
    }
    #pragma unroll
    for (int u = 0; u < 4; u++) {
        int m = m0 + ty * 4 + u;
        if (m >= M) break;
        float bm = bias[m];
        float4 r;
        upk2(accP[u][0], r.x, r.y);
        upk2(accP[u][1], r.z, r.w);
        r.x += bm; r.y += bm; r.z += bm; r.w += bm;
        float* dst = &out[(size_t)b * outBStride + (size_t)m * Nn + n0 + tx * 4];
        if (accFlag) {
            float4 o = *(float4*)dst;
            r.x += o.x; r.y += o.y; r.z += o.z; r.w += o.w;
        }
        *(float4*)dst = r;
    }
}

// ---------------- gated TCN unit ----------------
__global__ void gated_conv_k(Srcs srcs, int inBStride,
                             const float* __restrict__ Wf, const float* __restrict__ bf,
                             const float* __restrict__ Wg, const float* __restrict__ bg,
                             float* __restrict__ out) {
    __shared__ float Wfs[16 * 68];
    __shared__ float Wgs[16 * 68];
    __shared__ float Ins[16 * 68];
    const int tid = threadIdx.x;
    const int tx = tid & 15, ty = tid >> 4;
    const int col0 = blockIdx.x * 64;
    const int b = col0 / Nn, n0 = col0 % Nn;
    const int m0 = blockIdx.y * 64;

    u64 accF[4][2] = {};
    u64 accG[4][2] = {};

    for (int k0 = 0; k0 < Hc; k0 += 16) {
        for (int t = tid; t < 1024; t += 256) {
            int m = t >> 4, kk = t & 15;
            Wfs[kk * 68 + m] = Wf[(size_t)(m0 + m) * Hc + k0 + kk];
            Wgs[kk * 68 + m] = Wg[(size_t)(m0 + m) * Hc + k0 + kk];
        }
        for (int t = tid; t < 1024; t += 256) {
            int kk = t >> 6, n = t & 63;
            int c = k0 + kk;
            Ins[kk * 68 + n] = srcs.p[c >> 5][(size_t)b * inBStride + (size_t)(c & 31) * Nn + n0 + n];
        }
        __syncthreads();
        #pragma unroll
        for (int kk = 0; kk < 16; kk++) {
            float4 fv = *(const float4*)&Wfs[kk * 68 + ty * 4];
            float4 gv = *(const float4*)&Wgs[kk * 68 + ty * 4];
            u64 ip0 = *(const u64*)&Ins[kk * 68 + tx * 4];
            u64 ip1 = *(const u64*)&Ins[kk * 68 + tx * 4 + 2];
            float fa[4] = {fv.x, fv.y, fv.z, fv.w};
            float ga[4] = {gv.x, gv.y, gv.z, gv.w};
            #pragma unroll
            for (int u = 0; u < 4; u++) {
                u64 fp = splat2(fa[u]);
                u64 gp = splat2(ga[u]);
                accF[u][0] = fma2(fp, ip0, accF[u][0]);
                accF[u][1] = fma2(fp, ip1, accF[u][1]);
                accG[u][0] = fma2(gp, ip0, accG[u][0]);
                accG[u][1] = fma2(gp, ip1, accG[u][1]);
            }
        }
        __syncthreads();
    }
    #pragma unroll
    for (int u = 0; u < 4; u++) {
        int m = m0 + ty * 4 + u;
        float bfm = bf[m], bgm = bg[m];
        float ff[4], gg[4];
        upk2(accF[u][0], ff[0], ff[1]);
        upk2(accF[u][1], ff[2], ff[3]);
        upk2(accG[u][0], gg[0], gg[1]);
        upk2(accG[u][1], gg[2], gg[3]);
        float4 r;
        float f, s;
        f = tanhf(ff[0] + bfm); s = 1.f / (1.f + expf(-(gg[0] + bgm))); r.x = f * s;
        f = tanhf(ff[1] + bfm); s = 1.f / (1.f + expf(-(gg[1] + bgm))); r.y = f * s;
        f = tanhf(ff[2] + bfm); s = 1.f / (1.f + expf(-(gg[2] + bgm))); r.z = f * s;
        f = tanhf(ff[3] + bfm); s = 1.f / (1.f + expf(-(gg[3] + bgm))); r.w = f * s;
        *(float4*)&out[(size_t)b * Hc * Nn + (size_t)m * Nn + n0 + tx * 4] = r;
    }
}

// ---------------- layernorm ----------------
__global__ void ln_stats_k() {
    int b = blockIdx.x;
    const float* xp = g_xacc + (size_t)b * Ee * Nn;
    float s = 0.f, s2 = 0.f;
    for (int i = threadIdx.x; i < Ee * Nn; i += blockDim.x) {
        float v = xp[i];
        s += v; s2 += v * v;
    }
    float ts = blockReduceSum(s);
    float ts2 = blockReduceSum(s2);
    if (threadIdx.x == 0) {
        float inv = 1.0f / (Ee * Nn);
        float mu = ts * inv;
        g_stats[b * 2] = mu;
        g_stats[b * 2 + 1] = ts2 * inv - mu * mu;
    }
}

__global__ void ln_apply_k(const float* __restrict__ w, const float* __restrict__ bparm) {
    int i = blockIdx.x * 256 + threadIdx.x;
    if (i >= NEL) return;
    int b = i / (Ee * Nn);
    int cn = i % (Ee * Nn);
    float mu = g_stats[b * 2];
    float var = g_stats[b * 2 + 1];
    float val = (g_xacc[i] - mu) * rsqrtf(var + EPSV) * w[cn] + bparm[cn];
    g_x[i] = fmaxf(val, 0.f);
}

// ---------------- host orchestration ----------------
extern "C" void kernel_launch(void* const* d_in, const int* in_sizes, int n_in,
                              void* d_out, int out_size) {
    (void)in_sizes; (void)n_in; (void)out_size;
    const float* in_x  = (const float*)d_in[0];
    const float* dyG   = (const float*)d_in[1];
    const float* stG   = (const float*)d_in[2];
    const float* spE   = (const float*)d_in[3];
    const float* tdE   = (const float*)d_in[4];
    const float* twE   = (const float*)d_in[5];
    const float* encWf = (const float*)d_in[6];
    const float* encbf = (const float*)d_in[7];
    const float* encWg = (const float*)d_in[8];
    const float* encbg = (const float*)d_in[9];
    const float* skW   = (const float*)d_in[10];
    const float* skb   = (const float*)d_in[11];
    const float* nw    = (const float*)d_in[12];
    const float* nb    = (const float*)d_in[13];
    const float* gW[3] = {(const float*)d_in[14], (const float*)d_in[16], (const float*)d_in[18]};
    const float* gb[3] = {(const float*)d_in[15], (const float*)d_in[17], (const float*)d_in[19]};
    const float* seW   = (const float*)d_in[20];
    const float* seb   = (const float*)d_in[21];
    const float* eW    = (const float*)d_in[22];
    const float* eb    = (const float*)d_in[23];
    float* outp = (float*)d_out;

    float *px, *pxacc, *ph1, *ph2, *phid, *phid2, *pskip, *prss, *prsd, *pcsd;
    cudaGetSymbolAddress((void**)&px,    g_x);
    cudaGetSymbolAddress((void**)&pxacc, g_xacc);
    cudaGetSymbolAddress((void**)&ph1,   g_h1);
    cudaGetSymbolAddress((void**)&ph2,   g_h2);
    cudaGetSymbolAddress((void**)&phid,  g_hid);
    cudaGetSymbolAddress((void**)&phid2, g_hid2);
    cudaGetSymbolAddress((void**)&pskip, g_skip);
    cudaGetSymbolAddress((void**)&prss,  g_rs_s);
    cudaGetSymbolAddress((void**)&prsd,  g_rs_d);
    cudaGetSymbolAddress((void**)&pcsd,  g_cs_d);
    __nv_bfloat16 *pAhi, *pAlo, *pAThi, *pATlo, *pShi, *pSlo;
    cudaGetSymbolAddress((void**)&pAhi,  g_Ahi);
    cudaGetSymbolAddress((void**)&pAlo,  g_Alo);
    cudaGetSymbolAddress((void**)&pAThi, g_AThi);
    cudaGetSymbolAddress((void**)&pATlo, g_ATlo);
    cudaGetSymbolAddress((void**)&pShi,  g_Shi);
    cudaGetSymbolAddress((void**)&pSlo,  g_Slo);

    // prep
    copyk<<<NEL / 256, 256>>>(px, in_x, NEL);
    rowsum_static<<<Nn, 256>>>(stG);
    rowsum_dy<<<dim3(Nn, Bb), 256>>>(dyG);
    colsum_dy<<<dim3(Nn / 256, Bb, CRS), 256>>>(dyG);
    colsum_fin<<<Bb * Nn / 256, 256>>>();
    cvtA_k<<<(Bb * Nn * Nn / 4 + 255) / 256, 256>>>(dyG, pAhi, pAlo, Bb * Nn * Nn / 4);
    cvtA_k<<<(Nn * Nn / 4 + 255) / 256, 256>>>(stG, pShi, pSlo, Nn * Nn / 4);
    transA_k<<<dim3(Nn / 32, Nn / 32, Bb), dim3(32, 8)>>>(dyG);

    const dim3 convGrid(Bb * Nn / 64, 1);
    const dim3 spmmGrid(Nn / 64, Bb);
    const int hsG = (NEL / 4 + 255) / 256;
    for (int i = 0; i < 3; i++) {
        // ---- TCN chain ----
        Srcs s1; s1.p[0] = px; s1.p[1] = spE; s1.p[2] = tdE; s1.p[3] = twE;
        gated_conv_k<<<dim3(Bb * Nn / 64, 2), 256>>>(s1, Ee * Nn,
            encWf + (size_t)(i * 2 + 0) * Hc * Hc, encbf + (i * 2 + 0) * Hc,
            encWg + (size_t)(i * 2 + 0) * Hc * Hc, encbg + (i * 2 + 0) * Hc, phid);
        Srcs s2; for (int s = 0; s < 4; s++) s2.p[s] = phid + (size_t)s * 32 * Nn;
        gated_conv_k<<<dim3(Bb * Nn / 64, 2), 256>>>(s2, Hc * Nn,
            encWf + (size_t)(i * 2 + 1) * Hc * Hc, encbf + (i * 2 + 1) * Hc,
            encWg + (size_t)(i * 2 + 1) * Hc * Hc, encbg + (i * 2 + 1) * Hc, phid2);
        // ---- skip += skip_W @ hidden ----
        Srcs s3; for (int s = 0; s < 4; s++) s3.p[s] = phid2 + (size_t)s * 32 * Nn;
        conv1x1_k<<<dim3(Bb * Nn / 64, 4), 256>>>(s3, Hc * Nn,
            skW + (size_t)i * Sc * Hc, skb + i * Sc, Sc, Hc, pskip, Sc * Nn, i > 0);
        // ---- mixprops ----
        copyk<<<NEL / 256, 256>>>(pxacc, px, NEL);
        for (int g = 0; g < 3; g++) {
            const __nv_bfloat16* Ah = (g == 0) ? pShi : (g == 1 ? pAhi : pAThi);
            const __nv_bfloat16* Al = (g == 0) ? pSlo : (g == 1 ? pAlo : pATlo);
            size_t abst = (g == 0) ? 0 : (size_t)Nn * Nn;
            const float* den = (g == 0) ? prss : (g == 1 ? prsd : pcsd);
            int denB = (g == 0) ? 0 : Nn;
            hsplit_k<<<hsG, 256>>>(px);
            spmm_mma<<<spmmGrid, 256>>>(Ah, Al, abst, px, px, den, denB, ph1);
            hsplit_k<<<hsG, 256>>>(ph1);
            spmm_mma<<<spmmGrid, 256>>>(Ah, Al, abst, ph1, px, den, denB, ph2);
            Srcs sm; sm.p[0] = px; sm.p[1] = ph1; sm.p[2] = ph2;
            conv1x1_k<<<convGrid, 256>>>(sm, Ee * Nn,
                gW[g] + (size_t)i * Ee * 96, gb[g] + i * Ee, Ee, 96, pxacc, Ee * Nn, 1);
        }
        // ---- layernorm + relu -> new x ----
        ln_stats_k<<<Bb, 1024>>>();
        ln_apply_k<<<NEL / 256, 256>>>(nw + (size_t)i * Ee * Nn, nb + (size_t)i * Ee * Nn);
    }
    // ---- skip end + output ----
    Srcs se; se.p[0] = px;
    conv1x1_k<<<dim3(Bb * Nn / 64, 4), 256>>>(se, Ee * Nn, seW, seb, Sc, Ee, pskip, Sc * Nn, 1);
    Srcs send; for (int s = 0; s < 8; s++) send.p[s] = pskip + (size_t)s * 32 * Nn;
    conv1x1_k<<<convGrid, 256>>>(send, Sc * Nn, eW, eb, Tt, Sc, outp, Tt * Nn, 0);
}

// round 9
// speedup vs baseline: 1.6087x; 1.1163x over previous
#include <cuda_runtime.h>
#include <cuda_bf16.h>
#include <math.h>
#include <stdint.h>

#define Bb 8
#define Nn 2048
#define Ee 32
#define Hc 128
#define Sc 256
#define Tt 12
#define NEL (Bb*Ee*Nn)
#define ALPHA 0.05f
#define EPSV 1e-5f
#define AP 72   // smem pitch in bf16 units (144B: conflict-free for ldmatrix)

typedef unsigned long long u64;

// ---------------- packed fp32x2 helpers (for SIMT convs) ----------------
__device__ __forceinline__ u64 splat2(float a) {
    u64 d; asm("mov.b64 %0, {%1, %1};" : "=l"(d) : "f"(a)); return d;
}
__device__ __forceinline__ void upk2(u64 v, float& lo, float& hi) {
    asm("mov.b64 {%0, %1}, %2;" : "=f"(lo), "=f"(hi) : "l"(v));
}
__device__ __forceinline__ u64 fma2(u64 a, u64 b, u64 c) {
    u64 d; asm("fma.rn.f32x2 %0, %1, %2, %3;" : "=l"(d) : "l"(a), "l"(b), "l"(c)); return d;
}

// ---------------- warp-level bf16 MMA + ldmatrix ----------------
__device__ __forceinline__ void hmma(float4& d, uint32_t a0, uint32_t a1, uint32_t a2,
                                     uint32_t a3, uint32_t b0, uint32_t b1) {
    asm volatile(
        "mma.sync.aligned.m16n8k16.row.col.f32.bf16.bf16.f32 "
        "{%0,%1,%2,%3}, {%4,%5,%6,%7}, {%8,%9}, {%0,%1,%2,%3};"
        : "+f"(d.x), "+f"(d.y), "+f"(d.z), "+f"(d.w)
        : "r"(a0), "r"(a1), "r"(a2), "r"(a3), "r"(b0), "r"(b1));
}
__device__ __forceinline__ void ldm4(uint32_t& r0, uint32_t& r1, uint32_t& r2, uint32_t& r3,
                                     uint32_t addr) {
    asm volatile("ldmatrix.sync.aligned.m8n8.x4.shared.b16 {%0,%1,%2,%3}, [%4];"
        : "=r"(r0), "=r"(r1), "=r"(r2), "=r"(r3) : "r"(addr));
}
__device__ __forceinline__ uint32_t smem_u32(const void* p) {
    uint32_t a;
    asm("{ .reg .u64 t; cvta.to.shared.u64 t, %1; cvt.u32.u64 %0, t; }" : "=r"(a) : "l"(p));
    return a;
}

// ---------------- device scratch ----------------
__device__ float g_x[NEL];
__device__ float g_xacc[NEL];
__device__ float g_h1[NEL];
__device__ float g_h2[NEL];
__device__ float g_hid[Bb*Hc*Nn];
__device__ float g_hid2[Bb*Hc*Nn];
__device__ float g_skip[Bb*Sc*Nn];
__device__ float g_rs_s[Nn];
__device__ float g_rs_d[Bb*Nn];
__device__ float g_cs_d[Bb*Nn];
__device__ float g_stats[Bb*2];
__device__ __nv_bfloat16 g_Ahi[Bb*Nn*Nn];
__device__ __nv_bfloat16 g_Alo[Bb*Nn*Nn];
__device__ __nv_bfloat16 g_AThi[Bb*Nn*Nn];
__device__ __nv_bfloat16 g_ATlo[Bb*Nn*Nn];
__device__ __nv_bfloat16 g_Shi[Nn*Nn];
__device__ __nv_bfloat16 g_Slo[Nn*Nn];
__device__ __nv_bfloat16 g_sxHi[NEL];
__device__ __nv_bfloat16 g_sxLo[NEL];
__device__ __nv_bfloat16 g_s1Hi[NEL];
__device__ __nv_bfloat16 g_s1Lo[NEL];

struct Srcs { const float* p[8]; };

__device__ __forceinline__ void bsplit(float a, __nv_bfloat16& h, __nv_bfloat16& l) {
    h = __float2bfloat16(a);
    l = __float2bfloat16(a - __bfloat162float(h));
}
__device__ __forceinline__ uint32_t bpack(__nv_bfloat16 a, __nv_bfloat16 b) {
    __nv_bfloat162 t; t.x = a; t.y = b;
    return *reinterpret_cast<uint32_t*>(&t);
}

// ---------------- helpers ----------------
__device__ __forceinline__ float blockReduceSum(float v) {
    __shared__ float sh[32];
    int lane = threadIdx.x & 31, wid = threadIdx.x >> 5;
    #pragma unroll
    for (int o = 16; o; o >>= 1) v += __shfl_down_sync(0xffffffffu, v, o);
    __syncthreads();
    if (lane == 0) sh[wid] = v;
    __syncthreads();
    int nw = blockDim.x >> 5;
    v = (threadIdx.x < nw) ? sh[threadIdx.x] : 0.f;
    if (wid == 0) {
        #pragma unroll
        for (int o = 16; o; o >>= 1) v += __shfl_down_sync(0xffffffffu, v, o);
    }
    return v;
}

// copy + split: dst=src (f32), and bf16 hi/lo split into g_sxHi/g_sxLo
__global__ void copy_split_k(float* __restrict__ dst, const float* __restrict__ src) {
    int i = blockIdx.x * 256 + threadIdx.x;
    if (i >= NEL / 4) return;
    float4 a = ((const float4*)src)[i];
    ((float4*)dst)[i] = a;
    __nv_bfloat16 h0, h1, h2, h3, l0, l1, l2, l3;
    bsplit(a.x, h0, l0); bsplit(a.y, h1, l1); bsplit(a.z, h2, l2); bsplit(a.w, h3, l3);
    ((uint2*)g_sxHi)[i] = make_uint2(bpack(h0, h1), bpack(h2, h3));
    ((uint2*)g_sxLo)[i] = make_uint2(bpack(l0, l1), bpack(l2, l3));
}

__global__ void copyk(float* __restrict__ dst, const float* __restrict__ src, int n) {
    int i = blockIdx.x * 256 + threadIdx.x;
    if (i < n) dst[i] = src[i];
}

// ---------------- fused prep ----------------
__global__ void init_den_k() {
    int i = blockIdx.x * 256 + threadIdx.x;
    if (i < Nn) g_rs_s[i] = 1.0f;
    if (i < Bb * Nn) { g_rs_d[i] = 1.0f; g_cs_d[i] = 1.0f; }
}

// One pass over dyG: bf16 hi/lo, transposed hi/lo, rowsum & colsum partials.
// Tile 64x64, 256 threads. Shared pitch 68 floats (272B, float4-aligned).
__global__ void prepA_k(const float* __restrict__ A) {
    __shared__ float sh[64][68];
    const int b = blockIdx.z;
    const int r0 = blockIdx.x * 64, c0 = blockIdx.y * 64;
    const int tid = threadIdx.x;
    const int row = tid >> 2, q = tid & 3;

    const float* Ab = A + (size_t)b * Nn * Nn;
    float rsum = 0.f;
    #pragma unroll
    for (int j = 0; j < 4; j++) {
        int idx4 = q + j * 4;              // float4 index within row (0..15)
        float4 v = *(const float4*)&Ab[(size_t)(r0 + row) * Nn + c0 + idx4 * 4];
        *(float4*)&sh[row][idx4 * 4] = v;
        rsum += v.x + v.y + v.z + v.w;
        __nv_bfloat16 h0, h1, h2, h3, l0, l1, l2, l3;
        bsplit(v.x, h0, l0); bsplit(v.y, h1, l1); bsplit(v.z, h2, l2); bsplit(v.w, h3, l3);
        size_t o = ((size_t)b * Nn + r0 + row) * Nn + c0 + idx4 * 4;
        *(uint2*)&g_Ahi[o] = make_uint2(bpack(h0, h1), bpack(h2, h3));
        *(uint2*)&g_Alo[o] = make_uint2(bpack(l0, l1), bpack(l2, l3));
    }
    rsum += __shfl_down_sync(0xffffffffu, rsum, 1);
    rsum += __shfl_down_sync(0xffffffffu, rsum, 2);
    if (q == 0) atomicAdd(&g_rs_d[b * Nn + r0 + row], rsum);
    __syncthreads();
    // transposed: AT[c][r] = sh[r][c]; this thread covers c = c0+row, 16 r values
    float csum = 0.f;
    #pragma unroll
    for (int j = 0; j < 4; j++) {
        int idx4 = q + j * 4;
        float4 v;
        v.x = sh[idx4 * 4 + 0][row];
        v.y = sh[idx4 * 4 + 1][row];
        v.z = sh[idx4 * 4 + 2][row];
        v.w = sh[idx4 * 4 + 3][row];
        csum += v.x + v.y + v.z + v.w;
        __nv_bfloat16 h0, h1, h2, h3, l0, l1, l2, l3;
        bsplit(v.x, h0, l0); bsplit(v.y, h1, l1); bsplit(v.z, h2, l2); bsplit(v.w, h3, l3);
        size_t o = ((size_t)b * Nn + c0 + row) * Nn + r0 + idx4 * 4;
        *(uint2*)&g_AThi[o] = make_uint2(bpack(h0, h1), bpack(h2, h3));
        *(uint2*)&g_ATlo[o] = make_uint2(bpack(l0, l1), bpack(l2, l3));
    }
    csum += __shfl_down_sync(0xffffffffu, csum, 1);
    csum += __shfl_down_sync(0xffffffffu, csum, 2);
    if (q == 0) atomicAdd(&g_cs_d[b * Nn + c0 + row], csum);
}

// static graph: cvt hi/lo + rowsum (no transpose needed)
__global__ void prepS_k(const float* __restrict__ S) {
    const int r0 = blockIdx.x * 64, c0 = blockIdx.y * 64;
    const int tid = threadIdx.x;
    const int row = tid >> 2, q = tid & 3;
    float rsum = 0.f;
    #pragma unroll
    for (int j = 0; j < 4; j++) {
        int idx4 = q + j * 4;
        float4 v = *(const float4*)&S[(size_t)(r0 + row) * Nn + c0 + idx4 * 4];
        rsum += v.x + v.y + v.z + v.w;
        __nv_bfloat16 h0, h1, h2, h3, l0, l1, l2, l3;
        bsplit(v.x, h0, l0); bsplit(v.y, h1, l1); bsplit(v.z, h2, l2); bsplit(v.w, h3, l3);
        size_t o = (size_t)(r0 + row) * Nn + c0 + idx4 * 4;
        *(uint2*)&g_Shi[o] = make_uint2(bpack(h0, h1), bpack(h2, h3));
        *(uint2*)&g_Slo[o] = make_uint2(bpack(l0, l1), bpack(l2, l3));
    }
    rsum += __shfl_down_sync(0xffffffffu, rsum, 1);
    rsum += __shfl_down_sync(0xffffffffu, rsum, 2);
    if (q == 0) atomicAdd(&g_rs_s[r0 + row], rsum);
}

// ---------------- HMMA SpMM with fused mixprop hop epilogue ------------------
__global__ void __launch_bounds__(256) spmm_mma(
        const __nv_bfloat16* __restrict__ Ahi, const __nv_bfloat16* __restrict__ Alo,
        size_t aBStride,
        const __nv_bfloat16* __restrict__ HhB, const __nv_bfloat16* __restrict__ HlB,
        const float* __restrict__ hin, const float* __restrict__ xin,
        const float* __restrict__ den, int denB, float* __restrict__ hout,
        int writeSplit) {
    __shared__ __nv_bfloat16 sAh[64 * AP];
    __shared__ __nv_bfloat16 sAl[64 * AP];
    __shared__ __nv_bfloat16 sHh[32 * AP];
    __shared__ __nv_bfloat16 sHl[32 * AP];

    const int tid = threadIdx.x, wid = tid >> 5, lane = tid & 31;
    const int g = lane >> 2, tg = lane & 3;
    const int vt = blockIdx.x, b = blockIdx.y;
    const int v0 = vt * 64;
    const int warpV = (wid >> 1) * 16;
    const int c0w = (wid & 1) * 16;

    const __nv_bfloat16* Ah = Ahi + (size_t)b * aBStride;
    const __nv_bfloat16* Al = Alo + (size_t)b * aBStride;
    const __nv_bfloat16* Hh = HhB + (size_t)b * Ee * Nn;
    const __nv_bfloat16* Hl = HlB + (size_t)b * Ee * Nn;
    const float* hb = hin + (size_t)b * Ee * Nn;

    const uint32_t sAh_u = smem_u32(sAh), sAl_u = smem_u32(sAl);
    const uint32_t sHh_u = smem_u32(sHh), sHl_u = smem_u32(sHl);
    const int rowA = warpV + (lane & 15);
    const int khA  = (lane >> 4) * 8;
    const uint32_t offA = (uint32_t)(rowA * AP + khA) * 2;
    const int rowB = c0w + (lane & 7) + ((lane >> 4) & 1) * 8;
    const int khB  = ((lane >> 3) & 1) * 8;
    const uint32_t offB = (uint32_t)(rowB * AP + khB) * 2;

    float4 acc[2] = {};

    int ar0 = tid >> 3,           au0 = tid & 7;
    int ar1 = (tid + 256) >> 3,   au1 = tid & 7;
    int hc  = tid >> 3,           hu = tid & 7;

    uint4 pAh0, pAh1, pAl0, pAl1, pHh, pHl;
    {
        pAh0 = *(const uint4*)(Ah + (size_t)(v0 + ar0) * Nn + au0 * 8);
        pAh1 = *(const uint4*)(Ah + (size_t)(v0 + ar1) * Nn + au1 * 8);
        pAl0 = *(const uint4*)(Al + (size_t)(v0 + ar0) * Nn + au0 * 8);
        pAl1 = *(const uint4*)(Al + (size_t)(v0 + ar1) * Nn + au1 * 8);
        pHh  = *(const uint4*)(Hh + (size_t)hc * Nn + hu * 8);
        pHl  = *(const uint4*)(Hl + (size_t)hc * Nn + hu * 8);
    }

    for (int ch = 0; ch < 32; ch++) {
        __syncthreads();
        *(uint4*)&sAh[ar0 * AP + au0 * 8] = pAh0;
        *(uint4*)&sAh[ar1 * AP + au1 * 8] = pAh1;
        *(uint4*)&sAl[ar0 * AP + au0 * 8] = pAl0;
        *(uint4*)&sAl[ar1 * AP + au1 * 8] = pAl1;
        *(uint4*)&sHh[hc * AP + hu * 8] = pHh;
        *(uint4*)&sHl[hc * AP + hu * 8] = pHl;
        if (ch < 31) {
            const int w0 = (ch + 1) * 64;
            pAh0 = *(const uint4*)(Ah + (size_t)(v0 + ar0) * Nn + w0 + au0 * 8);
            pAh1 = *(const uint4*)(Ah + (size_t)(v0 + ar1) * Nn + w0 + au1 * 8);
            pAl0 = *(const uint4*)(Al + (size_t)(v0 + ar0) * Nn + w0 + au0 * 8);
            pAl1 = *(const uint4*)(Al + (size_t)(v0 + ar1) * Nn + w0 + au1 * 8);
            pHh  = *(const uint4*)(Hh + (size_t)hc * Nn + w0 + hu * 8);
            pHl  = *(const uint4*)(Hl + (size_t)hc * Nn + w0 + hu * 8);
        }
        __syncthreads();
        #pragma unroll
        for (int ks = 0; ks < 4; ks++) {
            const uint32_t ko = ks * 32;
            uint32_t ah0, ah1, ah2, ah3, al0, al1, al2, al3;
            uint32_t bh00, bh01, bh10, bh11, bl00, bl01, bl10, bl11;
            ldm4(ah0, ah1, ah2, ah3, sAh_u + offA + ko);
            ldm4(al0, al1, al2, al3, sAl_u + offA + ko);
            ldm4(bh00, bh01, bh10, bh11, sHh_u + offB + ko);
            ldm4(bl00, bl01, bl10, bl11, sHl_u + offB + ko);
            hmma(acc[0], ah0, ah1, ah2, ah3, bh00, bh01);
            hmma(acc[0], ah0, ah1, ah2, ah3, bl00, bl01);
            hmma(acc[0], al0, al1, al2, al3, bh00, bh01);
            hmma(acc[1], ah0, ah1, ah2, ah3, bh10, bh11);
            hmma(acc[1], ah0, ah1, ah2, ah3, bl10, bl11);
            hmma(acc[1], al0, al1, al2, al3, bh10, bh11);
        }
    }

    // fused epilogue (+ optional split write for next hop)
    const int vlo = v0 + warpV + g;
    const int vhi = vlo + 8;
    const float dn_lo = den[denB * b + vlo];
    const float dn_hi = den[denB * b + vhi];
    const float* xb = xin + (size_t)b * Ee * Nn;
    float* ob = hout + (size_t)b * Ee * Nn;
    __nv_bfloat16* oh = g_s1Hi + (size_t)b * Ee * Nn;
    __nv_bfloat16* ol = g_s1Lo + (size_t)b * Ee * Nn;
    #pragma unroll
    for (int nt = 0; nt < 2; nt++) {
        int c0 = c0w + nt * 8 + 2 * tg;
        float vals[4];
        size_t idxs[4];
        idxs[0] = (size_t)c0 * Nn + vlo;
        idxs[1] = (size_t)(c0 + 1) * Nn + vlo;
        idxs[2] = (size_t)c0 * Nn + vhi;
        idxs[3] = (size_t)(c0 + 1) * Nn + vhi;
        vals[0] = ALPHA * xb[idxs[0]] + (1.0f - ALPHA) * ((acc[nt].x + hb[idxs[0]]) / dn_lo);
        vals[1] = ALPHA * xb[idxs[1]] + (1.0f - ALPHA) * ((acc[nt].y + hb[idxs[1]]) / dn_lo);
        vals[2] = ALPHA * xb[idxs[2]] + (1.0f - ALPHA) * ((acc[nt].z + hb[idxs[2]]) / dn_hi);
        vals[3] = ALPHA * xb[idxs[3]] + (1.0f - ALPHA) * ((acc[nt].w + hb[idxs[3]]) / dn_hi);
        #pragma unroll
        for (int u = 0; u < 4; u++) {
            ob[idxs[u]] = vals[u];
            if (writeSplit) {
                __nv_bfloat16 h, l; bsplit(vals[u], h, l);
                oh[idxs[u]] = h;
                ol[idxs[u]] = l;
            }
        }
    }
}

// ---------------- generic 1x1 conv (channel-mix GEMM), f32x2 packed ----------
__global__ void conv1x1_k(Srcs srcs, int inBStride,
                          const float* __restrict__ W, const float* __restrict__ bias,
                          int M, int K, float* __restrict__ out, int outBStride, int accFlag) {
    __shared__ float Ws[16 * 68];
    __shared__ float Ins[16 * 68];
    const int tid = threadIdx.x;
    const int tx = tid & 15, ty = tid >> 4;
    const int col0 = blockIdx.x * 64;
    const int b = col0 / Nn, n0 = col0 % Nn;
    const int m0 = blockIdx.y * 64;

    u64 accP[4][2] = {};

    for (int k0 = 0; k0 < K; k0 += 16) {
        for (int t = tid; t < 1024; t += 256) {
            int m = t >> 4, kk = t & 15;
            Ws[kk * 68 + m] = (m0 + m < M) ? W[(size_t)(m0 + m) * K + k0 + kk] : 0.f;
        }
        for (int t = tid; t < 1024; t += 256) {
            int kk = t >> 6, n = t & 63;
            int c = k0 + kk;
            Ins[kk * 68 + n] = srcs.p[c >> 5][(size_t)b * inBStride + (size_t)(c & 31) * Nn + n0 + n];
        }
        __syncthreads();
        #pragma unroll
        for (int kk = 0; kk < 16; kk++) {
            float4 wv = *(const float4*)&Ws[kk * 68 + ty * 4];
            u64 ip0 = *(const u64*)&Ins[kk * 68 + tx * 4];
            u64 ip1 = *(const u64*)&Ins[kk * 68 + tx * 4 + 2];
            float wa[4] = {wv.x, wv.y, wv.z, wv.w};
            #pragma unroll
            for (int u = 0; u < 4; u++) {
                u64 wp = splat2(wa[u]);
                accP[u][0] = fma2(wp, ip0, accP[u][0]);
                accP[u][1] = fma2(wp, ip1, accP[u][1]);
            }
        }
        __syncthreads();
    }
    #pragma unroll
    for (int u = 0; u < 4; u++) {
        int m = m0 + ty * 4 + u;
        if (m >= M) break;
        float bm = bias[m];
        float4 r;
        upk2(accP[u][0], r.x, r.y);
        upk2(accP[u][1], r.z, r.w);
        r.x += bm; r.y += bm; r.z += bm; r.w += bm;
        float* dst = &out[(size_t)b * outBStride + (size_t)m * Nn + n0 + tx * 4];
        if (accFlag) {
            float4 o = *(float4*)dst;
            r.x += o.x; r.y += o.y; r.z += o.z; r.w += o.w;
        }
        *(float4*)dst = r;
    }
}

// ---------------- gated TCN unit ----------------
__global__ void gated_conv_k(Srcs srcs, int inBStride,
                             const float* __restrict__ Wf, const float* __restrict__ bf,
                             const float* __restrict__ Wg, const float* __restrict__ bg,
                             float* __restrict__ out) {
    __shared__ float Wfs[16 * 68];
    __shared__ float Wgs[16 * 68];
    __shared__ float Ins[16 * 68];
    const int tid = threadIdx.x;
    const int tx = tid & 15, ty = tid >> 4;
    const int col0 = blockIdx.x * 64;
    const int b = col0 / Nn, n0 = col0 % Nn;
    const int m0 = blockIdx.y * 64;

    u64 accF[4][2] = {};
    u64 accG[4][2] = {};

    for (int k0 = 0; k0 < Hc; k0 += 16) {
        for (int t = tid; t < 1024; t += 256) {
            int m = t >> 4, kk = t & 15;
            Wfs[kk * 68 + m] = Wf[(size_t)(m0 + m) * Hc + k0 + kk];
            Wgs[kk * 68 + m] = Wg[(size_t)(m0 + m) * Hc + k0 + kk];
        }
        for (int t = tid; t < 1024; t += 256) {
            int kk = t >> 6, n = t & 63;
            int c = k0 + kk;
            Ins[kk * 68 + n] = srcs.p[c >> 5][(size_t)b * inBStride + (size_t)(c & 31) * Nn + n0 + n];
        }
        __syncthreads();
        #pragma unroll
        for (int kk = 0; kk < 16; kk++) {
            float4 fv = *(const float4*)&Wfs[kk * 68 + ty * 4];
            float4 gv = *(const float4*)&Wgs[kk * 68 + ty * 4];
            u64 ip0 = *(const u64*)&Ins[kk * 68 + tx * 4];
            u64 ip1 = *(const u64*)&Ins[kk * 68 + tx * 4 + 2];
            float fa[4] = {fv.x, fv.y, fv.z, fv.w};
            float ga[4] = {gv.x, gv.y, gv.z, gv.w};
            #pragma unroll
            for (int u = 0; u < 4; u++) {
                u64 fp = splat2(fa[u]);
                u64 gp = splat2(ga[u]);
                accF[u][0] = fma2(fp, ip0, accF[u][0]);
                accF[u][1] = fma2(fp, ip1, accF[u][1]);
                accG[u][0] = fma2(gp, ip0, accG[u][0]);
                accG[u][1] = fma2(gp, ip1, accG[u][1]);
            }
        }
        __syncthreads();
    }
    #pragma unroll
    for (int u = 0; u < 4; u++) {
        int m = m0 + ty * 4 + u;
        float bfm = bf[m], bgm = bg[m];
        float ff[4], gg[4];
        upk2(accF[u][0], ff[0], ff[1]);
        upk2(accF[u][1], ff[2], ff[3]);
        upk2(accG[u][0], gg[0], gg[1]);
        upk2(accG[u][1], gg[2], gg[3]);
        float4 r;
        float f, s;
        f = tanhf(ff[0] + bfm); s = 1.f / (1.f + expf(-(gg[0] + bgm))); r.x = f * s;
        f = tanhf(ff[1] + bfm); s = 1.f / (1.f + expf(-(gg[1] + bgm))); r.y = f * s;
        f = tanhf(ff[2] + bfm); s = 1.f / (1.f + expf(-(gg[2] + bgm))); r.z = f * s;
        f = tanhf(ff[3] + bfm); s = 1.f / (1.f + expf(-(gg[3] + bgm))); r.w = f * s;
        *(float4*)&out[(size_t)b * Hc * Nn + (size_t)m * Nn + n0 + tx * 4] = r;
    }
}

// ---------------- layernorm ----------------
__global__ void ln_stats_k() {
    int b = blockIdx.x;
    const float* xp = g_xacc + (size_t)b * Ee * Nn;
    float s = 0.f, s2 = 0.f;
    for (int i = threadIdx.x; i < Ee * Nn; i += blockDim.x) {
        float v = xp[i];
        s += v; s2 += v * v;
    }
    float ts = blockReduceSum(s);
    float ts2 = blockReduceSum(s2);
    if (threadIdx.x == 0) {
        float inv = 1.0f / (Ee * Nn);
        float mu = ts * inv;
        g_stats[b * 2] = mu;
        g_stats[b * 2 + 1] = ts2 * inv - mu * mu;
    }
}

// layernorm+relu -> g_x, also writes bf16 splits of g_x
__global__ void ln_apply_k(const float* __restrict__ w, const float* __restrict__ bparm) {
    int i = blockIdx.x * 256 + threadIdx.x;
    if (i >= NEL) return;
    int b = i / (Ee * Nn);
    int cn = i % (Ee * Nn);
    float mu = g_stats[b * 2];
    float var = g_stats[b * 2 + 1];
    float val = (g_xacc[i] - mu) * rsqrtf(var + EPSV) * w[cn] + bparm[cn];
    val = fmaxf(val, 0.f);
    g_x[i] = val;
    __nv_bfloat16 h, l; bsplit(val, h, l);
    g_sxHi[i] = h;
    g_sxLo[i] = l;
}

// ---------------- host orchestration ----------------
extern "C" void kernel_launch(void* const* d_in, const int* in_sizes, int n_in,
                              void* d_out, int out_size) {
    (void)in_sizes; (void)n_in; (void)out_size;
    const float* in_x  = (const float*)d_in[0];
    const float* dyG   = (const float*)d_in[1];
    const float* stG   = (const float*)d_in[2];
    const float* spE   = (const float*)d_in[3];
    const float* tdE   = (const float*)d_in[4];
    const float* twE   = (const float*)d_in[5];
    const float* encWf = (const float*)d_in[6];
    const float* encbf = (const float*)d_in[7];
    const float* encWg = (const float*)d_in[8];
    const float* encbg = (const float*)d_in[9];
    const float* skW   = (const float*)d_in[10];
    const float* skb   = (const float*)d_in[11];
    const float* nw    = (const float*)d_in[12];
    const float* nb    = (const float*)d_in[13];
    const float* gW[3] = {(const float*)d_in[14], (const float*)d_in[16], (const float*)d_in[18]};
    const float* gb[3] = {(const float*)d_in[15], (const float*)d_in[17], (const float*)d_in[19]};
    const float* seW   = (const float*)d_in[20];
    const float* seb   = (const float*)d_in[21];
    const float* eW    = (const float*)d_in[22];
    const float* eb    = (const float*)d_in[23];
    float* outp = (float*)d_out;

    float *px, *pxacc, *ph1, *ph2, *phid, *phid2, *pskip, *prss, *prsd, *pcsd;
    cudaGetSymbolAddress((void**)&px,    g_x);
    cudaGetSymbolAddress((void**)&pxacc, g_xacc);
    cudaGetSymbolAddress((void**)&ph1,   g_h1);
    cudaGetSymbolAddress((void**)&ph2,   g_h2);
    cudaGetSymbolAddress((void**)&phid,  g_hid);
    cudaGetSymbolAddress((void**)&phid2, g_hid2);
    cudaGetSymbolAddress((void**)&pskip, g_skip);
    cudaGetSymbolAddress((void**)&prss,  g_rs_s);
    cudaGetSymbolAddress((void**)&prsd,  g_rs_d);
    cudaGetSymbolAddress((void**)&pcsd,  g_cs_d);
    __nv_bfloat16 *pAhi, *pAlo, *pAThi, *pATlo, *pShi, *pSlo, *psxHi, *psxLo, *ps1Hi, *ps1Lo;
    cudaGetSymbolAddress((void**)&pAhi,  g_Ahi);
    cudaGetSymbolAddress((void**)&pAlo,  g_Alo);
    cudaGetSymbolAddress((void**)&pAThi, g_AThi);
    cudaGetSymbolAddress((void**)&pATlo, g_ATlo);
    cudaGetSymbolAddress((void**)&pShi,  g_Shi);
    cudaGetSymbolAddress((void**)&pSlo,  g_Slo);
    cudaGetSymbolAddress((void**)&psxHi, g_sxHi);
    cudaGetSymbolAddress((void**)&psxLo, g_sxLo);
    cudaGetSymbolAddress((void**)&ps1Hi, g_s1Hi);
    cudaGetSymbolAddress((void**)&ps1Lo, g_s1Lo);

    // prep: x copy+split, fused degree sums + bf16 conversion + transpose
    copy_split_k<<<(NEL / 4 + 255) / 256, 256>>>(px, in_x);
    init_den_k<<<(Bb * Nn + 255) / 256, 256>>>();
    prepA_k<<<dim3(Nn / 64, Nn / 64, Bb), 256>>>(dyG);
    prepS_k<<<dim3(Nn / 64, Nn / 64), 256>>>(stG);

    const dim3 convGrid(Bb * Nn / 64, 1);
    const dim3 spmmGrid(Nn / 64, Bb);
    for (int i = 0; i < 3; i++) {
        // ---- TCN chain ----
        Srcs s1; s1.p[0] = px; s1.p[1] = spE; s1.p[2] = tdE; s1.p[3] = twE;
        gated_conv_k<<<dim3(Bb * Nn / 64, 2), 256>>>(s1, Ee * Nn,
            encWf + (size_t)(i * 2 + 0) * Hc * Hc, encbf + (i * 2 + 0) * Hc,
            encWg + (size_t)(i * 2 + 0) * Hc * Hc, encbg + (i * 2 + 0) * Hc, phid);
        Srcs s2; for (int s = 0; s < 4; s++) s2.p[s] = phid + (size_t)s * 32 * Nn;
        gated_conv_k<<<dim3(Bb * Nn / 64, 2), 256>>>(s2, Hc * Nn,
            encWf + (size_t)(i * 2 + 1) * Hc * Hc, encbf + (i * 2 + 1) * Hc,
            encWg + (size_t)(i * 2 + 1) * Hc * Hc, encbg + (i * 2 + 1) * Hc, phid2);
        // ---- skip += skip_W @ hidden ----
        Srcs s3; for (int s = 0; s < 4; s++) s3.p[s] = phid2 + (size_t)s * 32 * Nn;
        conv1x1_k<<<dim3(Bb * Nn / 64, 4), 256>>>(s3, Hc * Nn,
            skW + (size_t)i * Sc * Hc, skb + i * Sc, Sc, Hc, pskip, Sc * Nn, i > 0);
        // ---- mixprops ----
        copyk<<<NEL / 256, 256>>>(pxacc, px, NEL);
        for (int g = 0; g < 3; g++) {
            const __nv_bfloat16* Ah = (g == 0) ? pShi : (g == 1 ? pAhi : pAThi);
            const __nv_bfloat16* Al = (g == 0) ? pSlo : (g == 1 ? pAlo : pATlo);
            size_t abst = (g == 0) ? 0 : (size_t)Nn * Nn;
            const float* den = (g == 0) ? prss : (g == 1 ? prsd : pcsd);
            int denB = (g == 0) ? 0 : Nn;
            spmm_mma<<<spmmGrid, 256>>>(Ah, Al, abst, psxHi, psxLo, px, px, den, denB, ph1, 1);
            spmm_mma<<<spmmGrid, 256>>>(Ah, Al, abst, ps1Hi, ps1Lo, ph1, px, den, denB, ph2, 0);
            Srcs sm; sm.p[0] = px; sm.p[1] = ph1; sm.p[2] = ph2;
            conv1x1_k<<<convGrid, 256>>>(sm, Ee * Nn,
                gW[g] + (size_t)i * Ee * 96, gb[g] + i * Ee, Ee, 96, pxacc, Ee * Nn, 1);
        }
        // ---- layernorm + relu -> new x (+ splits) ----
        ln_stats_k<<<Bb, 1024>>>();
        ln_apply_k<<<NEL / 256, 256>>>(nw + (size_t)i * Ee * Nn, nb + (size_t)i * Ee * Nn);
    }
    // ---- skip end + output ----
    Srcs se; se.p[0] = px;
    conv1x1_k<<<dim3(Bb * Nn / 64, 4), 256>>>(se, Ee * Nn, seW, seb, Sc, Ee, pskip, Sc * Nn, 1);
    Srcs send; for (int s = 0; s < 8; s++) send.p[s] = pskip + (size_t)s * 32 * Nn;
    conv1x1_k<<<convGrid, 256>>>(send, Sc * Nn, eW, eb, Tt, Sc, outp, Tt * Nn, 0);
}

// round 10
// speedup vs baseline: 1.8854x; 1.1720x over previous
#include <cuda_runtime.h>
#include <cuda_bf16.h>
#include <math.h>
#include <stdint.h>

#define Bb 8
#define Nn 2048
#define Ee 32
#define Hc 128
#define Sc 256
#define Tt 12
#define NEL (Bb*Ee*Nn)
#define ALPHA 0.05f
#define EPSV 1e-5f
#define AP 72   // spmm smem pitch bf16 (144B)
#define CP 24   // conv smem pitch bf16 (48B; k16 rows, ldmatrix conflict-free)

typedef unsigned long long u64;
typedef __nv_bfloat16 bf16;

// ---------------- packed fp32x2 helpers (for SIMT convs) ----------------
__device__ __forceinline__ u64 splat2(float a) {
    u64 d; asm("mov.b64 %0, {%1, %1};" : "=l"(d) : "f"(a)); return d;
}
__device__ __forceinline__ void upk2(u64 v, float& lo, float& hi) {
    asm("mov.b64 {%0, %1}, %2;" : "=f"(lo), "=f"(hi) : "l"(v));
}
__device__ __forceinline__ u64 fma2(u64 a, u64 b, u64 c) {
    u64 d; asm("fma.rn.f32x2 %0, %1, %2, %3;" : "=l"(d) : "l"(a), "l"(b), "l"(c)); return d;
}

// ---------------- warp-level bf16 MMA + ldmatrix ----------------
__device__ __forceinline__ void hmma(float4& d, uint32_t a0, uint32_t a1, uint32_t a2,
                                     uint32_t a3, uint32_t b0, uint32_t b1) {
    asm volatile(
        "mma.sync.aligned.m16n8k16.row.col.f32.bf16.bf16.f32 "
        "{%0,%1,%2,%3}, {%4,%5,%6,%7}, {%8,%9}, {%0,%1,%2,%3};"
        : "+f"(d.x), "+f"(d.y), "+f"(d.z), "+f"(d.w)
        : "r"(a0), "r"(a1), "r"(a2), "r"(a3), "r"(b0), "r"(b1));
}
__device__ __forceinline__ void ldm4(uint32_t& r0, uint32_t& r1, uint32_t& r2, uint32_t& r3,
                                     uint32_t addr) {
    asm volatile("ldmatrix.sync.aligned.m8n8.x4.shared.b16 {%0,%1,%2,%3}, [%4];"
        : "=r"(r0), "=r"(r1), "=r"(r2), "=r"(r3) : "r"(addr));
}
__device__ __forceinline__ uint32_t smem_u32(const void* p) {
    uint32_t a;
    asm("{ .reg .u64 t; cvta.to.shared.u64 t, %1; cvt.u32.u64 %0, t; }" : "=r"(a) : "l"(p));
    return a;
}

// ---------------- device scratch ----------------
__device__ float g_x[NEL];
__device__ float g_xacc[NEL];
__device__ float g_h1[NEL];
__device__ float g_h2[NEL];
__device__ float g_skip[Bb*Sc*Nn];
__device__ float g_rs_s[Nn];
__device__ float g_rs_d[Bb*Nn];
__device__ float g_cs_d[Bb*Nn];
__device__ float g_stats[Bb*2];
__device__ bf16 g_Ahi[Bb*Nn*Nn];
__device__ bf16 g_Alo[Bb*Nn*Nn];
__device__ bf16 g_AThi[Bb*Nn*Nn];
__device__ bf16 g_ATlo[Bb*Nn*Nn];
__device__ bf16 g_Shi[Nn*Nn];
__device__ bf16 g_Slo[Nn*Nn];
__device__ bf16 g_sxHi[NEL];
__device__ bf16 g_sxLo[NEL];
__device__ bf16 g_s1Hi[NEL];
__device__ bf16 g_s1Lo[NEL];
// transposed-split activations: [b][n][128]
__device__ bf16 g_in1Th[Bb*Nn*Hc];
__device__ bf16 g_in1Tl[Bb*Nn*Hc];
__device__ bf16 g_hidTh[Bb*Nn*Hc];
__device__ bf16 g_hidTl[Bb*Nn*Hc];
__device__ bf16 g_hid2Th[Bb*Nn*Hc];
__device__ bf16 g_hid2Tl[Bb*Nn*Hc];
// split weights
__device__ bf16 g_eWfh[6*Hc*Hc];
__device__ bf16 g_eWfl[6*Hc*Hc];
__device__ bf16 g_eWgh[6*Hc*Hc];
__device__ bf16 g_eWgl[6*Hc*Hc];
__device__ bf16 g_skWh[3*Sc*Hc];
__device__ bf16 g_skWl[3*Sc*Hc];

struct Srcs { const float* p[8]; };

__device__ __forceinline__ void bsplit(float a, bf16& h, bf16& l) {
    h = __float2bfloat16(a);
    l = __float2bfloat16(a - __bfloat162float(h));
}
__device__ __forceinline__ uint32_t bpack(bf16 a, bf16 b) {
    __nv_bfloat162 t; t.x = a; t.y = b;
    return *reinterpret_cast<uint32_t*>(&t);
}

// ---------------- helpers ----------------
__device__ __forceinline__ float blockReduceSum(float v) {
    __shared__ float sh[32];
    int lane = threadIdx.x & 31, wid = threadIdx.x >> 5;
    #pragma unroll
    for (int o = 16; o; o >>= 1) v += __shfl_down_sync(0xffffffffu, v, o);
    __syncthreads();
    if (lane == 0) sh[wid] = v;
    __syncthreads();
    int nw = blockDim.x >> 5;
    v = (threadIdx.x < nw) ? sh[threadIdx.x] : 0.f;
    if (wid == 0) {
        #pragma unroll
        for (int o = 16; o; o >>= 1) v += __shfl_down_sync(0xffffffffu, v, o);
    }
    return v;
}

// copy + split + transposed x-part of in1T
__global__ void copy_split_k(float* __restrict__ dst, const float* __restrict__ src) {
    int i = blockIdx.x * 256 + threadIdx.x;
    if (i >= NEL / 4) return;
    float4 a = ((const float4*)src)[i];
    ((float4*)dst)[i] = a;
    bf16 h[4], l[4];
    bsplit(a.x, h[0], l[0]); bsplit(a.y, h[1], l[1]);
    bsplit(a.z, h[2], l[2]); bsplit(a.w, h[3], l[3]);
    ((uint2*)g_sxHi)[i] = make_uint2(bpack(h[0], h[1]), bpack(h[2], h[3]));
    ((uint2*)g_sxLo)[i] = make_uint2(bpack(l[0], l[1]), bpack(l[2], l[3]));
    int n4 = i % (Nn / 4);
    int c  = (i / (Nn / 4)) % Ee;
    int b  = i / (Ee * Nn / 4);
    size_t base = ((size_t)b * Nn + n4 * 4) * Hc + c;
    #pragma unroll
    for (int u = 0; u < 4; u++) {
        g_in1Th[base + (size_t)u * Hc] = h[u];
        g_in1Tl[base + (size_t)u * Hc] = l[u];
    }
}

__global__ void copyk(float* __restrict__ dst, const float* __restrict__ src, int n) {
    int i = blockIdx.x * 256 + threadIdx.x;
    if (i < n) dst[i] = src[i];
}

// ---------------- fused prep ----------------
__global__ void init_den_k() {
    int i = blockIdx.x * 256 + threadIdx.x;
    if (i < Nn) g_rs_s[i] = 1.0f;
    if (i < Bb * Nn) { g_rs_d[i] = 1.0f; g_cs_d[i] = 1.0f; }
}

__global__ void prepA_k(const float* __restrict__ A) {
    __shared__ float sh[64][68];
    const int b = blockIdx.z;
    const int r0 = blockIdx.x * 64, c0 = blockIdx.y * 64;
    const int tid = threadIdx.x;
    const int row = tid >> 2, q = tid & 3;

    const float* Ab = A + (size_t)b * Nn * Nn;
    float rsum = 0.f;
    #pragma unroll
    for (int j = 0; j < 4; j++) {
        int idx4 = q + j * 4;
        float4 v = *(const float4*)&Ab[(size_t)(r0 + row) * Nn + c0 + idx4 * 4];
        *(float4*)&sh[row][idx4 * 4] = v;
        rsum += v.x + v.y + v.z + v.w;
        bf16 h0, h1, h2, h3, l0, l1, l2, l3;
        bsplit(v.x, h0, l0); bsplit(v.y, h1, l1); bsplit(v.z, h2, l2); bsplit(v.w, h3, l3);
        size_t o = ((size_t)b * Nn + r0 + row) * Nn + c0 + idx4 * 4;
        *(uint2*)&g_Ahi[o] = make_uint2(bpack(h0, h1), bpack(h2, h3));
        *(uint2*)&g_Alo[o] = make_uint2(bpack(l0, l1), bpack(l2, l3));
    }
    rsum += __shfl_down_sync(0xffffffffu, rsum, 1);
    rsum += __shfl_down_sync(0xffffffffu, rsum, 2);
    if (q == 0) atomicAdd(&g_rs_d[b * Nn + r0 + row], rsum);
    __syncthreads();
    float csum = 0.f;
    #pragma unroll
    for (int j = 0; j < 4; j++) {
        int idx4 = q + j * 4;
        float4 v;
        v.x = sh[idx4 * 4 + 0][row];
        v.y = sh[idx4 * 4 + 1][row];
        v.z = sh[idx4 * 4 + 2][row];
        v.w = sh[idx4 * 4 + 3][row];
        csum += v.x + v.y + v.z + v.w;
        bf16 h0, h1, h2, h3, l0, l1, l2, l3;
        bsplit(v.x, h0, l0); bsplit(v.y, h1, l1); bsplit(v.z, h2, l2); bsplit(v.w, h3, l3);
        size_t o = ((size_t)b * Nn + c0 + row) * Nn + r0 + idx4 * 4;
        *(uint2*)&g_AThi[o] = make_uint2(bpack(h0, h1), bpack(h2, h3));
        *(uint2*)&g_ATlo[o] = make_uint2(bpack(l0, l1), bpack(l2, l3));
    }
    csum += __shfl_down_sync(0xffffffffu, csum, 1);
    csum += __shfl_down_sync(0xffffffffu, csum, 2);
    if (q == 0) atomicAdd(&g_cs_d[b * Nn + c0 + row], csum);
}

__global__ void prepS_k(const float* __restrict__ S) {
    const int r0 = blockIdx.x * 64, c0 = blockIdx.y * 64;
    const int tid = threadIdx.x;
    const int row = tid >> 2, q = tid & 3;
    float rsum = 0.f;
    #pragma unroll
    for (int j = 0; j < 4; j++) {
        int idx4 = q + j * 4;
        float4 v = *(const float4*)&S[(size_t)(r0 + row) * Nn + c0 + idx4 * 4];
        rsum += v.x + v.y + v.z + v.w;
        bf16 h0, h1, h2, h3, l0, l1, l2, l3;
        bsplit(v.x, h0, l0); bsplit(v.y, h1, l1); bsplit(v.z, h2, l2); bsplit(v.w, h3, l3);
        size_t o = (size_t)(r0 + row) * Nn + c0 + idx4 * 4;
        *(uint2*)&g_Shi[o] = make_uint2(bpack(h0, h1), bpack(h2, h3));
        *(uint2*)&g_Slo[o] = make_uint2(bpack(l0, l1), bpack(l2, l3));
    }
    rsum += __shfl_down_sync(0xffffffffu, rsum, 1);
    rsum += __shfl_down_sync(0xffffffffu, rsum, 2);
    if (q == 0) atomicAdd(&g_rs_s[r0 + row], rsum);
}

// generic f32 -> bf16 hi/lo splitter (weights)
__global__ void cvt_k(const float* __restrict__ A, bf16* __restrict__ hi,
                      bf16* __restrict__ lo, int n4) {
    int i = blockIdx.x * 256 + threadIdx.x;
    if (i >= n4) return;
    float4 a = ((const float4*)A)[i];
    bf16 h0, h1, h2, h3, l0, l1, l2, l3;
    bsplit(a.x, h0, l0); bsplit(a.y, h1, l1); bsplit(a.z, h2, l2); bsplit(a.w, h3, l3);
    ((uint2*)hi)[i] = make_uint2(bpack(h0, h1), bpack(h2, h3));
    ((uint2*)lo)[i] = make_uint2(bpack(l0, l1), bpack(l2, l3));
}

// embeddings -> transposed-split in1T channels 32..127 (one-time)
__global__ void embT_k(const float* __restrict__ spE, const float* __restrict__ tdE,
                       const float* __restrict__ twE) {
    int idx = blockIdx.x * 256 + threadIdx.x;
    if (idx >= Bb * 96 * (Nn / 4)) return;
    int n4 = idx % (Nn / 4);
    int rest = idx / (Nn / 4);
    int ch = rest % 96, b = rest / 96;
    const float* src = (ch < 32) ? spE : (ch < 64 ? tdE : twE);
    int c = ch & 31;
    float4 v = *(const float4*)(src + ((size_t)b * 32 + c) * Nn + n4 * 4);
    int oc = 32 + ch;
    float vv[4] = {v.x, v.y, v.z, v.w};
    size_t base = ((size_t)b * Nn + n4 * 4) * Hc + oc;
    #pragma unroll
    for (int u = 0; u < 4; u++) {
        bf16 h, l; bsplit(vv[u], h, l);
        g_in1Th[base + (size_t)u * Hc] = h;
        g_in1Tl[base + (size_t)u * Hc] = l;
    }
}

// ---------------- HMMA SpMM with fused mixprop hop epilogue ------------------
__global__ void __launch_bounds__(256) spmm_mma(
        const bf16* __restrict__ Ahi, const bf16* __restrict__ Alo,
        size_t aBStride,
        const bf16* __restrict__ HhB, const bf16* __restrict__ HlB,
        const float* __restrict__ hin, const float* __restrict__ xin,
        const float* __restrict__ den, int denB, float* __restrict__ hout,
        int writeSplit) {
    __shared__ bf16 sAh[64 * AP];
    __shared__ bf16 sAl[64 * AP];
    __shared__ bf16 sHh[32 * AP];
    __shared__ bf16 sHl[32 * AP];

    const int tid = threadIdx.x, wid = tid >> 5, lane = tid & 31;
    const int g = lane >> 2, tg = lane & 3;
    const int vt = blockIdx.x, b = blockIdx.y;
    const int v0 = vt * 64;
    const int warpV = (wid >> 1) * 16;
    const int c0w = (wid & 1) * 16;

    const bf16* Ah = Ahi + (size_t)b * aBStride;
    const bf16* Al = Alo + (size_t)b * aBStride;
    const bf16* Hh = HhB + (size_t)b * Ee * Nn;
    const bf16* Hl = HlB + (size_t)b * Ee * Nn;
    const float* hb = hin + (size_t)b * Ee * Nn;

    const uint32_t sAh_u = smem_u32(sAh), sAl_u = smem_u32(sAl);
    const uint32_t sHh_u = smem_u32(sHh), sHl_u = smem_u32(sHl);
    const int rowA = warpV + (lane & 15);
    const int khA  = (lane >> 4) * 8;
    const uint32_t offA = (uint32_t)(rowA * AP + khA) * 2;
    const int rowB = c0w + (lane & 7) + ((lane >> 4) & 1) * 8;
    const int khB  = ((lane >> 3) & 1) * 8;
    const uint32_t offB = (uint32_t)(rowB * AP + khB) * 2;

    float4 acc[2] = {};

    int ar0 = tid >> 3,           au0 = tid & 7;
    int ar1 = (tid + 256) >> 3,   au1 = tid & 7;
    int hc  = tid >> 3,           hu = tid & 7;

    uint4 pAh0, pAh1, pAl0, pAl1, pHh, pHl;
    {
        pAh0 = *(const uint4*)(Ah + (size_t)(v0 + ar0) * Nn + au0 * 8);
        pAh1 = *(const uint4*)(Ah + (size_t)(v0 + ar1) * Nn + au1 * 8);
        pAl0 = *(const uint4*)(Al + (size_t)(v0 + ar0) * Nn + au0 * 8);
        pAl1 = *(const uint4*)(Al + (size_t)(v0 + ar1) * Nn + au1 * 8);
        pHh  = *(const uint4*)(Hh + (size_t)hc * Nn + hu * 8);
        pHl  = *(const uint4*)(Hl + (size_t)hc * Nn + hu * 8);
    }

    for (int ch = 0; ch < 32; ch++) {
        __syncthreads();
        *(uint4*)&sAh[ar0 * AP + au0 * 8] = pAh0;
        *(uint4*)&sAh[ar1 * AP + au1 * 8] = pAh1;
        *(uint4*)&sAl[ar0 * AP + au0 * 8] = pAl0;
        *(uint4*)&sAl[ar1 * AP + au1 * 8] = pAl1;
        *(uint4*)&sHh[hc * AP + hu * 8] = pHh;
        *(uint4*)&sHl[hc * AP + hu * 8] = pHl;
        if (ch < 31) {
            const int w0 = (ch + 1) * 64;
            pAh0 = *(const uint4*)(Ah + (size_t)(v0 + ar0) * Nn + w0 + au0 * 8);
            pAh1 = *(const uint4*)(Ah + (size_t)(v0 + ar1) * Nn + w0 + au1 * 8);
            pAl0 = *(const uint4*)(Al + (size_t)(v0 + ar0) * Nn + w0 + au0 * 8);
            pAl1 = *(const uint4*)(Al + (size_t)(v0 + ar1) * Nn + w0 + au1 * 8);
            pHh  = *(const uint4*)(Hh + (size_t)hc * Nn + w0 + hu * 8);
            pHl  = *(const uint4*)(Hl + (size_t)hc * Nn + w0 + hu * 8);
        }
        __syncthreads();
        #pragma unroll
        for (int ks = 0; ks < 4; ks++) {
            const uint32_t ko = ks * 32;
            uint32_t ah0, ah1, ah2, ah3, al0, al1, al2, al3;
            uint32_t bh00, bh01, bh10, bh11, bl00, bl01, bl10, bl11;
            ldm4(ah0, ah1, ah2, ah3, sAh_u + offA + ko);
            ldm4(al0, al1, al2, al3, sAl_u + offA + ko);
            ldm4(bh00, bh01, bh10, bh11, sHh_u + offB + ko);
            ldm4(bl00, bl01, bl10, bl11, sHl_u + offB + ko);
            hmma(acc[0], ah0, ah1, ah2, ah3, bh00, bh01);
            hmma(acc[0], ah0, ah1, ah2, ah3, bl00, bl01);
            hmma(acc[0], al0, al1, al2, al3, bh00, bh01);
            hmma(acc[1], ah0, ah1, ah2, ah3, bh10, bh11);
            hmma(acc[1], ah0, ah1, ah2, ah3, bl10, bl11);
            hmma(acc[1], al0, al1, al2, al3, bh10, bh11);
        }
    }

    const int vlo = v0 + warpV + g;
    const int vhi = vlo + 8;
    const float dn_lo = den[denB * b + vlo];
    const float dn_hi = den[denB * b + vhi];
    const float* xb = xin + (size_t)b * Ee * Nn;
    float* ob = hout + (size_t)b * Ee * Nn;
    bf16* oh = g_s1Hi + (size_t)b * Ee * Nn;
    bf16* ol = g_s1Lo + (size_t)b * Ee * Nn;
    #pragma unroll
    for (int nt = 0; nt < 2; nt++) {
        int c0 = c0w + nt * 8 + 2 * tg;
        float vals[4];
        size_t idxs[4];
        idxs[0] = (size_t)c0 * Nn + vlo;
        idxs[1] = (size_t)(c0 + 1) * Nn + vlo;
        idxs[2] = (size_t)c0 * Nn + vhi;
        idxs[3] = (size_t)(c0 + 1) * Nn + vhi;
        vals[0] = ALPHA * xb[idxs[0]] + (1.0f - ALPHA) * ((acc[nt].x + hb[idxs[0]]) / dn_lo);
        vals[1] = ALPHA * xb[idxs[1]] + (1.0f - ALPHA) * ((acc[nt].y + hb[idxs[1]]) / dn_lo);
        vals[2] = ALPHA * xb[idxs[2]] + (1.0f - ALPHA) * ((acc[nt].z + hb[idxs[2]]) / dn_hi);
        vals[3] = ALPHA * xb[idxs[3]] + (1.0f - ALPHA) * ((acc[nt].w + hb[idxs[3]]) / dn_hi);
        #pragma unroll
        for (int u = 0; u < 4; u++) {
            ob[idxs[u]] = vals[u];
            if (writeSplit) {
                bf16 h, l; bsplit(vals[u], h, l);
                oh[idxs[u]] = h;
                ol[idxs[u]] = l;
            }
        }
    }
}

// ---------------- HMMA gated conv: out = tanh(Wf in+bf)*sigmoid(Wg in+bg) ----
// in/out in transposed-split layout [b][n][128]. Block 256 thr, tile 128m x 64n.
__global__ void __launch_bounds__(256) gated_mma(
        const bf16* __restrict__ inTh, const bf16* __restrict__ inTl,
        const bf16* __restrict__ Wfh, const bf16* __restrict__ Wfl,
        const bf16* __restrict__ Wgh, const bf16* __restrict__ Wgl,
        const float* __restrict__ bf_, const float* __restrict__ bg_,
        bf16* __restrict__ outTh, bf16* __restrict__ outTl) {
    __shared__ bf16 sWfh[Hc * CP], sWfl[Hc * CP], sWgh[Hc * CP], sWgl[Hc * CP];
    __shared__ bf16 sIh[64 * CP], sIl[64 * CP];

    const int tid = threadIdx.x, wid = tid >> 5, lane = tid & 31;
    const int g = lane >> 2, tg = lane & 3;
    const int col0 = blockIdx.x * 64;
    const int b = col0 / Nn, n0 = col0 % Nn;
    const int warpM = wid * 16;

    const uint32_t sWfh_u = smem_u32(sWfh), sWfl_u = smem_u32(sWfl);
    const uint32_t sWgh_u = smem_u32(sWgh), sWgl_u = smem_u32(sWgl);
    const uint32_t sIh_u = smem_u32(sIh), sIl_u = smem_u32(sIl);
    const uint32_t offA = (uint32_t)((warpM + (lane & 15)) * CP + (lane >> 4) * 8) * 2;
    const uint32_t offB = (uint32_t)(((lane & 7) + ((lane >> 4) & 1) * 8) * CP
                                     + ((lane >> 3) & 1) * 8) * 2;

    float4 aF[8] = {}, aG[8] = {};

    const int wrow = tid >> 1, whalf = tid & 1;   // weights: 128 rows x 2 halves
    const int it = tid & 127, iarr = tid >> 7;    // input: 64 rows x 2 halves x 2 arrays
    const int irow = it >> 1, ihalf = it & 1;
    const bf16* isrc = iarr ? inTl : inTh;
    bf16* idst = iarr ? sIl : sIh;

    for (int chunk = 0; chunk < 8; chunk++) {
        const int k0 = chunk * 16;
        __syncthreads();
        size_t wg = (size_t)wrow * Hc + k0 + whalf * 8;
        *(uint4*)&sWfh[wrow * CP + whalf * 8] = *(const uint4*)(Wfh + wg);
        *(uint4*)&sWfl[wrow * CP + whalf * 8] = *(const uint4*)(Wfl + wg);
        *(uint4*)&sWgh[wrow * CP + whalf * 8] = *(const uint4*)(Wgh + wg);
        *(uint4*)&sWgl[wrow * CP + whalf * 8] = *(const uint4*)(Wgl + wg);
        *(uint4*)&idst[irow * CP + ihalf * 8] =
            *(const uint4*)(isrc + ((size_t)b * Nn + n0 + irow) * Hc + k0 + ihalf * 8);
        __syncthreads();

        uint32_t fh0, fh1, fh2, fh3, fl0, fl1, fl2, fl3;
        uint32_t gh0, gh1, gh2, gh3, gl0, gl1, gl2, gl3;
        ldm4(fh0, fh1, fh2, fh3, sWfh_u + offA);
        ldm4(fl0, fl1, fl2, fl3, sWfl_u + offA);
        ldm4(gh0, gh1, gh2, gh3, sWgh_u + offA);
        ldm4(gl0, gl1, gl2, gl3, sWgl_u + offA);
        #pragma unroll
        for (int grp = 0; grp < 4; grp++) {
            const uint32_t go = (uint32_t)(grp * 16 * CP) * 2;
            uint32_t bh0, bh1, bh2, bh3, bl0, bl1, bl2, bl3;
            ldm4(bh0, bh1, bh2, bh3, sIh_u + go + offB);
            ldm4(bl0, bl1, bl2, bl3, sIl_u + go + offB);
            hmma(aF[2*grp], fh0, fh1, fh2, fh3, bh0, bh1);
            hmma(aF[2*grp], fh0, fh1, fh2, fh3, bl0, bl1);
            hmma(aF[2*grp], fl0, fl1, fl2, fl3, bh0, bh1);
            hmma(aF[2*grp+1], fh0, fh1, fh2, fh3, bh2, bh3);
            hmma(aF[2*grp+1], fh0, fh1, fh2, fh3, bl2, bl3);
            hmma(aF[2*grp+1], fl0, fl1, fl2, fl3, bh2, bh3);
            hmma(aG[2*grp], gh0, gh1, gh2, gh3, bh0, bh1);
            hmma(aG[2*grp], gh0, gh1, gh2, gh3, bl0, bl1);
            hmma(aG[2*grp], gl0, gl1, gl2, gl3, bh0, bh1);
            hmma(aG[2*grp+1], gh0, gh1, gh2, gh3, bh2, bh3);
            hmma(aG[2*grp+1], gh0, gh1, gh2, gh3, bl2, bl3);
            hmma(aG[2*grp+1], gl0, gl1, gl2, gl3, bh2, bh3);
        }
    }

    const int m_lo = warpM + g, m_hi = m_lo + 8;
    const float bflo = bf_[m_lo], bfhi = bf_[m_hi];
    const float bglo = bg_[m_lo], bghi = bg_[m_hi];
    #pragma unroll
    for (int nt = 0; nt < 8; nt++) {
        int n = n0 + nt * 8 + 2 * tg;
        size_t r0 = ((size_t)b * Nn + n) * Hc;
        size_t r1 = r0 + Hc;
        float v0 = tanhf(aF[nt].x + bflo) * (1.f / (1.f + expf(-(aG[nt].x + bglo))));
        float v1 = tanhf(aF[nt].y + bflo) * (1.f / (1.f + expf(-(aG[nt].y + bglo))));
        float v2 = tanhf(aF[nt].z + bfhi) * (1.f / (1.f + expf(-(aG[nt].z + bghi))));
        float v3 = tanhf(aF[nt].w + bfhi) * (1.f / (1.f + expf(-(aG[nt].w + bghi))));
        bf16 h, l;
        bsplit(v0, h, l); outTh[r0 + m_lo] = h; outTl[r0 + m_lo] = l;
        bsplit(v1, h, l); outTh[r1 + m_lo] = h; outTl[r1 + m_lo] = l;
        bsplit(v2, h, l); outTh[r0 + m_hi] = h; outTl[r0 + m_hi] = l;
        bsplit(v3, h, l); outTh[r1 + m_hi] = h; outTl[r1 + m_hi] = l;
    }
}

// ---------------- HMMA skip conv: skip (+)= W @ hid2 + bias ----------------
__global__ void __launch_bounds__(256) skip_mma(
        const bf16* __restrict__ inTh, const bf16* __restrict__ inTl,
        const bf16* __restrict__ Wh, const bf16* __restrict__ Wl,
        const float* __restrict__ bias, float* __restrict__ out, int accFlag) {
    __shared__ bf16 sWh[Hc * CP], sWl[Hc * CP];
    __shared__ bf16 sIh[64 * CP], sIl[64 * CP];

    const int tid = threadIdx.x, wid = tid >> 5, lane = tid & 31;
    const int g = lane >> 2, tg = lane & 3;
    const int col0 = blockIdx.x * 64;
    const int b = col0 / Nn, n0 = col0 % Nn;
    const int mbase = blockIdx.y * 128;
    const int warpM = wid * 16;

    const uint32_t sWh_u = smem_u32(sWh), sWl_u = smem_u32(sWl);
    const uint32_t sIh_u = smem_u32(sIh), sIl_u = smem_u32(sIl);
    const uint32_t offA = (uint32_t)((warpM + (lane & 15)) * CP + (lane >> 4) * 8) * 2;
    const uint32_t offB = (uint32_t)(((lane & 7) + ((lane >> 4) & 1) * 8) * CP
                                     + ((lane >> 3) & 1) * 8) * 2;

    float4 acc[8] = {};

    const int wrow = tid >> 1, whalf = tid & 1;
    const int it = tid & 127, iarr = tid >> 7;
    const int irow = it >> 1, ihalf = it & 1;
    const bf16* isrc = iarr ? inTl : inTh;
    bf16* idst = iarr ? sIl : sIh;

    for (int chunk = 0; chunk < 8; chunk++) {
        const int k0 = chunk * 16;
        __syncthreads();
        size_t wg = (size_t)(mbase + wrow) * Hc + k0 + whalf * 8;
        *(uint4*)&sWh[wrow * CP + whalf * 8] = *(const uint4*)(Wh + wg);
        *(uint4*)&sWl[wrow * CP + whalf * 8] = *(const uint4*)(Wl + wg);
        *(uint4*)&idst[irow * CP + ihalf * 8] =
            *(const uint4*)(isrc + ((size_t)b * Nn + n0 + irow) * Hc + k0 + ihalf * 8);
        __syncthreads();

        uint32_t wh0, wh1, wh2, wh3, wl0, wl1, wl2, wl3;
        ldm4(wh0, wh1, wh2, wh3, sWh_u + offA);
        ldm4(wl0, wl1, wl2, wl3, sWl_u + offA);
        #pragma unroll
        for (int grp = 0; grp < 4; grp++) {
            const uint32_t go = (uint32_t)(grp * 16 * CP) * 2;
            uint32_t bh0, bh1, bh2, bh3, bl0, bl1, bl2, bl3;
            ldm4(bh0, bh1, bh2, bh3, sIh_u + go + offB);
            ldm4(bl0, bl1, bl2, bl3, sIl_u + go + offB);
            hmma(acc[2*grp], wh0, wh1, wh2, wh3, bh0, bh1);
            hmma(acc[2*grp], wh0, wh1, wh2, wh3, bl0, bl1);
            hmma(acc[2*grp], wl0, wl1, wl2, wl3, bh0, bh1);
            hmma(acc[2*grp+1], wh0, wh1, wh2, wh3, bh2, bh3);
            hmma(acc[2*grp+1], wh0, wh1, wh2, wh3, bl2, bl3);
            hmma(acc[2*grp+1], wl0, wl1, wl2, wl3, bh2, bh3);
        }
    }

    const int m_lo = mbase + warpM + g, m_hi = m_lo + 8;
    const float blo = bias[m_lo], bhi = bias[m_hi];
    #pragma unroll
    for (int nt = 0; nt < 8; nt++) {
        int n = n0 + nt * 8 + 2 * tg;
        float* d0 = &out[((size_t)b * Sc + m_lo) * Nn + n];
        float* d1 = &out[((size_t)b * Sc + m_hi) * Nn + n];
        float2 r0 = make_float2(acc[nt].x + blo, acc[nt].y + blo);
        float2 r1 = make_float2(acc[nt].z + bhi, acc[nt].w + bhi);
        if (accFlag) {
            float2 o0 = *(float2*)d0, o1 = *(float2*)d1;
            r0.x += o0.x; r0.y += o0.y; r1.x += o1.x; r1.y += o1.y;
        }
        *(float2*)d0 = r0;
        *(float2*)d1 = r1;
    }
}

// ---------------- generic 1x1 conv (channel-mix GEMM), f32x2 packed ----------
__global__ void conv1x1_k(Srcs srcs, int inBStride,
                          const float* __restrict__ W, const float* __restrict__ bias,
                          int M, int K, float* __restrict__ out, int outBStride, int accFlag) {
    __shared__ float Ws[16 * 68];
    __shared__ float Ins[16 * 68];
    const int tid = threadIdx.x;
    const int tx = tid & 15, ty = tid >> 4;
    const int col0 = blockIdx.x * 64;
    const int b = col0 / Nn, n0 = col0 % Nn;
    const int m0 = blockIdx.y * 64;

    u64 accP[4][2] = {};

    for (int k0 = 0; k0 < K; k0 += 16) {
        for (int t = tid; t < 1024; t += 256) {
            int m = t >> 4, kk = t & 15;
            Ws[kk * 68 + m] = (m0 + m < M) ? W[(size_t)(m0 + m) * K + k0 + kk] : 0.f;
        }
        for (int t = tid; t < 1024; t += 256) {
            int kk = t >> 6, n = t & 63;
            int c = k0 + kk;
            Ins[kk * 68 + n] = srcs.p[c >> 5][(size_t)b * inBStride + (size_t)(c & 31) * Nn + n0 + n];
        }
        __syncthreads();
        #pragma unroll
        for (int kk = 0; kk < 16; kk++) {
            float4 wv = *(const float4*)&Ws[kk * 68 + ty * 4];
            u64 ip0 = *(const u64*)&Ins[kk * 68 + tx * 4];
            u64 ip1 = *(const u64*)&Ins[kk * 68 + tx * 4 + 2];
            float wa[4] = {wv.x, wv.y, wv.z, wv.w};
            #pragma unroll
            for (int u = 0; u < 4; u++) {
                u64 wp = splat2(wa[u]);
                accP[u][0] = fma2(wp, ip0, accP[u][0]);
                accP[u][1] = fma2(wp, ip1, accP[u][1]);
            }
        }
        __syncthreads();
    }
    #pragma unroll
    for (int u = 0; u < 4; u++) {
        int m = m0 + ty * 4 + u;
        if (m >= M) break;
        float bm = bias[m];
        float4 r;
        upk2(accP[u][0], r.x, r.y);
        upk2(accP[u][1], r.z, r.w);
        r.x += bm; r.y += bm; r.z += bm; r.w += bm;
        float* dst = &out[(size_t)b * outBStride + (size_t)m * Nn + n0 + tx * 4];
        if (accFlag) {
            float4 o = *(float4*)dst;
            r.x += o.x; r.y += o.y; r.z += o.z; r.w += o.w;
        }
        *(float4*)dst = r;
    }
}

// ---------------- layernorm ----------------
__global__ void ln_stats_k() {
    int b = blockIdx.x;
    const float* xp = g_xacc + (size_t)b * Ee * Nn;
    float s = 0.f, s2 = 0.f;
    for (int i = threadIdx.x; i < Ee * Nn; i += blockDim.x) {
        float v = xp[i];
        s += v; s2 += v * v;
    }
    float ts = blockReduceSum(s);
    float ts2 = blockReduceSum(s2);
    if (threadIdx.x == 0) {
        float inv = 1.0f / (Ee * Nn);
        float mu = ts * inv;
        g_stats[b * 2] = mu;
        g_stats[b * 2 + 1] = ts2 * inv - mu * mu;
    }
}

// layernorm+relu -> g_x, splits, and transposed x-part of in1T
__global__ void ln_apply_k(const float* __restrict__ w, const float* __restrict__ bparm) {
    int i = blockIdx.x * 256 + threadIdx.x;
    if (i >= NEL) return;
    int b = i >> 16;              // /(Ee*Nn)
    int cn = i & (Ee * Nn - 1);
    float mu = g_stats[b * 2];
    float var = g_stats[b * 2 + 1];
    float val = (g_xacc[i] - mu) * rsqrtf(var + EPSV) * w[cn] + bparm[cn];
    val = fmaxf(val, 0.f);
    g_x[i] = val;
    bf16 h, l; bsplit(val, h, l);
    g_sxHi[i] = h;
    g_sxLo[i] = l;
    int n = i & (Nn - 1);
    int c = (i >> 11) & 31;
    size_t o = ((size_t)b * Nn + n) * Hc + c;
    g_in1Th[o] = h;
    g_in1Tl[o] = l;
}

// ---------------- host orchestration ----------------
extern "C" void kernel_launch(void* const* d_in, const int* in_sizes, int n_in,
                              void* d_out, int out_size) {
    (void)in_sizes; (void)n_in; (void)out_size;
    const float* in_x  = (const float*)d_in[0];
    const float* dyG   = (const float*)d_in[1];
    const float* stG   = (const float*)d_in[2];
    const float* spE   = (const float*)d_in[3];
    const float* tdE   = (const float*)d_in[4];
    const float* twE   = (const float*)d_in[5];
    const float* encWf = (const float*)d_in[6];
    const float* encbf = (const float*)d_in[7];
    const float* encWg = (const float*)d_in[8];
    const float* encbg = (const float*)d_in[9];
    const float* skW   = (const float*)d_in[10];
    const float* skb   = (const float*)d_in[11];
    const float* nw    = (const float*)d_in[12];
    const float* nb    = (const float*)d_in[13];
    const float* gW[3] = {(const float*)d_in[14], (const float*)d_in[16], (const float*)d_in[18]};
    const float* gb[3] = {(const float*)d_in[15], (const float*)d_in[17], (const float*)d_in[19]};
    const float* seW   = (const float*)d_in[20];
    const float* seb   = (const float*)d_in[21];
    const float* eW    = (const float*)d_in[22];
    const float* eb    = (const float*)d_in[23];
    float* outp = (float*)d_out;

    float *px, *pxacc, *ph1, *ph2, *pskip, *prss, *prsd, *pcsd;
    cudaGetSymbolAddress((void**)&px,    g_x);
    cudaGetSymbolAddress((void**)&pxacc, g_xacc);
    cudaGetSymbolAddress((void**)&ph1,   g_h1);
    cudaGetSymbolAddress((void**)&ph2,   g_h2);
    cudaGetSymbolAddress((void**)&pskip, g_skip);
    cudaGetSymbolAddress((void**)&prss,  g_rs_s);
    cudaGetSymbolAddress((void**)&prsd,  g_rs_d);
    cudaGetSymbolAddress((void**)&pcsd,  g_cs_d);
    bf16 *pAhi, *pAlo, *pAThi, *pATlo, *pShi, *pSlo, *psxHi, *psxLo, *ps1Hi, *ps1Lo;
    cudaGetSymbolAddress((void**)&pAhi,  g_Ahi);
    cudaGetSymbolAddress((void**)&pAlo,  g_Alo);
    cudaGetSymbolAddress((void**)&pAThi, g_AThi);
    cudaGetSymbolAddress((void**)&pATlo, g_ATlo);
    cudaGetSymbolAddress((void**)&pShi,  g_Shi);
    cudaGetSymbolAddress((void**)&pSlo,  g_Slo);
    cudaGetSymbolAddress((void**)&psxHi, g_sxHi);
    cudaGetSymbolAddress((void**)&psxLo, g_sxLo);
    cudaGetSymbolAddress((void**)&ps1Hi, g_s1Hi);
    cudaGetSymbolAddress((void**)&ps1Lo, g_s1Lo);
    bf16 *pin1Th, *pin1Tl, *phidTh, *phidTl, *phid2Th, *phid2Tl;
    cudaGetSymbolAddress((void**)&pin1Th, g_in1Th);
    cudaGetSymbolAddress((void**)&pin1Tl, g_in1Tl);
    cudaGetSymbolAddress((void**)&phidTh, g_hidTh);
    cudaGetSymbolAddress((void**)&phidTl, g_hidTl);
    cudaGetSymbolAddress((void**)&phid2Th, g_hid2Th);
    cudaGetSymbolAddress((void**)&phid2Tl, g_hid2Tl);
    bf16 *peWfh, *peWfl, *peWgh, *peWgl, *pskWh, *pskWl;
    cudaGetSymbolAddress((void**)&peWfh, g_eWfh);
    cudaGetSymbolAddress((void**)&peWfl, g_eWfl);
    cudaGetSymbolAddress((void**)&peWgh, g_eWgh);
    cudaGetSymbolAddress((void**)&peWgl, g_eWgl);
    cudaGetSymbolAddress((void**)&pskWh, g_skWh);
    cudaGetSymbolAddress((void**)&pskWl, g_skWl);

    // ---- prep ----
    copy_split_k<<<(NEL / 4 + 255) / 256, 256>>>(px, in_x);
    init_den_k<<<(Bb * Nn + 255) / 256, 256>>>();
    prepA_k<<<dim3(Nn / 64, Nn / 64, Bb), 256>>>(dyG);
    prepS_k<<<dim3(Nn / 64, Nn / 64), 256>>>(stG);
    cvt_k<<<(6 * Hc * Hc / 4 + 255) / 256, 256>>>(encWf, peWfh, peWfl, 6 * Hc * Hc / 4);
    cvt_k<<<(6 * Hc * Hc / 4 + 255) / 256, 256>>>(encWg, peWgh, peWgl, 6 * Hc * Hc / 4);
    cvt_k<<<(3 * Sc * Hc / 4 + 255) / 256, 256>>>(skW, pskWh, pskWl, 3 * Sc * Hc / 4);
    embT_k<<<(Bb * 96 * (Nn / 4) + 255) / 256, 256>>>(spE, tdE, twE);

    const dim3 convGrid(Bb * Nn / 64, 1);
    const dim3 spmmGrid(Nn / 64, Bb);
    for (int i = 0; i < 3; i++) {
        // ---- TCN chain (HMMA) ----
        gated_mma<<<Bb * Nn / 64, 256>>>(pin1Th, pin1Tl,
            peWfh + (size_t)(i * 2 + 0) * Hc * Hc, peWfl + (size_t)(i * 2 + 0) * Hc * Hc,
            peWgh + (size_t)(i * 2 + 0) * Hc * Hc, peWgl + (size_t)(i * 2 + 0) * Hc * Hc,
            encbf + (i * 2 + 0) * Hc, encbg + (i * 2 + 0) * Hc, phidTh, phidTl);
        gated_mma<<<Bb * Nn / 64, 256>>>(phidTh, phidTl,
            peWfh + (size_t)(i * 2 + 1) * Hc * Hc, peWfl + (size_t)(i * 2 + 1) * Hc * Hc,
            peWgh + (size_t)(i * 2 + 1) * Hc * Hc, peWgl + (size_t)(i * 2 + 1) * Hc * Hc,
            encbf + (i * 2 + 1) * Hc, encbg + (i * 2 + 1) * Hc, phid2Th, phid2Tl);
        // ---- skip += skip_W @ hidden (HMMA) ----
        skip_mma<<<dim3(Bb * Nn / 64, 2), 256>>>(phid2Th, phid2Tl,
            pskWh + (size_t)i * Sc * Hc, pskWl + (size_t)i * Sc * Hc,
            skb + i * Sc, pskip, i > 0);
        // ---- mixprops ----
        copyk<<<NEL / 256, 256>>>(pxacc, px, NEL);
        for (int g = 0; g < 3; g++) {
            const bf16* Ah = (g == 0) ? pShi : (g == 1 ? pAhi : pAThi);
            const bf16* Al = (g == 0) ? pSlo : (g == 1 ? pAlo : pATlo);
            size_t abst = (g == 0) ? 0 : (size_t)Nn * Nn;
            const float* den = (g == 0) ? prss : (g == 1 ? prsd : pcsd);
            int denB = (g == 0) ? 0 : Nn;
            spmm_mma<<<spmmGrid, 256>>>(Ah, Al, abst, psxHi, psxLo, px, px, den, denB, ph1, 1);
            spmm_mma<<<spmmGrid, 256>>>(Ah, Al, abst, ps1Hi, ps1Lo, ph1, px, den, denB, ph2, 0);
            Srcs sm; sm.p[0] = px; sm.p[1] = ph1; sm.p[2] = ph2;
            conv1x1_k<<<convGrid, 256>>>(sm, Ee * Nn,
                gW[g] + (size_t)i * Ee * 96, gb[g] + i * Ee, Ee, 96, pxacc, Ee * Nn, 1);
        }
        // ---- layernorm + relu -> new x (+ splits + in1T x-part) ----
        ln_stats_k<<<Bb, 1024>>>();
        ln_apply_k<<<NEL / 256, 256>>>(nw + (size_t)i * Ee * Nn, nb + (size_t)i * Ee * Nn);
    }
    // ---- skip end + output ----
    Srcs se; se.p[0] = px;
    conv1x1_k<<<dim3(Bb * Nn / 64, 4), 256>>>(se, Ee * Nn, seW, seb, Sc, Ee, pskip, Sc * Nn, 1);
    Srcs send; for (int s = 0; s < 8; s++) send.p[s] = pskip + (size_t)s * 32 * Nn;
    conv1x1_k<<<convGrid, 256>>>(send, Sc * Nn, eW, eb, Tt, Sc, outp, Tt * Nn, 0);
}

// round 11
// speedup vs baseline: 1.9303x; 1.0238x over previous
#include <cuda_runtime.h>
#include <cuda_bf16.h>
#include <math.h>
#include <stdint.h>

#define Bb 8
#define Nn 2048
#define Ee 32
#define Hc 128
#define Sc 256
#define Tt 12
#define NEL (Bb*Ee*Nn)
#define ALPHA 0.05f
#define EPSV 1e-5f
#define AP 72   // spmm smem pitch bf16 (144B)
#define CP 24   // conv smem pitch bf16 (48B)

typedef unsigned long long u64;
typedef __nv_bfloat16 bf16;

// ---------------- packed fp32x2 helpers (for SIMT convs) ----------------
__device__ __forceinline__ u64 splat2(float a) {
    u64 d; asm("mov.b64 %0, {%1, %1};" : "=l"(d) : "f"(a)); return d;
}
__device__ __forceinline__ void upk2(u64 v, float& lo, float& hi) {
    asm("mov.b64 {%0, %1}, %2;" : "=f"(lo), "=f"(hi) : "l"(v));
}
__device__ __forceinline__ u64 fma2(u64 a, u64 b, u64 c) {
    u64 d; asm("fma.rn.f32x2 %0, %1, %2, %3;" : "=l"(d) : "l"(a), "l"(b), "l"(c)); return d;
}

// ---------------- warp-level bf16 MMA + ldmatrix ----------------
__device__ __forceinline__ void hmma(float4& d, uint32_t a0, uint32_t a1, uint32_t a2,
                                     uint32_t a3, uint32_t b0, uint32_t b1) {
    asm volatile(
        "mma.sync.aligned.m16n8k16.row.col.f32.bf16.bf16.f32 "
        "{%0,%1,%2,%3}, {%4,%5,%6,%7}, {%8,%9}, {%0,%1,%2,%3};"
        : "+f"(d.x), "+f"(d.y), "+f"(d.z), "+f"(d.w)
        : "r"(a0), "r"(a1), "r"(a2), "r"(a3), "r"(b0), "r"(b1));
}
__device__ __forceinline__ void ldm4(uint32_t& r0, uint32_t& r1, uint32_t& r2, uint32_t& r3,
                                     uint32_t addr) {
    asm volatile("ldmatrix.sync.aligned.m8n8.x4.shared.b16 {%0,%1,%2,%3}, [%4];"
        : "=r"(r0), "=r"(r1), "=r"(r2), "=r"(r3) : "r"(addr));
}
__device__ __forceinline__ uint32_t smem_u32(const void* p) {
    uint32_t a;
    asm("{ .reg .u64 t; cvta.to.shared.u64 t, %1; cvt.u32.u64 %0, t; }" : "=r"(a) : "l"(p));
    return a;
}

// ---------------- device scratch ----------------
__device__ float g_x[NEL];
__device__ float g_xacc[NEL];
__device__ float g_h1g[3][NEL];
__device__ float g_h2g[3][NEL];
__device__ float g_skip[Bb*Sc*Nn];
__device__ float g_rs_s[Nn];
__device__ float g_rs_d[Bb*Nn];
__device__ float g_cs_d[Bb*Nn];
__device__ float g_red[Bb*2];
__device__ bf16 g_Ahi[Bb*Nn*Nn];
__device__ bf16 g_Alo[Bb*Nn*Nn];
__device__ bf16 g_AThi[Bb*Nn*Nn];
__device__ bf16 g_ATlo[Bb*Nn*Nn];
__device__ bf16 g_Shi[Nn*Nn];
__device__ bf16 g_Slo[Nn*Nn];
__device__ bf16 g_sxHi[NEL];
__device__ bf16 g_sxLo[NEL];
__device__ bf16 g_s1Hi[NEL];
__device__ bf16 g_s1Lo[NEL];
// transposed-split activations [b][n][128]
__device__ bf16 g_in1Th[Bb*Nn*Hc];
__device__ bf16 g_in1Tl[Bb*Nn*Hc];
__device__ bf16 g_hidTh[Bb*Nn*Hc];
__device__ bf16 g_hidTl[Bb*Nn*Hc];
__device__ bf16 g_hid2Th[Bb*Nn*Hc];
__device__ bf16 g_hid2Tl[Bb*Nn*Hc];
// split weights
__device__ bf16 g_eWfh[6*Hc*Hc];
__device__ bf16 g_eWfl[6*Hc*Hc];
__device__ bf16 g_eWgh[6*Hc*Hc];
__device__ bf16 g_eWgl[6*Hc*Hc];
__device__ bf16 g_skWh[3*Sc*Hc];
__device__ bf16 g_skWl[3*Sc*Hc];
// combined mixprop mlp weights: [3][32][224], bias [3][32]
__device__ float g_gWc[3*32*224];
__device__ float g_gbc[96];

struct Srcs { const float* p[8]; };

__device__ __forceinline__ void bsplit(float a, bf16& h, bf16& l) {
    h = __float2bfloat16(a);
    l = __float2bfloat16(a - __bfloat162float(h));
}
__device__ __forceinline__ uint32_t bpack(bf16 a, bf16 b) {
    __nv_bfloat162 t; t.x = a; t.y = b;
    return *reinterpret_cast<uint32_t*>(&t);
}

// ---------------- helpers ----------------
__device__ __forceinline__ float blockReduceSum(float v) {
    __shared__ float sh[32];
    int lane = threadIdx.x & 31, wid = threadIdx.x >> 5;
    #pragma unroll
    for (int o = 16; o; o >>= 1) v += __shfl_down_sync(0xffffffffu, v, o);
    __syncthreads();
    if (lane == 0) sh[wid] = v;
    __syncthreads();
    int nw = blockDim.x >> 5;
    v = (threadIdx.x < nw) ? sh[threadIdx.x] : 0.f;
    if (wid == 0) {
        #pragma unroll
        for (int o = 16; o; o >>= 1) v += __shfl_down_sync(0xffffffffu, v, o);
    }
    return v;
}

__global__ void copy_split_k(float* __restrict__ dst, const float* __restrict__ src) {
    int i = blockIdx.x * 256 + threadIdx.x;
    if (i >= NEL / 4) return;
    float4 a = ((const float4*)src)[i];
    ((float4*)dst)[i] = a;
    bf16 h[4], l[4];
    bsplit(a.x, h[0], l[0]); bsplit(a.y, h[1], l[1]);
    bsplit(a.z, h[2], l[2]); bsplit(a.w, h[3], l[3]);
    ((uint2*)g_sxHi)[i] = make_uint2(bpack(h[0], h[1]), bpack(h[2], h[3]));
    ((uint2*)g_sxLo)[i] = make_uint2(bpack(l[0], l[1]), bpack(l[2], l[3]));
    int n4 = i % (Nn / 4);
    int c  = (i / (Nn / 4)) % Ee;
    int b  = i / (Ee * Nn / 4);
    size_t base = ((size_t)b * Nn + n4 * 4) * Hc + c;
    #pragma unroll
    for (int u = 0; u < 4; u++) {
        g_in1Th[base + (size_t)u * Hc] = h[u];
        g_in1Tl[base + (size_t)u * Hc] = l[u];
    }
}

// ---------------- fused prep ----------------
__global__ void init_den_k() {
    int i = blockIdx.x * 256 + threadIdx.x;
    if (i < Nn) g_rs_s[i] = 1.0f;
    if (i < Bb * Nn) { g_rs_d[i] = 1.0f; g_cs_d[i] = 1.0f; }
}

__global__ void prepA_k(const float* __restrict__ A) {
    __shared__ float sh[64][68];
    const int b = blockIdx.z;
    const int r0 = blockIdx.x * 64, c0 = blockIdx.y * 64;
    const int tid = threadIdx.x;
    const int row = tid >> 2, q = tid & 3;

    const float* Ab = A + (size_t)b * Nn * Nn;
    float rsum = 0.f;
    #pragma unroll
    for (int j = 0; j < 4; j++) {
        int idx4 = q + j * 4;
        float4 v = *(const float4*)&Ab[(size_t)(r0 + row) * Nn + c0 + idx4 * 4];
        *(float4*)&sh[row][idx4 * 4] = v;
        rsum += v.x + v.y + v.z + v.w;
        bf16 h0, h1, h2, h3, l0, l1, l2, l3;
        bsplit(v.x, h0, l0); bsplit(v.y, h1, l1); bsplit(v.z, h2, l2); bsplit(v.w, h3, l3);
        size_t o = ((size_t)b * Nn + r0 + row) * Nn + c0 + idx4 * 4;
        *(uint2*)&g_Ahi[o] = make_uint2(bpack(h0, h1), bpack(h2, h3));
        *(uint2*)&g_Alo[o] = make_uint2(bpack(l0, l1), bpack(l2, l3));
    }
    rsum += __shfl_down_sync(0xffffffffu, rsum, 1);
    rsum += __shfl_down_sync(0xffffffffu, rsum, 2);
    if (q == 0) atomicAdd(&g_rs_d[b * Nn + r0 + row], rsum);
    __syncthreads();
    float csum = 0.f;
    #pragma unroll
    for (int j = 0; j < 4; j++) {
        int idx4 = q + j * 4;
        float4 v;
        v.x = sh[idx4 * 4 + 0][row];
        v.y = sh[idx4 * 4 + 1][row];
        v.z = sh[idx4 * 4 + 2][row];
        v.w = sh[idx4 * 4 + 3][row];
        csum += v.x + v.y + v.z + v.w;
        bf16 h0, h1, h2, h3, l0, l1, l2, l3;
        bsplit(v.x, h0, l0); bsplit(v.y, h1, l1); bsplit(v.z, h2, l2); bsplit(v.w, h3, l3);
        size_t o = ((size_t)b * Nn + c0 + row) * Nn + r0 + idx4 * 4;
        *(uint2*)&g_AThi[o] = make_uint2(bpack(h0, h1), bpack(h2, h3));
        *(uint2*)&g_ATlo[o] = make_uint2(bpack(l0, l1), bpack(l2, l3));
    }
    csum += __shfl_down_sync(0xffffffffu, csum, 1);
    csum += __shfl_down_sync(0xffffffffu, csum, 2);
    if (q == 0) atomicAdd(&g_cs_d[b * Nn + c0 + row], csum);
}

__global__ void prepS_k(const float* __restrict__ S) {
    const int r0 = blockIdx.x * 64, c0 = blockIdx.y * 64;
    const int tid = threadIdx.x;
    const int row = tid >> 2, q = tid & 3;
    float rsum = 0.f;
    #pragma unroll
    for (int j = 0; j < 4; j++) {
        int idx4 = q + j * 4;
        float4 v = *(const float4*)&S[(size_t)(r0 + row) * Nn + c0 + idx4 * 4];
        rsum += v.x + v.y + v.z + v.w;
        bf16 h0, h1, h2, h3, l0, l1, l2, l3;
        bsplit(v.x, h0, l0); bsplit(v.y, h1, l1); bsplit(v.z, h2, l2); bsplit(v.w, h3, l3);
        size_t o = (size_t)(r0 + row) * Nn + c0 + idx4 * 4;
        *(uint2*)&g_Shi[o] = make_uint2(bpack(h0, h1), bpack(h2, h3));
        *(uint2*)&g_Slo[o] = make_uint2(bpack(l0, l1), bpack(l2, l3));
    }
    rsum += __shfl_down_sync(0xffffffffu, rsum, 1);
    rsum += __shfl_down_sync(0xffffffffu, rsum, 2);
    if (q == 0) atomicAdd(&g_rs_s[r0 + row], rsum);
}

__global__ void cvt_k(const float* __restrict__ A, bf16* __restrict__ hi,
                      bf16* __restrict__ lo, int n4) {
    int i = blockIdx.x * 256 + threadIdx.x;
    if (i >= n4) return;
    float4 a = ((const float4*)A)[i];
    bf16 h0, h1, h2, h3, l0, l1, l2, l3;
    bsplit(a.x, h0, l0); bsplit(a.y, h1, l1); bsplit(a.z, h2, l2); bsplit(a.w, h3, l3);
    ((uint2*)hi)[i] = make_uint2(bpack(h0, h1), bpack(h2, h3));
    ((uint2*)lo)[i] = make_uint2(bpack(l0, l1), bpack(l2, l3));
}

__global__ void embT_k(const float* __restrict__ spE, const float* __restrict__ tdE,
                       const float* __restrict__ twE) {
    int idx = blockIdx.x * 256 + threadIdx.x;
    if (idx >= Bb * 96 * (Nn / 4)) return;
    int n4 = idx % (Nn / 4);
    int rest = idx / (Nn / 4);
    int ch = rest % 96, b = rest / 96;
    const float* src = (ch < 32) ? spE : (ch < 64 ? tdE : twE);
    int c = ch & 31;
    float4 v = *(const float4*)(src + ((size_t)b * 32 + c) * Nn + n4 * 4);
    int oc = 32 + ch;
    float vv[4] = {v.x, v.y, v.z, v.w};
    size_t base = ((size_t)b * Nn + n4 * 4) * Hc + oc;
    #pragma unroll
    for (int u = 0; u < 4; u++) {
        bf16 h, l; bsplit(vv[u], h, l);
        g_in1Th[base + (size_t)u * Hc] = h;
        g_in1Tl[base + (size_t)u * Hc] = l;
    }
}

// combined mixprop weights: Wc[i][m][0:32]=sum_g gWg[:,0:32];
// Wc[i][m][32+64g+j]=gWg[m][32+j], Wc[i][m][64+64g+j]=gWg[m][64+j]
__global__ void combW_k(const float* __restrict__ W0, const float* __restrict__ W1,
                        const float* __restrict__ W2) {
    int idx = blockIdx.x * 256 + threadIdx.x;
    if (idx >= 3 * 32 * 224) return;
    int c = idx % 224;
    int m = (idx / 224) % 32;
    int i = idx / (224 * 32);
    const float* W[3] = {W0 + (size_t)i * 32 * 96, W1 + (size_t)i * 32 * 96, W2 + (size_t)i * 32 * 96};
    float v;
    if (c < 32) v = W[0][m * 96 + c] + W[1][m * 96 + c] + W[2][m * 96 + c];
    else {
        int t = c - 32, g = t >> 6, j = t & 63;
        v = W[g][m * 96 + 32 + j];
    }
    g_gWc[idx] = v;
}
__global__ void combB_k(const float* __restrict__ b0, const float* __restrict__ b1,
                        const float* __restrict__ b2) {
    int idx = threadIdx.x;
    if (idx < 96) g_gbc[idx] = b0[idx] + b1[idx] + b2[idx];
}

// ---------------- HMMA SpMM with fused mixprop hop epilogue ------------------
__global__ void __launch_bounds__(256) spmm_mma(
        const bf16* __restrict__ Ahi, const bf16* __restrict__ Alo,
        size_t aBStride,
        const bf16* __restrict__ HhB, const bf16* __restrict__ HlB,
        const float* __restrict__ hin, const float* __restrict__ xin,
        const float* __restrict__ den, int denB, float* __restrict__ hout,
        int writeSplit) {
    __shared__ bf16 sAh[64 * AP];
    __shared__ bf16 sAl[64 * AP];
    __shared__ bf16 sHh[32 * AP];
    __shared__ bf16 sHl[32 * AP];

    const int tid = threadIdx.x, wid = tid >> 5, lane = tid & 31;
    const int g = lane >> 2, tg = lane & 3;
    const int vt = blockIdx.x, b = blockIdx.y;
    const int v0 = vt * 64;
    const int warpV = (wid >> 1) * 16;
    const int c0w = (wid & 1) * 16;

    const bf16* Ah = Ahi + (size_t)b * aBStride;
    const bf16* Al = Alo + (size_t)b * aBStride;
    const bf16* Hh = HhB + (size_t)b * Ee * Nn;
    const bf16* Hl = HlB + (size_t)b * Ee * Nn;
    const float* hb = hin + (size_t)b * Ee * Nn;

    const uint32_t sAh_u = smem_u32(sAh), sAl_u = smem_u32(sAl);
    const uint32_t sHh_u = smem_u32(sHh), sHl_u = smem_u32(sHl);
    const int rowA = warpV + (lane & 15);
    const int khA  = (lane >> 4) * 8;
    const uint32_t offA = (uint32_t)(rowA * AP + khA) * 2;
    const int rowB = c0w + (lane & 7) + ((lane >> 4) & 1) * 8;
    const int khB  = ((lane >> 3) & 1) * 8;
    const uint32_t offB = (uint32_t)(rowB * AP + khB) * 2;

    float4 acc[2] = {};

    int ar0 = tid >> 3,           au0 = tid & 7;
    int ar1 = (tid + 256) >> 3,   au1 = tid & 7;
    int hc  = tid >> 3,           hu = tid & 7;

    uint4 pAh0, pAh1, pAl0, pAl1, pHh, pHl;
    {
        pAh0 = *(const uint4*)(Ah + (size_t)(v0 + ar0) * Nn + au0 * 8);
        pAh1 = *(const uint4*)(Ah + (size_t)(v0 + ar1) * Nn + au1 * 8);
        pAl0 = *(const uint4*)(Al + (size_t)(v0 + ar0) * Nn + au0 * 8);
        pAl1 = *(const uint4*)(Al + (size_t)(v0 + ar1) * Nn + au1 * 8);
        pHh  = *(const uint4*)(Hh + (size_t)hc * Nn + hu * 8);
        pHl  = *(const uint4*)(Hl + (size_t)hc * Nn + hu * 8);
    }

    for (int ch = 0; ch < 32; ch++) {
        __syncthreads();
        *(uint4*)&sAh[ar0 * AP + au0 * 8] = pAh0;
        *(uint4*)&sAh[ar1 * AP + au1 * 8] = pAh1;
        *(uint4*)&sAl[ar0 * AP + au0 * 8] = pAl0;
        *(uint4*)&sAl[ar1 * AP + au1 * 8] = pAl1;
        *(uint4*)&sHh[hc * AP + hu * 8] = pHh;
        *(uint4*)&sHl[hc * AP + hu * 8] = pHl;
        if (ch < 31) {
            const int w0 = (ch + 1) * 64;
            pAh0 = *(const uint4*)(Ah + (size_t)(v0 + ar0) * Nn + w0 + au0 * 8);
            pAh1 = *(const uint4*)(Ah + (size_t)(v0 + ar1) * Nn + w0 + au1 * 8);
            pAl0 = *(const uint4*)(Al + (size_t)(v0 + ar0) * Nn + w0 + au0 * 8);
            pAl1 = *(const uint4*)(Al + (size_t)(v0 + ar1) * Nn + w0 + au1 * 8);
            pHh  = *(const uint4*)(Hh + (size_t)hc * Nn + w0 + hu * 8);
            pHl  = *(const uint4*)(Hl + (size_t)hc * Nn + w0 + hu * 8);
        }
        __syncthreads();
        #pragma unroll
        for (int ks = 0; ks < 4; ks++) {
            const uint32_t ko = ks * 32;
            uint32_t ah0, ah1, ah2, ah3, al0, al1, al2, al3;
            uint32_t bh00, bh01, bh10, bh11, bl00, bl01, bl10, bl11;
            ldm4(ah0, ah1, ah2, ah3, sAh_u + offA + ko);
            ldm4(al0, al1, al2, al3, sAl_u + offA + ko);
            ldm4(bh00, bh01, bh10, bh11, sHh_u + offB + ko);
            ldm4(bl00, bl01, bl10, bl11, sHl_u + offB + ko);
            hmma(acc[0], ah0, ah1, ah2, ah3, bh00, bh01);
            hmma(acc[0], ah0, ah1, ah2, ah3, bl00, bl01);
            hmma(acc[0], al0, al1, al2, al3, bh00, bh01);
            hmma(acc[1], ah0, ah1, ah2, ah3, bh10, bh11);
            hmma(acc[1], ah0, ah1, ah2, ah3, bl10, bl11);
            hmma(acc[1], al0, al1, al2, al3, bh10, bh11);
        }
    }

    const int vlo = v0 + warpV + g;
    const int vhi = vlo + 8;
    const float dn_lo = den[denB * b + vlo];
    const float dn_hi = den[denB * b + vhi];
    const float* xb = xin + (size_t)b * Ee * Nn;
    float* ob = hout + (size_t)b * Ee * Nn;
    bf16* oh = g_s1Hi + (size_t)b * Ee * Nn;
    bf16* ol = g_s1Lo + (size_t)b * Ee * Nn;
    #pragma unroll
    for (int nt = 0; nt < 2; nt++) {
        int c0 = c0w + nt * 8 + 2 * tg;
        float vals[4];
        size_t idxs[4];
        idxs[0] = (size_t)c0 * Nn + vlo;
        idxs[1] = (size_t)(c0 + 1) * Nn + vlo;
        idxs[2] = (size_t)c0 * Nn + vhi;
        idxs[3] = (size_t)(c0 + 1) * Nn + vhi;
        vals[0] = ALPHA * xb[idxs[0]] + (1.0f - ALPHA) * ((acc[nt].x + hb[idxs[0]]) / dn_lo);
        vals[1] = ALPHA * xb[idxs[1]] + (1.0f - ALPHA) * ((acc[nt].y + hb[idxs[1]]) / dn_lo);
        vals[2] = ALPHA * xb[idxs[2]] + (1.0f - ALPHA) * ((acc[nt].z + hb[idxs[2]]) / dn_hi);
        vals[3] = ALPHA * xb[idxs[3]] + (1.0f - ALPHA) * ((acc[nt].w + hb[idxs[3]]) / dn_hi);
        #pragma unroll
        for (int u = 0; u < 4; u++) {
            ob[idxs[u]] = vals[u];
            if (writeSplit) {
                bf16 h, l; bsplit(vals[u], h, l);
                oh[idxs[u]] = h;
                ol[idxs[u]] = l;
            }
        }
    }
}

// ---------------- HMMA gated conv ----------------
__global__ void __launch_bounds__(256) gated_mma(
        const bf16* __restrict__ inTh, const bf16* __restrict__ inTl,
        const bf16* __restrict__ Wfh, const bf16* __restrict__ Wfl,
        const bf16* __restrict__ Wgh, const bf16* __restrict__ Wgl,
        const float* __restrict__ bf_, const float* __restrict__ bg_,
        bf16* __restrict__ outTh, bf16* __restrict__ outTl) {
    __shared__ bf16 sWfh[Hc * CP], sWfl[Hc * CP], sWgh[Hc * CP], sWgl[Hc * CP];
    __shared__ bf16 sIh[64 * CP], sIl[64 * CP];

    const int tid = threadIdx.x, wid = tid >> 5, lane = tid & 31;
    const int g = lane >> 2, tg = lane & 3;
    const int col0 = blockIdx.x * 64;
    const int b = col0 / Nn, n0 = col0 % Nn;
    const int warpM = wid * 16;

    const uint32_t sWfh_u = smem_u32(sWfh), sWfl_u = smem_u32(sWfl);
    const uint32_t sWgh_u = smem_u32(sWgh), sWgl_u = smem_u32(sWgl);
    const uint32_t sIh_u = smem_u32(sIh), sIl_u = smem_u32(sIl);
    const uint32_t offA = (uint32_t)((warpM + (lane & 15)) * CP + (lane >> 4) * 8) * 2;
    const uint32_t offB = (uint32_t)(((lane & 7) + ((lane >> 4) & 1) * 8) * CP
                                     + ((lane >> 3) & 1) * 8) * 2;

    float4 aF[8] = {}, aG[8] = {};

    const int wrow = tid >> 1, whalf = tid & 1;
    const int it = tid & 127, iarr = tid >> 7;
    const int irow = it >> 1, ihalf = it & 1;
    const bf16* isrc = iarr ? inTl : inTh;
    bf16* idst = iarr ? sIl : sIh;

    for (int chunk = 0; chunk < 8; chunk++) {
        const int k0 = chunk * 16;
        __syncthreads();
        size_t wg = (size_t)wrow * Hc + k0 + whalf * 8;
        *(uint4*)&sWfh[wrow * CP + whalf * 8] = *(const uint4*)(Wfh + wg);
        *(uint4*)&sWfl[wrow * CP + whalf * 8] = *(const uint4*)(Wfl + wg);
        *(uint4*)&sWgh[wrow * CP + whalf * 8] = *(const uint4*)(Wgh + wg);
        *(uint4*)&sWgl[wrow * CP + whalf * 8] = *(const uint4*)(Wgl + wg);
        *(uint4*)&idst[irow * CP + ihalf * 8] =
            *(const uint4*)(isrc + ((size_t)b * Nn + n0 + irow) * Hc + k0 + ihalf * 8);
        __syncthreads();

        uint32_t fh0, fh1, fh2, fh3, fl0, fl1, fl2, fl3;
        uint32_t gh0, gh1, gh2, gh3, gl0, gl1, gl2, gl3;
        ldm4(fh0, fh1, fh2, fh3, sWfh_u + offA);
        ldm4(fl0, fl1, fl2, fl3, sWfl_u + offA);
        ldm4(gh0, gh1, gh2, gh3, sWgh_u + offA);
        ldm4(gl0, gl1, gl2, gl3, sWgl_u + offA);
        #pragma unroll
        for (int grp = 0; grp < 4; grp++) {
            const uint32_t go = (uint32_t)(grp * 16 * CP) * 2;
            uint32_t bh0, bh1, bh2, bh3, bl0, bl1, bl2, bl3;
            ldm4(bh0, bh1, bh2, bh3, sIh_u + go + offB);
            ldm4(bl0, bl1, bl2, bl3, sIl_u + go + offB);
            hmma(aF[2*grp], fh0, fh1, fh2, fh3, bh0, bh1);
            hmma(aF[2*grp], fh0, fh1, fh2, fh3, bl0, bl1);
            hmma(aF[2*grp], fl0, fl1, fl2, fl3, bh0, bh1);
            hmma(aF[2*grp+1], fh0, fh1, fh2, fh3, bh2, bh3);
            hmma(aF[2*grp+1], fh0, fh1, fh2, fh3, bl2, bl3);
            hmma(aF[2*grp+1], fl0, fl1, fl2, fl3, bh2, bh3);
            hmma(aG[2*grp], gh0, gh1, gh2, gh3, bh0, bh1);
            hmma(aG[2*grp], gh0, gh1, gh2, gh3, bl0, bl1);
            hmma(aG[2*grp], gl0, gl1, gl2, gl3, bh0, bh1);
            hmma(aG[2*grp+1], gh0, gh1, gh2, gh3, bh2, bh3);
            hmma(aG[2*grp+1], gh0, gh1, gh2, gh3, bl2, bl3);
            hmma(aG[2*grp+1], gl0, gl1, gl2, gl3, bh2, bh3);
        }
    }

    const int m_lo = warpM + g, m_hi = m_lo + 8;
    const float bflo = bf_[m_lo], bfhi = bf_[m_hi];
    const float bglo = bg_[m_lo], bghi = bg_[m_hi];
    #pragma unroll
    for (int nt = 0; nt < 8; nt++) {
        int n = n0 + nt * 8 + 2 * tg;
        size_t r0 = ((size_t)b * Nn + n) * Hc;
        size_t r1 = r0 + Hc;
        float v0 = tanhf(aF[nt].x + bflo) * (1.f / (1.f + expf(-(aG[nt].x + bglo))));
        float v1 = tanhf(aF[nt].y + bflo) * (1.f / (1.f + expf(-(aG[nt].y + bglo))));
        float v2 = tanhf(aF[nt].z + bfhi) * (1.f / (1.f + expf(-(aG[nt].z + bghi))));
        float v3 = tanhf(aF[nt].w + bfhi) * (1.f / (1.f + expf(-(aG[nt].w + bghi))));
        bf16 h, l;
        bsplit(v0, h, l); outTh[r0 + m_lo] = h; outTl[r0 + m_lo] = l;
        bsplit(v1, h, l); outTh[r1 + m_lo] = h; outTl[r1 + m_lo] = l;
        bsplit(v2, h, l); outTh[r0 + m_hi] = h; outTl[r0 + m_hi] = l;
        bsplit(v3, h, l); outTh[r1 + m_hi] = h; outTl[r1 + m_hi] = l;
    }
}

// ---------------- HMMA skip conv ----------------
__global__ void __launch_bounds__(256) skip_mma(
        const bf16* __restrict__ inTh, const bf16* __restrict__ inTl,
        const bf16* __restrict__ Wh, const bf16* __restrict__ Wl,
        const float* __restrict__ bias, float* __restrict__ out, int accFlag) {
    __shared__ bf16 sWh[Hc * CP], sWl[Hc * CP];
    __shared__ bf16 sIh[64 * CP], sIl[64 * CP];

    const int tid = threadIdx.x, wid = tid >> 5, lane = tid & 31;
    const int g = lane >> 2, tg = lane & 3;
    const int col0 = blockIdx.x * 64;
    const int b = col0 / Nn, n0 = col0 % Nn;
    const int mbase = blockIdx.y * 128;
    const int warpM = wid * 16;

    const uint32_t sWh_u = smem_u32(sWh), sWl_u = smem_u32(sWl);
    const uint32_t sIh_u = smem_u32(sIh), sIl_u = smem_u32(sIl);
    const uint32_t offA = (uint32_t)((warpM + (lane & 15)) * CP + (lane >> 4) * 8) * 2;
    const uint32_t offB = (uint32_t)(((lane & 7) + ((lane >> 4) & 1) * 8) * CP
                                     + ((lane >> 3) & 1) * 8) * 2;

    float4 acc[8] = {};

    const int wrow = tid >> 1, whalf = tid & 1;
    const int it = tid & 127, iarr = tid >> 7;
    const int irow = it >> 1, ihalf = it & 1;
    const bf16* isrc = iarr ? inTl : inTh;
    bf16* idst = iarr ? sIl : sIh;

    for (int chunk = 0; chunk < 8; chunk++) {
        const int k0 = chunk * 16;
        __syncthreads();
        size_t wg = (size_t)(mbase + wrow) * Hc + k0 + whalf * 8;
        *(uint4*)&sWh[wrow * CP + whalf * 8] = *(const uint4*)(Wh + wg);
        *(uint4*)&sWl[wrow * CP + whalf * 8] = *(const uint4*)(Wl + wg);
        *(uint4*)&idst[irow * CP + ihalf * 8] =
            *(const uint4*)(isrc + ((size_t)b * Nn + n0 + irow) * Hc + k0 + ihalf * 8);
        __syncthreads();

        uint32_t wh0, wh1, wh2, wh3, wl0, wl1, wl2, wl3;
        ldm4(wh0, wh1, wh2, wh3, sWh_u + offA);
        ldm4(wl0, wl1, wl2, wl3, sWl_u + offA);
        #pragma unroll
        for (int grp = 0; grp < 4; grp++) {
            const uint32_t go = (uint32_t)(grp * 16 * CP) * 2;
            uint32_t bh0, bh1, bh2, bh3, bl0, bl1, bl2, bl3;
            ldm4(bh0, bh1, bh2, bh3, sIh_u + go + offB);
            ldm4(bl0, bl1, bl2, bl3, sIl_u + go + offB);
            hmma(acc[2*grp], wh0, wh1, wh2, wh3, bh0, bh1);
            hmma(acc[2*grp], wh0, wh1, wh2, wh3, bl0, bl1);
            hmma(acc[2*grp], wl0, wl1, wl2, wl3, bh0, bh1);
            hmma(acc[2*grp+1], wh0, wh1, wh2, wh3, bh2, bh3);
            hmma(acc[2*grp+1], wh0, wh1, wh2, wh3, bl2, bl3);
            hmma(acc[2*grp+1], wl0, wl1, wl2, wl3, bh2, bh3);
        }
    }

    const int m_lo = mbase + warpM + g, m_hi = m_lo + 8;
    const float blo = bias[m_lo], bhi = bias[m_hi];
    #pragma unroll
    for (int nt = 0; nt < 8; nt++) {
        int n = n0 + nt * 8 + 2 * tg;
        float* d0 = &out[((size_t)b * Sc + m_lo) * Nn + n];
        float* d1 = &out[((size_t)b * Sc + m_hi) * Nn + n];
        float2 r0 = make_float2(acc[nt].x + blo, acc[nt].y + blo);
        float2 r1 = make_float2(acc[nt].z + bhi, acc[nt].w + bhi);
        if (accFlag) {
            float2 o0 = *(float2*)d0, o1 = *(float2*)d1;
            r0.x += o0.x; r0.y += o0.y; r1.x += o1.x; r1.y += o1.y;
        }
        *(float2*)d0 = r0;
        *(float2*)d1 = r1;
    }
}

// ---------------- generic 1x1 conv (f32x2 packed) with optional identity add --
__global__ void conv1x1_k(Srcs srcs, int inBStride,
                          const float* __restrict__ W, const float* __restrict__ bias,
                          int M, int K, float* __restrict__ out, int outBStride,
                          int accFlag, const float* __restrict__ iden) {
    __shared__ float Ws[16 * 68];
    __shared__ float Ins[16 * 68];
    const int tid = threadIdx.x;
    const int tx = tid & 15, ty = tid >> 4;
    const int col0 = blockIdx.x * 64;
    const int b = col0 / Nn, n0 = col0 % Nn;
    const int m0 = blockIdx.y * 64;

    u64 accP[4][2] = {};

    for (int k0 = 0; k0 < K; k0 += 16) {
        for (int t = tid; t < 1024; t += 256) {
            int m = t >> 4, kk = t & 15;
            Ws[kk * 68 + m] = (m0 + m < M) ? W[(size_t)(m0 + m) * K + k0 + kk] : 0.f;
        }
        for (int t = tid; t < 1024; t += 256) {
            int kk = t >> 6, n = t & 63;
            int c = k0 + kk;
            Ins[kk * 68 + n] = srcs.p[c >> 5][(size_t)b * inBStride + (size_t)(c & 31) * Nn + n0 + n];
        }
        __syncthreads();
        #pragma unroll
        for (int kk = 0; kk < 16; kk++) {
            float4 wv = *(const float4*)&Ws[kk * 68 + ty * 4];
            u64 ip0 = *(const u64*)&Ins[kk * 68 + tx * 4];
            u64 ip1 = *(const u64*)&Ins[kk * 68 + tx * 4 + 2];
            float wa[4] = {wv.x, wv.y, wv.z, wv.w};
            #pragma unroll
            for (int u = 0; u < 4; u++) {
                u64 wp = splat2(wa[u]);
                accP[u][0] = fma2(wp, ip0, accP[u][0]);
                accP[u][1] = fma2(wp, ip1, accP[u][1]);
            }
        }
        __syncthreads();
    }
    #pragma unroll
    for (int u = 0; u < 4; u++) {
        int m = m0 + ty * 4 + u;
        if (m >= M) break;
        float bm = bias[m];
        float4 r;
        upk2(accP[u][0], r.x, r.y);
        upk2(accP[u][1], r.z, r.w);
        r.x += bm; r.y += bm; r.z += bm; r.w += bm;
        float* dst = &out[(size_t)b * outBStride + (size_t)m * Nn + n0 + tx * 4];
        if (iden) {
            float4 o = *(const float4*)&iden[(size_t)b * outBStride + (size_t)m * Nn + n0 + tx * 4];
            r.x += o.x; r.y += o.y; r.z += o.z; r.w += o.w;
        }
        if (accFlag) {
            float4 o = *(float4*)dst;
            r.x += o.x; r.y += o.y; r.z += o.z; r.w += o.w;
        }
        *(float4*)dst = r;
    }
}

// ---------------- layernorm (two-stage) ----------------
__global__ void zero_red_k() {
    if (threadIdx.x < Bb * 2) g_red[threadIdx.x] = 0.f;
}
__global__ void ln_part_k() {
    int b = blockIdx.y, z = blockIdx.x;
    const float* xp = g_xacc + (size_t)b * Ee * Nn + (size_t)z * (Ee * Nn / 16);
    float s = 0.f, s2 = 0.f;
    for (int i = threadIdx.x; i < Ee * Nn / 16; i += 256) {
        float v = xp[i];
        s += v; s2 += v * v;
    }
    float ts = blockReduceSum(s);
    float ts2 = blockReduceSum(s2);
    if (threadIdx.x == 0) {
        atomicAdd(&g_red[b * 2], ts);
        atomicAdd(&g_red[b * 2 + 1], ts2);
    }
}

__global__ void ln_apply_k(const float* __restrict__ w, const float* __restrict__ bparm) {
    int i = blockIdx.x * 256 + threadIdx.x;
    if (i >= NEL) return;
    int b = i >> 16;
    int cn = i & (Ee * Nn - 1);
    float inv = 1.0f / (Ee * Nn);
    float mu = g_red[b * 2] * inv;
    float var = g_red[b * 2 + 1] * inv - mu * mu;
    float val = (g_xacc[i] - mu) * rsqrtf(var + EPSV) * w[cn] + bparm[cn];
    val = fmaxf(val, 0.f);
    g_x[i] = val;
    bf16 h, l; bsplit(val, h, l);
    g_sxHi[i] = h;
    g_sxLo[i] = l;
    int n = i & (Nn - 1);
    int c = (i >> 11) & 31;
    size_t o = ((size_t)b * Nn + n) * Hc + c;
    g_in1Th[o] = h;
    g_in1Tl[o] = l;
}

// ---------------- host orchestration ----------------
extern "C" void kernel_launch(void* const* d_in, const int* in_sizes, int n_in,
                              void* d_out, int out_size) {
    (void)in_sizes; (void)n_in; (void)out_size;
    const float* in_x  = (const float*)d_in[0];
    const float* dyG   = (const float*)d_in[1];
    const float* stG   = (const float*)d_in[2];
    const float* spE   = (const float*)d_in[3];
    const float* tdE   = (const float*)d_in[4];
    const float* twE   = (const float*)d_in[5];
    const float* encWf = (const float*)d_in[6];
    const float* encbf = (const float*)d_in[7];
    const float* encWg = (const float*)d_in[8];
    const float* encbg = (const float*)d_in[9];
    const float* skW   = (const float*)d_in[10];
    const float* skb   = (const float*)d_in[11];
    const float* nw    = (const float*)d_in[12];
    const float* nb    = (const float*)d_in[13];
    const float* gW[3] = {(const float*)d_in[14], (const float*)d_in[16], (const float*)d_in[18]};
    const float* gb[3] = {(const float*)d_in[15], (const float*)d_in[17], (const float*)d_in[19]};
    const float* seW   = (const float*)d_in[20];
    const float* seb   = (const float*)d_in[21];
    const float* eW    = (const float*)d_in[22];
    const float* eb    = (const float*)d_in[23];
    float* outp = (float*)d_out;

    float *px, *pxacc, *pskip, *prss, *prsd, *pcsd, *ph1g, *ph2g, *pgWc, *pgbc;
    cudaGetSymbolAddress((void**)&px,    g_x);
    cudaGetSymbolAddress((void**)&pxacc, g_xacc);
    cudaGetSymbolAddress((void**)&pskip, g_skip);
    cudaGetSymbolAddress((void**)&prss,  g_rs_s);
    cudaGetSymbolAddress((void**)&prsd,  g_rs_d);
    cudaGetSymbolAddress((void**)&pcsd,  g_cs_d);
    cudaGetSymbolAddress((void**)&ph1g,  g_h1g);
    cudaGetSymbolAddress((void**)&ph2g,  g_h2g);
    cudaGetSymbolAddress((void**)&pgWc,  g_gWc);
    cudaGetSymbolAddress((void**)&pgbc,  g_gbc);
    bf16 *pAhi, *pAlo, *pAThi, *pATlo, *pShi, *pSlo, *psxHi, *psxLo, *ps1Hi, *ps1Lo;
    cudaGetSymbolAddress((void**)&pAhi,  g_Ahi);
    cudaGetSymbolAddress((void**)&pAlo,  g_Alo);
    cudaGetSymbolAddress((void**)&pAThi, g_AThi);
    cudaGetSymbolAddress((void**)&pATlo, g_ATlo);
    cudaGetSymbolAddress((void**)&pShi,  g_Shi);
    cudaGetSymbolAddress((void**)&pSlo,  g_Slo);
    cudaGetSymbolAddress((void**)&psxHi, g_sxHi);
    cudaGetSymbolAddress((void**)&psxLo, g_sxLo);
    cudaGetSymbolAddress((void**)&ps1Hi, g_s1Hi);
    cudaGetSymbolAddress((void**)&ps1Lo, g_s1Lo);
    bf16 *pin1Th, *pin1Tl, *phidTh, *phidTl, *phid2Th, *phid2Tl;
    cudaGetSymbolAddress((void**)&pin1Th, g_in1Th);
    cudaGetSymbolAddress((void**)&pin1Tl, g_in1Tl);
    cudaGetSymbolAddress((void**)&phidTh, g_hidTh);
    cudaGetSymbolAddress((void**)&phidTl, g_hidTl);
    cudaGetSymbolAddress((void**)&phid2Th, g_hid2Th);
    cudaGetSymbolAddress((void**)&phid2Tl, g_hid2Tl);
    bf16 *peWfh, *peWfl, *peWgh, *peWgl, *pskWh, *pskWl;
    cudaGetSymbolAddress((void**)&peWfh, g_eWfh);
    cudaGetSymbolAddress((void**)&peWfl, g_eWfl);
    cudaGetSymbolAddress((void**)&peWgh, g_eWgh);
    cudaGetSymbolAddress((void**)&peWgl, g_eWgl);
    cudaGetSymbolAddress((void**)&pskWh, g_skWh);
    cudaGetSymbolAddress((void**)&pskWl, g_skWl);

    // ---- prep ----
    copy_split_k<<<(NEL / 4 + 255) / 256, 256>>>(px, in_x);
    init_den_k<<<(Bb * Nn + 255) / 256, 256>>>();
    prepA_k<<<dim3(Nn / 64, Nn / 64, Bb), 256>>>(dyG);
    prepS_k<<<dim3(Nn / 64, Nn / 64), 256>>>(stG);
    cvt_k<<<(6 * Hc * Hc / 4 + 255) / 256, 256>>>(encWf, peWfh, peWfl, 6 * Hc * Hc / 4);
    cvt_k<<<(6 * Hc * Hc / 4 + 255) / 256, 256>>>(encWg, peWgh, peWgl, 6 * Hc * Hc / 4);
    cvt_k<<<(3 * Sc * Hc / 4 + 255) / 256, 256>>>(skW, pskWh, pskWl, 3 * Sc * Hc / 4);
    embT_k<<<(Bb * 96 * (Nn / 4) + 255) / 256, 256>>>(spE, tdE, twE);
    combW_k<<<(3 * 32 * 224 + 255) / 256, 256>>>(gW[0], gW[1], gW[2]);
    combB_k<<<1, 96>>>(gb[0], gb[1], gb[2]);

    const dim3 convGrid(Bb * Nn / 64, 1);
    const dim3 spmmGrid(Nn / 64, Bb);
    for (int i = 0; i < 3; i++) {
        // ---- TCN chain (HMMA) ----
        gated_mma<<<Bb * Nn / 64, 256>>>(pin1Th, pin1Tl,
            peWfh + (size_t)(i * 2 + 0) * Hc * Hc, peWfl + (size_t)(i * 2 + 0) * Hc * Hc,
            peWgh + (size_t)(i * 2 + 0) * Hc * Hc, peWgl + (size_t)(i * 2 + 0) * Hc * Hc,
            encbf + (i * 2 + 0) * Hc, encbg + (i * 2 + 0) * Hc, phidTh, phidTl);
        gated_mma<<<Bb * Nn / 64, 256>>>(phidTh, phidTl,
            peWfh + (size_t)(i * 2 + 1) * Hc * Hc, peWfl + (size_t)(i * 2 + 1) * Hc * Hc,
            peWgh + (size_t)(i * 2 + 1) * Hc * Hc, peWgl + (size_t)(i * 2 + 1) * Hc * Hc,
            encbf + (i * 2 + 1) * Hc, encbg + (i * 2 + 1) * Hc, phid2Th, phid2Tl);
        // ---- skip += skip_W @ hidden (HMMA) ----
        skip_mma<<<dim3(Bb * Nn / 64, 2), 256>>>(phid2Th, phid2Tl,
            pskWh + (size_t)i * Sc * Hc, pskWl + (size_t)i * Sc * Hc,
            skb + i * Sc, pskip, i > 0);
        // ---- mixprop hops (HMMA), per-graph h1/h2 buffers ----
        for (int g = 0; g < 3; g++) {
            const bf16* Ah = (g == 0) ? pShi : (g == 1 ? pAhi : pAThi);
            const bf16* Al = (g == 0) ? pSlo : (g == 1 ? pAlo : pATlo);
            size_t abst = (g == 0) ? 0 : (size_t)Nn * Nn;
            const float* den = (g == 0) ? prss : (g == 1 ? prsd : pcsd);
            int denB = (g == 0) ? 0 : Nn;
            float* h1 = ph1g + (size_t)g * NEL;
            float* h2 = ph2g + (size_t)g * NEL;
            spmm_mma<<<spmmGrid, 256>>>(Ah, Al, abst, psxHi, psxLo, px, px, den, denB, h1, 1);
            spmm_mma<<<spmmGrid, 256>>>(Ah, Al, abst, ps1Hi, ps1Lo, h1, px, den, denB, h2, 0);
        }
        // ---- combined mixprop MLP: xacc = x + Wc @ [x,h1g0,h2g0,...] + bc ----
        Srcs sm;
        sm.p[0] = px;
        sm.p[1] = ph1g + 0 * NEL; sm.p[2] = ph2g + 0 * NEL;
        sm.p[3] = ph1g + 1 * NEL; sm.p[4] = ph2g + 1 * NEL;
        sm.p[5] = ph1g + 2 * NEL; sm.p[6] = ph2g + 2 * NEL;
        conv1x1_k<<<convGrid, 256>>>(sm, Ee * Nn,
            pgWc + (size_t)i * 32 * 224, pgbc + i * 32, Ee, 224, pxacc, Ee * Nn, 0, px);
        // ---- layernorm + relu (two-stage stats) ----
        zero_red_k<<<1, 32>>>();
        ln_part_k<<<dim3(16, Bb), 256>>>();
        ln_apply_k<<<NEL / 256, 256>>>(nw + (size_t)i * Ee * Nn, nb + (size_t)i * Ee * Nn);
    }
    // ---- skip end + output ----
    Srcs se; se.p[0] = px;
    conv1x1_k<<<dim3(Bb * Nn / 64, 4), 256>>>(se, Ee * Nn, seW, seb, Sc, Ee, pskip, Sc * Nn, 1, nullptr);
    Srcs send; for (int s = 0; s < 8; s++) send.p[s] = pskip + (size_t)s * 32 * Nn;
    conv1x1_k<<<convGrid, 256>>>(send, Sc * Nn, eW, eb, Tt, Sc, outp, Tt * Nn, 0, nullptr);
}

// round 12
// speedup vs baseline: 2.3294x; 1.2068x over previous
#include <cuda_runtime.h>
#include <cuda_bf16.h>
#include <math.h>
#include <stdint.h>

#define Bb 8
#define Nn 2048
#define Ee 32
#define Hc 128
#define Sc 256
#define Tt 12
#define NEL (Bb*Ee*Nn)
#define ALPHA 0.05f
#define EPSV 1e-5f
#define AP 72   // spmm smem pitch bf16 (144B)
#define CP 24   // conv smem pitch bf16 (48B)

typedef unsigned long long u64;
typedef __nv_bfloat16 bf16;

// ---------------- packed fp32x2 helpers (for SIMT convs) ----------------
__device__ __forceinline__ u64 splat2(float a) {
    u64 d; asm("mov.b64 %0, {%1, %1};" : "=l"(d) : "f"(a)); return d;
}
__device__ __forceinline__ void upk2(u64 v, float& lo, float& hi) {
    asm("mov.b64 {%0, %1}, %2;" : "=f"(lo), "=f"(hi) : "l"(v));
}
__device__ __forceinline__ u64 fma2(u64 a, u64 b, u64 c) {
    u64 d; asm("fma.rn.f32x2 %0, %1, %2, %3;" : "=l"(d) : "l"(a), "l"(b), "l"(c)); return d;
}

// ---------------- warp-level bf16 MMA + ldmatrix ----------------
__device__ __forceinline__ void hmma(float4& d, uint32_t a0, uint32_t a1, uint32_t a2,
                                     uint32_t a3, uint32_t b0, uint32_t b1) {
    asm volatile(
        "mma.sync.aligned.m16n8k16.row.col.f32.bf16.bf16.f32 "
        "{%0,%1,%2,%3}, {%4,%5,%6,%7}, {%8,%9}, {%0,%1,%2,%3};"
        : "+f"(d.x), "+f"(d.y), "+f"(d.z), "+f"(d.w)
        : "r"(a0), "r"(a1), "r"(a2), "r"(a3), "r"(b0), "r"(b1));
}
__device__ __forceinline__ void ldm4(uint32_t& r0, uint32_t& r1, uint32_t& r2, uint32_t& r3,
                                     uint32_t addr) {
    asm volatile("ldmatrix.sync.aligned.m8n8.x4.shared.b16 {%0,%1,%2,%3}, [%4];"
        : "=r"(r0), "=r"(r1), "=r"(r2), "=r"(r3) : "r"(addr));
}
__device__ __forceinline__ uint32_t smem_u32(const void* p) {
    uint32_t a;
    asm("{ .reg .u64 t; cvta.to.shared.u64 t, %1; cvt.u32.u64 %0, t; }" : "=r"(a) : "l"(p));
    return a;
}

// ---------------- device scratch ----------------
__device__ float g_x[NEL];
__device__ float g_xacc[NEL];
__device__ float g_h1g[3][NEL];
__device__ float g_h2g[3][NEL];
__device__ float g_skip[Bb*Sc*Nn];
__device__ float g_rs_s[Nn];
__device__ float g_rs_d[Bb*Nn];
__device__ float g_cs_d[Bb*Nn];
__device__ float g_red[Bb*2];
__device__ bf16 g_Ahi[Bb*Nn*Nn];
__device__ bf16 g_AThi[Bb*Nn*Nn];
__device__ bf16 g_Shi[Nn*Nn];
__device__ bf16 g_sxHi[NEL];
__device__ bf16 g_sxLo[NEL];
__device__ bf16 g_s1Hi[NEL];
__device__ bf16 g_s1Lo[NEL];
// transposed-split activations [b][n][128]
__device__ bf16 g_in1Th[Bb*Nn*Hc];
__device__ bf16 g_in1Tl[Bb*Nn*Hc];
__device__ bf16 g_hidTh[Bb*Nn*Hc];
__device__ bf16 g_hidTl[Bb*Nn*Hc];
__device__ bf16 g_hid2Th[Bb*Nn*Hc];
__device__ bf16 g_hid2Tl[Bb*Nn*Hc];
// split weights
__device__ bf16 g_eWfh[6*Hc*Hc];
__device__ bf16 g_eWfl[6*Hc*Hc];
__device__ bf16 g_eWgh[6*Hc*Hc];
__device__ bf16 g_eWgl[6*Hc*Hc];
__device__ bf16 g_skWh[3*Sc*Hc];
__device__ bf16 g_skWl[3*Sc*Hc];
// combined mixprop mlp weights: [3][32][224], bias [3][32]
__device__ float g_gWc[3*32*224];
__device__ float g_gbc[96];

struct Srcs { const float* p[8]; };

__device__ __forceinline__ void bsplit(float a, bf16& h, bf16& l) {
    h = __float2bfloat16(a);
    l = __float2bfloat16(a - __bfloat162float(h));
}
__device__ __forceinline__ uint32_t bpack(bf16 a, bf16 b) {
    __nv_bfloat162 t; t.x = a; t.y = b;
    return *reinterpret_cast<uint32_t*>(&t);
}

// ---------------- helpers ----------------
__device__ __forceinline__ float blockReduceSum(float v) {
    __shared__ float sh[32];
    int lane = threadIdx.x & 31, wid = threadIdx.x >> 5;
    #pragma unroll
    for (int o = 16; o; o >>= 1) v += __shfl_down_sync(0xffffffffu, v, o);
    __syncthreads();
    if (lane == 0) sh[wid] = v;
    __syncthreads();
    int nw = blockDim.x >> 5;
    v = (threadIdx.x < nw) ? sh[threadIdx.x] : 0.f;
    if (wid == 0) {
        #pragma unroll
        for (int o = 16; o; o >>= 1) v += __shfl_down_sync(0xffffffffu, v, o);
    }
    return v;
}

__global__ void copy_split_k(float* __restrict__ dst, const float* __restrict__ src) {
    int i = blockIdx.x * 256 + threadIdx.x;
    if (i >= NEL / 4) return;
    float4 a = ((const float4*)src)[i];
    ((float4*)dst)[i] = a;
    bf16 h[4], l[4];
    bsplit(a.x, h[0], l[0]); bsplit(a.y, h[1], l[1]);
    bsplit(a.z, h[2], l[2]); bsplit(a.w, h[3], l[3]);
    ((uint2*)g_sxHi)[i] = make_uint2(bpack(h[0], h[1]), bpack(h[2], h[3]));
    ((uint2*)g_sxLo)[i] = make_uint2(bpack(l[0], l[1]), bpack(l[2], l[3]));
    int n4 = i % (Nn / 4);
    int c  = (i / (Nn / 4)) % Ee;
    int b  = i / (Ee * Nn / 4);
    size_t base = ((size_t)b * Nn + n4 * 4) * Hc + c;
    #pragma unroll
    for (int u = 0; u < 4; u++) {
        g_in1Th[base + (size_t)u * Hc] = h[u];
        g_in1Tl[base + (size_t)u * Hc] = l[u];
    }
}

// ---------------- fused prep ----------------
__global__ void init_den_k() {
    int i = blockIdx.x * 256 + threadIdx.x;
    if (i < Nn) g_rs_s[i] = 1.0f;
    if (i < Bb * Nn) { g_rs_d[i] = 1.0f; g_cs_d[i] = 1.0f; }
}

__global__ void prepA_k(const float* __restrict__ A) {
    __shared__ float sh[64][68];
    const int b = blockIdx.z;
    const int r0 = blockIdx.x * 64, c0 = blockIdx.y * 64;
    const int tid = threadIdx.x;
    const int row = tid >> 2, q = tid & 3;

    const float* Ab = A + (size_t)b * Nn * Nn;
    float rsum = 0.f;
    #pragma unroll
    for (int j = 0; j < 4; j++) {
        int idx4 = q + j * 4;
        float4 v = *(const float4*)&Ab[(size_t)(r0 + row) * Nn + c0 + idx4 * 4];
        *(float4*)&sh[row][idx4 * 4] = v;
        rsum += v.x + v.y + v.z + v.w;
        bf16 h0 = __float2bfloat16(v.x), h1 = __float2bfloat16(v.y);
        bf16 h2 = __float2bfloat16(v.z), h3 = __float2bfloat16(v.w);
        size_t o = ((size_t)b * Nn + r0 + row) * Nn + c0 + idx4 * 4;
        *(uint2*)&g_Ahi[o] = make_uint2(bpack(h0, h1), bpack(h2, h3));
    }
    rsum += __shfl_down_sync(0xffffffffu, rsum, 1);
    rsum += __shfl_down_sync(0xffffffffu, rsum, 2);
    if (q == 0) atomicAdd(&g_rs_d[b * Nn + r0 + row], rsum);
    __syncthreads();
    float csum = 0.f;
    #pragma unroll
    for (int j = 0; j < 4; j++) {
        int idx4 = q + j * 4;
        float4 v;
        v.x = sh[idx4 * 4 + 0][row];
        v.y = sh[idx4 * 4 + 1][row];
        v.z = sh[idx4 * 4 + 2][row];
        v.w = sh[idx4 * 4 + 3][row];
        csum += v.x + v.y + v.z + v.w;
        bf16 h0 = __float2bfloat16(v.x), h1 = __float2bfloat16(v.y);
        bf16 h2 = __float2bfloat16(v.z), h3 = __float2bfloat16(v.w);
        size_t o = ((size_t)b * Nn + c0 + row) * Nn + r0 + idx4 * 4;
        *(uint2*)&g_AThi[o] = make_uint2(bpack(h0, h1), bpack(h2, h3));
    }
    csum += __shfl_down_sync(0xffffffffu, csum, 1);
    csum += __shfl_down_sync(0xffffffffu, csum, 2);
    if (q == 0) atomicAdd(&g_cs_d[b * Nn + c0 + row], csum);
}

__global__ void prepS_k(const float* __restrict__ S) {
    const int r0 = blockIdx.x * 64, c0 = blockIdx.y * 64;
    const int tid = threadIdx.x;
    const int row = tid >> 2, q = tid & 3;
    float rsum = 0.f;
    #pragma unroll
    for (int j = 0; j < 4; j++) {
        int idx4 = q + j * 4;
        float4 v = *(const float4*)&S[(size_t)(r0 + row) * Nn + c0 + idx4 * 4];
        rsum += v.x + v.y + v.z + v.w;
        bf16 h0 = __float2bfloat16(v.x), h1 = __float2bfloat16(v.y);
        bf16 h2 = __float2bfloat16(v.z), h3 = __float2bfloat16(v.w);
        size_t o = (size_t)(r0 + row) * Nn + c0 + idx4 * 4;
        *(uint2*)&g_Shi[o] = make_uint2(bpack(h0, h1), bpack(h2, h3));
    }
    rsum += __shfl_down_sync(0xffffffffu, rsum, 1);
    rsum += __shfl_down_sync(0xffffffffu, rsum, 2);
    if (q == 0) atomicAdd(&g_rs_s[r0 + row], rsum);
}

__global__ void cvt_k(const float* __restrict__ A, bf16* __restrict__ hi,
                      bf16* __restrict__ lo, int n4) {
    int i = blockIdx.x * 256 + threadIdx.x;
    if (i >= n4) return;
    float4 a = ((const float4*)A)[i];
    bf16 h0, h1, h2, h3, l0, l1, l2, l3;
    bsplit(a.x, h0, l0); bsplit(a.y, h1, l1); bsplit(a.z, h2, l2); bsplit(a.w, h3, l3);
    ((uint2*)hi)[i] = make_uint2(bpack(h0, h1), bpack(h2, h3));
    ((uint2*)lo)[i] = make_uint2(bpack(l0, l1), bpack(l2, l3));
}

__global__ void embT_k(const float* __restrict__ spE, const float* __restrict__ tdE,
                       const float* __restrict__ twE) {
    int idx = blockIdx.x * 256 + threadIdx.x;
    if (idx >= Bb * 96 * (Nn / 4)) return;
    int n4 = idx % (Nn / 4);
    int rest = idx / (Nn / 4);
    int ch = rest % 96, b = rest / 96;
    const float* src = (ch < 32) ? spE : (ch < 64 ? tdE : twE);
    int c = ch & 31;
    float4 v = *(const float4*)(src + ((size_t)b * 32 + c) * Nn + n4 * 4);
    int oc = 32 + ch;
    float vv[4] = {v.x, v.y, v.z, v.w};
    size_t base = ((size_t)b * Nn + n4 * 4) * Hc + oc;
    #pragma unroll
    for (int u = 0; u < 4; u++) {
        bf16 h, l; bsplit(vv[u], h, l);
        g_in1Th[base + (size_t)u * Hc] = h;
        g_in1Tl[base + (size_t)u * Hc] = l;
    }
}

__global__ void combW_k(const float* __restrict__ W0, const float* __restrict__ W1,
                        const float* __restrict__ W2) {
    int idx = blockIdx.x * 256 + threadIdx.x;
    if (idx >= 3 * 32 * 224) return;
    int c = idx % 224;
    int m = (idx / 224) % 32;
    int i = idx / (224 * 32);
    const float* W[3] = {W0 + (size_t)i * 32 * 96, W1 + (size_t)i * 32 * 96, W2 + (size_t)i * 32 * 96};
    float v;
    if (c < 32) v = W[0][m * 96 + c] + W[1][m * 96 + c] + W[2][m * 96 + c];
    else {
        int t = c - 32, g = t >> 6, j = t & 63;
        v = W[g][m * 96 + 32 + j];
    }
    g_gWc[idx] = v;
}
__global__ void combB_k(const float* __restrict__ b0, const float* __restrict__ b1,
                        const float* __restrict__ b2) {
    int idx = threadIdx.x;
    if (idx < 96) g_gbc[idx] = b0[idx] + b1[idx] + b2[idx];
}

// ---------------- HMMA SpMM (A single-bf16, h hi/lo) + fused hop epilogue ----
__global__ void __launch_bounds__(256) spmm_mma(
        const bf16* __restrict__ Ahi, size_t aBStride,
        const bf16* __restrict__ HhB, const bf16* __restrict__ HlB,
        const float* __restrict__ hin, const float* __restrict__ xin,
        const float* __restrict__ den, int denB, float* __restrict__ hout,
        int writeSplit) {
    __shared__ bf16 sAh[64 * AP];
    __shared__ bf16 sHh[32 * AP];
    __shared__ bf16 sHl[32 * AP];

    const int tid = threadIdx.x, wid = tid >> 5, lane = tid & 31;
    const int g = lane >> 2, tg = lane & 3;
    const int vt = blockIdx.x, b = blockIdx.y;
    const int v0 = vt * 64;
    const int warpV = (wid >> 1) * 16;
    const int c0w = (wid & 1) * 16;

    const bf16* Ah = Ahi + (size_t)b * aBStride;
    const bf16* Hh = HhB + (size_t)b * Ee * Nn;
    const bf16* Hl = HlB + (size_t)b * Ee * Nn;
    const float* hb = hin + (size_t)b * Ee * Nn;

    const uint32_t sAh_u = smem_u32(sAh);
    const uint32_t sHh_u = smem_u32(sHh), sHl_u = smem_u32(sHl);
    const int rowA = warpV + (lane & 15);
    const int khA  = (lane >> 4) * 8;
    const uint32_t offA = (uint32_t)(rowA * AP + khA) * 2;
    const int rowB = c0w + (lane & 7) + ((lane >> 4) & 1) * 8;
    const int khB  = ((lane >> 3) & 1) * 8;
    const uint32_t offB = (uint32_t)(rowB * AP + khB) * 2;

    float4 acc[2] = {};

    int ar0 = tid >> 3,           au0 = tid & 7;
    int ar1 = (tid + 256) >> 3,   au1 = tid & 7;
    int hc  = tid >> 3,           hu = tid & 7;

    uint4 pAh0, pAh1, pHh, pHl;
    {
        pAh0 = *(const uint4*)(Ah + (size_t)(v0 + ar0) * Nn + au0 * 8);
        pAh1 = *(const uint4*)(Ah + (size_t)(v0 + ar1) * Nn + au1 * 8);
        pHh  = *(const uint4*)(Hh + (size_t)hc * Nn + hu * 8);
        pHl  = *(const uint4*)(Hl + (size_t)hc * Nn + hu * 8);
    }

    for (int ch = 0; ch < 32; ch++) {
        __syncthreads();
        *(uint4*)&sAh[ar0 * AP + au0 * 8] = pAh0;
        *(uint4*)&sAh[ar1 * AP + au1 * 8] = pAh1;
        *(uint4*)&sHh[hc * AP + hu * 8] = pHh;
        *(uint4*)&sHl[hc * AP + hu * 8] = pHl;
        if (ch < 31) {
            const int w0 = (ch + 1) * 64;
            pAh0 = *(const uint4*)(Ah + (size_t)(v0 + ar0) * Nn + w0 + au0 * 8);
            pAh1 = *(const uint4*)(Ah + (size_t)(v0 + ar1) * Nn + w0 + au1 * 8);
            pHh  = *(const uint4*)(Hh + (size_t)hc * Nn + w0 + hu * 8);
            pHl  = *(const uint4*)(Hl + (size_t)hc * Nn + w0 + hu * 8);
        }
        __syncthreads();
        #pragma unroll
        for (int ks = 0; ks < 4; ks++) {
            const uint32_t ko = ks * 32;
            uint32_t ah0, ah1, ah2, ah3;
            uint32_t bh00, bh01, bh10, bh11, bl00, bl01, bl10, bl11;
            ldm4(ah0, ah1, ah2, ah3, sAh_u + offA + ko);
            ldm4(bh00, bh01, bh10, bh11, sHh_u + offB + ko);
            ldm4(bl00, bl01, bl10, bl11, sHl_u + offB + ko);
            hmma(acc[0], ah0, ah1, ah2, ah3, bh00, bh01);
            hmma(acc[0], ah0, ah1, ah2, ah3, bl00, bl01);
            hmma(acc[1], ah0, ah1, ah2, ah3, bh10, bh11);
            hmma(acc[1], ah0, ah1, ah2, ah3, bl10, bl11);
        }
    }

    const int vlo = v0 + warpV + g;
    const int vhi = vlo + 8;
    const float dn_lo = den[denB * b + vlo];
    const float dn_hi = den[denB * b + vhi];
    const float* xb = xin + (size_t)b * Ee * Nn;
    float* ob = hout + (size_t)b * Ee * Nn;
    bf16* oh = g_s1Hi + (size_t)b * Ee * Nn;
    bf16* ol = g_s1Lo + (size_t)b * Ee * Nn;
    #pragma unroll
    for (int nt = 0; nt < 2; nt++) {
        int c0 = c0w + nt * 8 + 2 * tg;
        float vals[4];
        size_t idxs[4];
        idxs[0] = (size_t)c0 * Nn + vlo;
        idxs[1] = (size_t)(c0 + 1) * Nn + vlo;
        idxs[2] = (size_t)c0 * Nn + vhi;
        idxs[3] = (size_t)(c0 + 1) * Nn + vhi;
        vals[0] = ALPHA * xb[idxs[0]] + (1.0f - ALPHA) * ((acc[nt].x + hb[idxs[0]]) / dn_lo);
        vals[1] = ALPHA * xb[idxs[1]] + (1.0f - ALPHA) * ((acc[nt].y + hb[idxs[1]]) / dn_lo);
        vals[2] = ALPHA * xb[idxs[2]] + (1.0f - ALPHA) * ((acc[nt].z + hb[idxs[2]]) / dn_hi);
        vals[3] = ALPHA * xb[idxs[3]] + (1.0f - ALPHA) * ((acc[nt].w + hb[idxs[3]]) / dn_hi);
        #pragma unroll
        for (int u = 0; u < 4; u++) {
            ob[idxs[u]] = vals[u];
            if (writeSplit) {
                bf16 h, l; bsplit(vals[u], h, l);
                oh[idxs[u]] = h;
                ol[idxs[u]] = l;
            }
        }
    }
}

// ---------------- HMMA gated conv ----------------
__global__ void __launch_bounds__(256) gated_mma(
        const bf16* __restrict__ inTh, const bf16* __restrict__ inTl,
        const bf16* __restrict__ Wfh, const bf16* __restrict__ Wfl,
        const bf16* __restrict__ Wgh, const bf16* __restrict__ Wgl,
        const float* __restrict__ bf_, const float* __restrict__ bg_,
        bf16* __restrict__ outTh, bf16* __restrict__ outTl) {
    __shared__ bf16 sWfh[Hc * CP], sWfl[Hc * CP], sWgh[Hc * CP], sWgl[Hc * CP];
    __shared__ bf16 sIh[64 * CP], sIl[64 * CP];

    const int tid = threadIdx.x, wid = tid >> 5, lane = tid & 31;
    const int g = lane >> 2, tg = lane & 3;
    const int col0 = blockIdx.x * 64;
    const int b = col0 / Nn, n0 = col0 % Nn;
    const int warpM = wid * 16;

    const uint32_t sWfh_u = smem_u32(sWfh), sWfl_u = smem_u32(sWfl);
    const uint32_t sWgh_u = smem_u32(sWgh), sWgl_u = smem_u32(sWgl);
    const uint32_t sIh_u = smem_u32(sIh), sIl_u = smem_u32(sIl);
    const uint32_t offA = (uint32_t)((warpM + (lane & 15)) * CP + (lane >> 4) * 8) * 2;
    const uint32_t offB = (uint32_t)(((lane & 7) + ((lane >> 4) & 1) * 8) * CP
                                     + ((lane >> 3) & 1) * 8) * 2;

    float4 aF[8] = {}, aG[8] = {};

    const int wrow = tid >> 1, whalf = tid & 1;
    const int it = tid & 127, iarr = tid >> 7;
    const int irow = it >> 1, ihalf = it & 1;
    const bf16* isrc = iarr ? inTl : inTh;
    bf16* idst = iarr ? sIl : sIh;

    for (int chunk = 0; chunk < 8; chunk++) {
        const int k0 = chunk * 16;
        __syncthreads();
        size_t wg = (size_t)wrow * Hc + k0 + whalf * 8;
        *(uint4*)&sWfh[wrow * CP + whalf * 8] = *(const uint4*)(Wfh + wg);
        *(uint4*)&sWfl[wrow * CP + whalf * 8] = *(const uint4*)(Wfl + wg);
        *(uint4*)&sWgh[wrow * CP + whalf * 8] = *(const uint4*)(Wgh + wg);
        *(uint4*)&sWgl[wrow * CP + whalf * 8] = *(const uint4*)(Wgl + wg);
        *(uint4*)&idst[irow * CP + ihalf * 8] =
            *(const uint4*)(isrc + ((size_t)b * Nn + n0 + irow) * Hc + k0 + ihalf * 8);
        __syncthreads();

        uint32_t fh0, fh1, fh2, fh3, fl0, fl1, fl2, fl3;
        uint32_t gh0, gh1, gh2, gh3, gl0, gl1, gl2, gl3;
        ldm4(fh0, fh1, fh2, fh3, sWfh_u + offA);
        ldm4(fl0, fl1, fl2, fl3, sWfl_u + offA);
        ldm4(gh0, gh1, gh2, gh3, sWgh_u + offA);
        ldm4(gl0, gl1, gl2, gl3, sWgl_u + offA);
        #pragma unroll
        for (int grp = 0; grp < 4; grp++) {
            const uint32_t go = (uint32_t)(grp * 16 * CP) * 2;
            uint32_t bh0, bh1, bh2, bh3, bl0, bl1, bl2, bl3;
            ldm4(bh0, bh1, bh2, bh3, sIh_u + go + offB);
            ldm4(bl0, bl1, bl2, bl3, sIl_u + go + offB);
            hmma(aF[2*grp], fh0, fh1, fh2, fh3, bh0, bh1);
            hmma(aF[2*grp], fh0, fh1, fh2, fh3, bl0, bl1);
            hmma(aF[2*grp], fl0, fl1, fl2, fl3, bh0, bh1);
            hmma(aF[2*grp+1], fh0, fh1, fh2, fh3, bh2, bh3);
            hmma(aF[2*grp+1], fh0, fh1, fh2, fh3, bl2, bl3);
            hmma(aF[2*grp+1], fl0, fl1, fl2, fl3, bh2, bh3);
            hmma(aG[2*grp], gh0, gh1, gh2, gh3, bh0, bh1);
            hmma(aG[2*grp], gh0, gh1, gh2, gh3, bl0, bl1);
            hmma(aG[2*grp], gl0, gl1, gl2, gl3, bh0, bh1);
            hmma(aG[2*grp+1], gh0, gh1, gh2, gh3, bh2, bh3);
            hmma(aG[2*grp+1], gh0, gh1, gh2, gh3, bl2, bl3);
            hmma(aG[2*grp+1], gl0, gl1, gl2, gl3, bh2, bh3);
        }
    }

    const int m_lo = warpM + g, m_hi = m_lo + 8;
    const float bflo = bf_[m_lo], bfhi = bf_[m_hi];
    const float bglo = bg_[m_lo], bghi = bg_[m_hi];
    #pragma unroll
    for (int nt = 0; nt < 8; nt++) {
        int n = n0 + nt * 8 + 2 * tg;
        size_t r0 = ((size_t)b * Nn + n) * Hc;
        size_t r1 = r0 + Hc;
        float v0 = tanhf(aF[nt].x + bflo) * (1.f / (1.f + expf(-(aG[nt].x + bglo))));
        float v1 = tanhf(aF[nt].y + bflo) * (1.f / (1.f + expf(-(aG[nt].y + bglo))));
        float v2 = tanhf(aF[nt].z + bfhi) * (1.f / (1.f + expf(-(aG[nt].z + bghi))));
        float v3 = tanhf(aF[nt].w + bfhi) * (1.f / (1.f + expf(-(aG[nt].w + bghi))));
        bf16 h, l;
        bsplit(v0, h, l); outTh[r0 + m_lo] = h; outTl[r0 + m_lo] = l;
        bsplit(v1, h, l); outTh[r1 + m_lo] = h; outTl[r1 + m_lo] = l;
        bsplit(v2, h, l); outTh[r0 + m_hi] = h; outTl[r0 + m_hi] = l;
        bsplit(v3, h, l); outTh[r1 + m_hi] = h; outTl[r1 + m_hi] = l;
    }
}

// ---------------- HMMA skip conv ----------------
__global__ void __launch_bounds__(256) skip_mma(
        const bf16* __restrict__ inTh, const bf16* __restrict__ inTl,
        const bf16* __restrict__ Wh, const bf16* __restrict__ Wl,
        const float* __restrict__ bias, float* __restrict__ out, int accFlag) {
    __shared__ bf16 sWh[Hc * CP], sWl[Hc * CP];
    __shared__ bf16 sIh[64 * CP], sIl[64 * CP];

    const int tid = threadIdx.x, wid = tid >> 5, lane = tid & 31;
    const int g = lane >> 2, tg = lane & 3;
    const int col0 = blockIdx.x * 64;
    const int b = col0 / Nn, n0 = col0 % Nn;
    const int mbase = blockIdx.y * 128;
    const int warpM = wid * 16;

    const uint32_t sWh_u = smem_u32(sWh), sWl_u = smem_u32(sWl);
    const uint32_t sIh_u = smem_u32(sIh), sIl_u = smem_u32(sIl);
    const uint32_t offA = (uint32_t)((warpM + (lane & 15)) * CP + (lane >> 4) * 8) * 2;
    const uint32_t offB = (uint32_t)(((lane & 7) + ((lane >> 4) & 1) * 8) * CP
                                     + ((lane >> 3) & 1) * 8) * 2;

    float4 acc[8] = {};

    const int wrow = tid >> 1, whalf = tid & 1;
    const int it = tid & 127, iarr = tid >> 7;
    const int irow = it >> 1, ihalf = it & 1;
    const bf16* isrc = iarr ? inTl : inTh;
    bf16* idst = iarr ? sIl : sIh;

    for (int chunk = 0; chunk < 8; chunk++) {
        const int k0 = chunk * 16;
        __syncthreads();
        size_t wg = (size_t)(mbase + wrow) * Hc + k0 + whalf * 8;
        *(uint4*)&sWh[wrow * CP + whalf * 8] = *(const uint4*)(Wh + wg);
        *(uint4*)&sWl[wrow * CP + whalf * 8] = *(const uint4*)(Wl + wg);
        *(uint4*)&idst[irow * CP + ihalf * 8] =
            *(const uint4*)(isrc + ((size_t)b * Nn + n0 + irow) * Hc + k0 + ihalf * 8);
        __syncthreads();

        uint32_t wh0, wh1, wh2, wh3, wl0, wl1, wl2, wl3;
        ldm4(wh0, wh1, wh2, wh3, sWh_u + offA);
        ldm4(wl0, wl1, wl2, wl3, sWl_u + offA);
        #pragma unroll
        for (int grp = 0; grp < 4; grp++) {
            const uint32_t go = (uint32_t)(grp * 16 * CP) * 2;
            uint32_t bh0, bh1, bh2, bh3, bl0, bl1, bl2, bl3;
            ldm4(bh0, bh1, bh2, bh3, sIh_u + go + offB);
            ldm4(bl0, bl1, bl2, bl3, sIl_u + go + offB);
            hmma(acc[2*grp], wh0, wh1, wh2, wh3, bh0, bh1);
            hmma(acc[2*grp], wh0, wh1, wh2, wh3, bl0, bl1);
            hmma(acc[2*grp], wl0, wl1, wl2, wl3, bh0, bh1);
            hmma(acc[2*grp+1], wh0, wh1, wh2, wh3, bh2, bh3);
            hmma(acc[2*grp+1], wh0, wh1, wh2, wh3, bl2, bl3);
            hmma(acc[2*grp+1], wl0, wl1, wl2, wl3, bh2, bh3);
        }
    }

    const int m_lo = mbase + warpM + g, m_hi = m_lo + 8;
    const float blo = bias[m_lo], bhi = bias[m_hi];
    #pragma unroll
    for (int nt = 0; nt < 8; nt++) {
        int n = n0 + nt * 8 + 2 * tg;
        float* d0 = &out[((size_t)b * Sc + m_lo) * Nn + n];
        float* d1 = &out[((size_t)b * Sc + m_hi) * Nn + n];
        float2 r0 = make_float2(acc[nt].x + blo, acc[nt].y + blo);
        float2 r1 = make_float2(acc[nt].z + bhi, acc[nt].w + bhi);
        if (accFlag) {
            float2 o0 = *(float2*)d0, o1 = *(float2*)d1;
            r0.x += o0.x; r0.y += o0.y; r1.x += o1.x; r1.y += o1.y;
        }
        *(float2*)d0 = r0;
        *(float2*)d1 = r1;
    }
}

// ---------------- generic 1x1 conv (f32x2 packed) with optional identity add --
__global__ void conv1x1_k(Srcs srcs, int inBStride,
                          const float* __restrict__ W, const float* __restrict__ bias,
                          int M, int K, float* __restrict__ out, int outBStride,
                          int accFlag, const float* __restrict__ iden) {
    __shared__ float Ws[16 * 68];
    __shared__ float Ins[16 * 68];
    const int tid = threadIdx.x;
    const int tx = tid & 15, ty = tid >> 4;
    const int col0 = blockIdx.x * 64;
    const int b = col0 / Nn, n0 = col0 % Nn;
    const int m0 = blockIdx.y * 64;

    u64 accP[4][2] = {};

    for (int k0 = 0; k0 < K; k0 += 16) {
        for (int t = tid; t < 1024; t += 256) {
            int m = t >> 4, kk = t & 15;
            Ws[kk * 68 + m] = (m0 + m < M) ? W[(size_t)(m0 + m) * K + k0 + kk] : 0.f;
        }
        for (int t = tid; t < 1024; t += 256) {
            int kk = t >> 6, n = t & 63;
            int c = k0 + kk;
            Ins[kk * 68 + n] = srcs.p[c >> 5][(size_t)b * inBStride + (size_t)(c & 31) * Nn + n0 + n];
        }
        __syncthreads();
        #pragma unroll
        for (int kk = 0; kk < 16; kk++) {
            float4 wv = *(const float4*)&Ws[kk * 68 + ty * 4];
            u64 ip0 = *(const u64*)&Ins[kk * 68 + tx * 4];
            u64 ip1 = *(const u64*)&Ins[kk * 68 + tx * 4 + 2];
            float wa[4] = {wv.x, wv.y, wv.z, wv.w};
            #pragma unroll
            for (int u = 0; u < 4; u++) {
                u64 wp = splat2(wa[u]);
                accP[u][0] = fma2(wp, ip0, accP[u][0]);
                accP[u][1] = fma2(wp, ip1, accP[u][1]);
            }
        }
        __syncthreads();
    }
    #pragma unroll
    for (int u = 0; u < 4; u++) {
        int m = m0 + ty * 4 + u;
        if (m >= M) break;
        float bm = bias[m];
        float4 r;
        upk2(accP[u][0], r.x, r.y);
        upk2(accP[u][1], r.z, r.w);
        r.x += bm; r.y += bm; r.z += bm; r.w += bm;
        float* dst = &out[(size_t)b * outBStride + (size_t)m * Nn + n0 + tx * 4];
        if (iden) {
            float4 o = *(const float4*)&iden[(size_t)b * outBStride + (size_t)m * Nn + n0 + tx * 4];
            r.x += o.x; r.y += o.y; r.z += o.z; r.w += o.w;
        }
        if (accFlag) {
            float4 o = *(float4*)dst;
            r.x += o.x; r.y += o.y; r.z += o.z; r.w += o.w;
        }
        *(float4*)dst = r;
    }
}

// ---------------- layernorm (two-stage) ----------------
__global__ void zero_red_k() {
    if (threadIdx.x < Bb * 2) g_red[threadIdx.x] = 0.f;
}
__global__ void ln_part_k() {
    int b = blockIdx.y, z = blockIdx.x;
    const float* xp = g_xacc + (size_t)b * Ee * Nn + (size_t)z * (Ee * Nn / 16);
    float s = 0.f, s2 = 0.f;
    for (int i = threadIdx.x; i < Ee * Nn / 16; i += 256) {
        float v = xp[i];
        s += v; s2 += v * v;
    }
    float ts = blockReduceSum(s);
    float ts2 = blockReduceSum(s2);
    if (threadIdx.x == 0) {
        atomicAdd(&g_red[b * 2], ts);
        atomicAdd(&g_red[b * 2 + 1], ts2);
    }
}

__global__ void ln_apply_k(const float* __restrict__ w, const float* __restrict__ bparm) {
    int i = blockIdx.x * 256 + threadIdx.x;
    if (i >= NEL) return;
    int b = i >> 16;
    int cn = i & (Ee * Nn - 1);
    float inv = 1.0f / (Ee * Nn);
    float mu = g_red[b * 2] * inv;
    float var = g_red[b * 2 + 1] * inv - mu * mu;
    float val = (g_xacc[i] - mu) * rsqrtf(var + EPSV) * w[cn] + bparm[cn];
    val = fmaxf(val, 0.f);
    g_x[i] = val;
    bf16 h, l; bsplit(val, h, l);
    g_sxHi[i] = h;
    g_sxLo[i] = l;
    int n = i & (Nn - 1);
    int c = (i >> 11) & 31;
    size_t o = ((size_t)b * Nn + n) * Hc + c;
    g_in1Th[o] = h;
    g_in1Tl[o] = l;
}

// ---------------- host orchestration ----------------
extern "C" void kernel_launch(void* const* d_in, const int* in_sizes, int n_in,
                              void* d_out, int out_size) {
    (void)in_sizes; (void)n_in; (void)out_size;
    const float* in_x  = (const float*)d_in[0];
    const float* dyG   = (const float*)d_in[1];
    const float* stG   = (const float*)d_in[2];
    const float* spE   = (const float*)d_in[3];
    const float* tdE   = (const float*)d_in[4];
    const float* twE   = (const float*)d_in[5];
    const float* encWf = (const float*)d_in[6];
    const float* encbf = (const float*)d_in[7];
    const float* encWg = (const float*)d_in[8];
    const float* encbg = (const float*)d_in[9];
    const float* skW   = (const float*)d_in[10];
    const float* skb   = (const float*)d_in[11];
    const float* nw    = (const float*)d_in[12];
    const float* nb    = (const float*)d_in[13];
    const float* gW[3] = {(const float*)d_in[14], (const float*)d_in[16], (const float*)d_in[18]};
    const float* gb[3] = {(const float*)d_in[15], (const float*)d_in[17], (const float*)d_in[19]};
    const float* seW   = (const float*)d_in[20];
    const float* seb   = (const float*)d_in[21];
    const float* eW    = (const float*)d_in[22];
    const float* eb    = (const float*)d_in[23];
    float* outp = (float*)d_out;

    float *px, *pxacc, *pskip, *prss, *prsd, *pcsd, *ph1g, *ph2g, *pgWc, *pgbc;
    cudaGetSymbolAddress((void**)&px,    g_x);
    cudaGetSymbolAddress((void**)&pxacc, g_xacc);
    cudaGetSymbolAddress((void**)&pskip, g_skip);
    cudaGetSymbolAddress((void**)&prss,  g_rs_s);
    cudaGetSymbolAddress((void**)&prsd,  g_rs_d);
    cudaGetSymbolAddress((void**)&pcsd,  g_cs_d);
    cudaGetSymbolAddress((void**)&ph1g,  g_h1g);
    cudaGetSymbolAddress((void**)&ph2g,  g_h2g);
    cudaGetSymbolAddress((void**)&pgWc,  g_gWc);
    cudaGetSymbolAddress((void**)&pgbc,  g_gbc);
    bf16 *pAhi, *pAThi, *pShi, *psxHi, *psxLo, *ps1Hi, *ps1Lo;
    cudaGetSymbolAddress((void**)&pAhi,  g_Ahi);
    cudaGetSymbolAddress((void**)&pAThi, g_AThi);
    cudaGetSymbolAddress((void**)&pShi,  g_Shi);
    cudaGetSymbolAddress((void**)&psxHi, g_sxHi);
    cudaGetSymbolAddress((void**)&psxLo, g_sxLo);
    cudaGetSymbolAddress((void**)&ps1Hi, g_s1Hi);
    cudaGetSymbolAddress((void**)&ps1Lo, g_s1Lo);
    bf16 *pin1Th, *pin1Tl, *phidTh, *phidTl, *phid2Th, *phid2Tl;
    cudaGetSymbolAddress((void**)&pin1Th, g_in1Th);
    cudaGetSymbolAddress((void**)&pin1Tl, g_in1Tl);
    cudaGetSymbolAddress((void**)&phidTh, g_hidTh);
    cudaGetSymbolAddress((void**)&phidTl, g_hidTl);
    cudaGetSymbolAddress((void**)&phid2Th, g_hid2Th);
    cudaGetSymbolAddress((void**)&phid2Tl, g_hid2Tl);
    bf16 *peWfh, *peWfl, *peWgh, *peWgl, *pskWh, *pskWl;
    cudaGetSymbolAddress((void**)&peWfh, g_eWfh);
    cudaGetSymbolAddress((void**)&peWfl, g_eWfl);
    cudaGetSymbolAddress((void**)&peWgh, g_eWgh);
    cudaGetSymbolAddress((void**)&peWgl, g_eWgl);
    cudaGetSymbolAddress((void**)&pskWh, g_skWh);
    cudaGetSymbolAddress((void**)&pskWl, g_skWl);

    // ---- prep ----
    copy_split_k<<<(NEL / 4 + 255) / 256, 256>>>(px, in_x);
    init_den_k<<<(Bb * Nn + 255) / 256, 256>>>();
    prepA_k<<<dim3(Nn / 64, Nn / 64, Bb), 256>>>(dyG);
    prepS_k<<<dim3(Nn / 64, Nn / 64), 256>>>(stG);
    cvt_k<<<(6 * Hc * Hc / 4 + 255) / 256, 256>>>(encWf, peWfh, peWfl, 6 * Hc * Hc / 4);
    cvt_k<<<(6 * Hc * Hc / 4 + 255) / 256, 256>>>(encWg, peWgh, peWgl, 6 * Hc * Hc / 4);
    cvt_k<<<(3 * Sc * Hc / 4 + 255) / 256, 256>>>(skW, pskWh, pskWl, 3 * Sc * Hc / 4);
    embT_k<<<(Bb * 96 * (Nn / 4) + 255) / 256, 256>>>(spE, tdE, twE);
    combW_k<<<(3 * 32 * 224 + 255) / 256, 256>>>(gW[0], gW[1], gW[2]);
    combB_k<<<1, 96>>>(gb[0], gb[1], gb[2]);

    const dim3 convGrid(Bb * Nn / 64, 1);
    const dim3 spmmGrid(Nn / 64, Bb);
    for (int i = 0; i < 3; i++) {
        // ---- TCN chain (HMMA) ----
        gated_mma<<<Bb * Nn / 64, 256>>>(pin1Th, pin1Tl,
            peWfh + (size_t)(i * 2 + 0) * Hc * Hc, peWfl + (size_t)(i * 2 + 0) * Hc * Hc,
            peWgh + (size_t)(i * 2 + 0) * Hc * Hc, peWgl + (size_t)(i * 2 + 0) * Hc * Hc,
            encbf + (i * 2 + 0) * Hc, encbg + (i * 2 + 0) * Hc, phidTh, phidTl);
        gated_mma<<<Bb * Nn / 64, 256>>>(phidTh, phidTl,
            peWfh + (size_t)(i * 2 + 1) * Hc * Hc, peWfl + (size_t)(i * 2 + 1) * Hc * Hc,
            peWgh + (size_t)(i * 2 + 1) * Hc * Hc, peWgl + (size_t)(i * 2 + 1) * Hc * Hc,
            encbf + (i * 2 + 1) * Hc, encbg + (i * 2 + 1) * Hc, phid2Th, phid2Tl);
        // ---- skip += skip_W @ hidden (HMMA) ----
        skip_mma<<<dim3(Bb * Nn / 64, 2), 256>>>(phid2Th, phid2Tl,
            pskWh + (size_t)i * Sc * Hc, pskWl + (size_t)i * Sc * Hc,
            skb + i * Sc, pskip, i > 0);
        // ---- mixprop hops (HMMA) ----
        for (int g = 0; g < 3; g++) {
            const bf16* Ah = (g == 0) ? pShi : (g == 1 ? pAhi : pAThi);
            size_t abst = (g == 0) ? 0 : (size_t)Nn * Nn;
            const float* den = (g == 0) ? prss : (g == 1 ? prsd : pcsd);
            int denB = (g == 0) ? 0 : Nn;
            float* h1 = ph1g + (size_t)g * NEL;
            float* h2 = ph2g + (size_t)g * NEL;
            spmm_mma<<<spmmGrid, 256>>>(Ah, abst, psxHi, psxLo, px, px, den, denB, h1, 1);
            spmm_mma<<<spmmGrid, 256>>>(Ah, abst, ps1Hi, ps1Lo, h1, px, den, denB, h2, 0);
        }
        // ---- combined mixprop MLP: xacc = x + Wc @ [x,h1g0,h2g0,...] + bc ----
        Srcs sm;
        sm.p[0] = px;
        sm.p[1] = ph1g + 0 * NEL; sm.p[2] = ph2g + 0 * NEL;
        sm.p[3] = ph1g + 1 * NEL; sm.p[4] = ph2g + 1 * NEL;
        sm.p[5] = ph1g + 2 * NEL; sm.p[6] = ph2g + 2 * NEL;
        conv1x1_k<<<convGrid, 256>>>(sm, Ee * Nn,
            pgWc + (size_t)i * 32 * 224, pgbc + i * 32, Ee, 224, pxacc, Ee * Nn, 0, px);
        // ---- layernorm + relu (two-stage stats) ----
        zero_red_k<<<1, 32>>>();
        ln_part_k<<<dim3(16, Bb), 256>>>();
        ln_apply_k<<<NEL / 256, 256>>>(nw + (size_t)i * Ee * Nn, nb + (size_t)i * Ee * Nn);
    }
    // ---- skip end + output ----
    Srcs se; se.p[0] = px;
    conv1x1_k<<<dim3(Bb * Nn / 64, 4), 256>>>(se, Ee * Nn, seW, seb, Sc, Ee, pskip, Sc * Nn, 1, nullptr);
    Srcs send; for (int s = 0; s < 8; s++) send.p[s] = pskip + (size_t)s * 32 * Nn;
    conv1x1_k<<<convGrid, 256>>>(send, Sc * Nn, eW, eb, Tt, Sc, outp, Tt * Nn, 0, nullptr);
}

// round 13
// speedup vs baseline: 2.9392x; 1.2618x over previous
#include <cuda_runtime.h>
#include <cuda_bf16.h>
#include <math.h>
#include <stdint.h>

#define Bb 8
#define Nn 2048
#define Ee 32
#define Hc 128
#define Sc 256
#define Tt 12
#define NEL (Bb*Ee*Nn)
#define ALPHA 0.05f
#define EPSV 1e-5f
#define AP 72   // spmm smem pitch bf16 (144B)
#define CP 24   // conv smem pitch bf16 (48B)

typedef unsigned long long u64;
typedef __nv_bfloat16 bf16;

// ---------------- packed fp32x2 helpers (for SIMT convs) ----------------
__device__ __forceinline__ u64 splat2(float a) {
    u64 d; asm("mov.b64 %0, {%1, %1};" : "=l"(d) : "f"(a)); return d;
}
__device__ __forceinline__ void upk2(u64 v, float& lo, float& hi) {
    asm("mov.b64 {%0, %1}, %2;" : "=f"(lo), "=f"(hi) : "l"(v));
}
__device__ __forceinline__ u64 fma2(u64 a, u64 b, u64 c) {
    u64 d; asm("fma.rn.f32x2 %0, %1, %2, %3;" : "=l"(d) : "l"(a), "l"(b), "l"(c)); return d;
}

// ---------------- warp-level bf16 MMA + ldmatrix ----------------
__device__ __forceinline__ void hmma(float4& d, uint32_t a0, uint32_t a1, uint32_t a2,
                                     uint32_t a3, uint32_t b0, uint32_t b1) {
    asm volatile(
        "mma.sync.aligned.m16n8k16.row.col.f32.bf16.bf16.f32 "
        "{%0,%1,%2,%3}, {%4,%5,%6,%7}, {%8,%9}, {%0,%1,%2,%3};"
        : "+f"(d.x), "+f"(d.y), "+f"(d.z), "+f"(d.w)
        : "r"(a0), "r"(a1), "r"(a2), "r"(a3), "r"(b0), "r"(b1));
}
__device__ __forceinline__ void ldm4(uint32_t& r0, uint32_t& r1, uint32_t& r2, uint32_t& r3,
                                     uint32_t addr) {
    asm volatile("ldmatrix.sync.aligned.m8n8.x4.shared.b16 {%0,%1,%2,%3}, [%4];"
        : "=r"(r0), "=r"(r1), "=r"(r2), "=r"(r3) : "r"(addr));
}
__device__ __forceinline__ uint32_t smem_u32(const void* p) {
    uint32_t a;
    asm("{ .reg .u64 t; cvta.to.shared.u64 t, %1; cvt.u32.u64 %0, t; }" : "=r"(a) : "l"(p));
    return a;
}

// ---------------- device scratch ----------------
__device__ float g_x[NEL];
__device__ float g_xacc[NEL];
__device__ float g_h1g[3][NEL];
__device__ float g_h2g[3][NEL];
__device__ float g_skip[Bb*Sc*Nn];
__device__ float g_rs_s[Nn];
__device__ float g_rs_d[Bb*Nn];
__device__ float g_cs_d[Bb*Nn];
__device__ float g_red[Bb*2];
__device__ bf16 g_Ahi[Bb*Nn*Nn];
__device__ bf16 g_AThi[Bb*Nn*Nn];
__device__ bf16 g_Shi[Nn*Nn];
__device__ bf16 g_sxHi[NEL];
__device__ bf16 g_s1Hi[3][NEL];
// transposed-split activations [b][n][128]
__device__ bf16 g_in1Th[Bb*Nn*Hc];
__device__ bf16 g_in1Tl[Bb*Nn*Hc];
__device__ bf16 g_hidTh[Bb*Nn*Hc];
__device__ bf16 g_hidTl[Bb*Nn*Hc];
__device__ bf16 g_hid2Th[Bb*Nn*Hc];
__device__ bf16 g_hid2Tl[Bb*Nn*Hc];
// split weights
__device__ bf16 g_eWfh[6*Hc*Hc];
__device__ bf16 g_eWfl[6*Hc*Hc];
__device__ bf16 g_eWgh[6*Hc*Hc];
__device__ bf16 g_eWgl[6*Hc*Hc];
__device__ bf16 g_skWh[3*Sc*Hc];
__device__ bf16 g_skWl[3*Sc*Hc];
// combined mixprop mlp weights
__device__ float g_gWc[3*32*224];
__device__ float g_gbc[96];

struct Srcs { const float* p[8]; };
struct SpmmB {
    const bf16* A[3];
    u64 abst[3];
    const float* den[3];
    int denB[3];
    const bf16* H[3];
    const float* hin[3];
    float* hout[3];
    bf16* sOut[3];
    int writeSplit;
};

__device__ __forceinline__ void bsplit(float a, bf16& h, bf16& l) {
    h = __float2bfloat16(a);
    l = __float2bfloat16(a - __bfloat162float(h));
}
__device__ __forceinline__ uint32_t bpack(bf16 a, bf16 b) {
    __nv_bfloat162 t; t.x = a; t.y = b;
    return *reinterpret_cast<uint32_t*>(&t);
}

// ---------------- helpers ----------------
__device__ __forceinline__ float blockReduceSum(float v) {
    __shared__ float sh[32];
    int lane = threadIdx.x & 31, wid = threadIdx.x >> 5;
    #pragma unroll
    for (int o = 16; o; o >>= 1) v += __shfl_down_sync(0xffffffffu, v, o);
    __syncthreads();
    if (lane == 0) sh[wid] = v;
    __syncthreads();
    int nw = blockDim.x >> 5;
    v = (threadIdx.x < nw) ? sh[threadIdx.x] : 0.f;
    if (wid == 0) {
        #pragma unroll
        for (int o = 16; o; o >>= 1) v += __shfl_down_sync(0xffffffffu, v, o);
    }
    return v;
}

__global__ void copy_split_k(float* __restrict__ dst, const float* __restrict__ src) {
    int i = blockIdx.x * 256 + threadIdx.x;
    if (i >= NEL / 4) return;
    float4 a = ((const float4*)src)[i];
    ((float4*)dst)[i] = a;
    bf16 h[4], l[4];
    bsplit(a.x, h[0], l[0]); bsplit(a.y, h[1], l[1]);
    bsplit(a.z, h[2], l[2]); bsplit(a.w, h[3], l[3]);
    ((uint2*)g_sxHi)[i] = make_uint2(bpack(h[0], h[1]), bpack(h[2], h[3]));
    int n4 = i % (Nn / 4);
    int c  = (i / (Nn / 4)) % Ee;
    int b  = i / (Ee * Nn / 4);
    size_t base = ((size_t)b * Nn + n4 * 4) * Hc + c;
    #pragma unroll
    for (int u = 0; u < 4; u++) {
        g_in1Th[base + (size_t)u * Hc] = h[u];
        g_in1Tl[base + (size_t)u * Hc] = l[u];
    }
}

// ---------------- fused prep ----------------
__global__ void init_den_k() {
    int i = blockIdx.x * 256 + threadIdx.x;
    if (i < Nn) g_rs_s[i] = 1.0f;
    if (i < Bb * Nn) { g_rs_d[i] = 1.0f; g_cs_d[i] = 1.0f; }
}

__global__ void prepA_k(const float* __restrict__ A) {
    __shared__ float sh[64][68];
    const int b = blockIdx.z;
    const int r0 = blockIdx.x * 64, c0 = blockIdx.y * 64;
    const int tid = threadIdx.x;
    const int row = tid >> 2, q = tid & 3;

    const float* Ab = A + (size_t)b * Nn * Nn;
    float rsum = 0.f;
    #pragma unroll
    for (int j = 0; j < 4; j++) {
        int idx4 = q + j * 4;
        float4 v = *(const float4*)&Ab[(size_t)(r0 + row) * Nn + c0 + idx4 * 4];
        *(float4*)&sh[row][idx4 * 4] = v;
        rsum += v.x + v.y + v.z + v.w;
        bf16 h0 = __float2bfloat16(v.x), h1 = __float2bfloat16(v.y);
        bf16 h2 = __float2bfloat16(v.z), h3 = __float2bfloat16(v.w);
        size_t o = ((size_t)b * Nn + r0 + row) * Nn + c0 + idx4 * 4;
        *(uint2*)&g_Ahi[o] = make_uint2(bpack(h0, h1), bpack(h2, h3));
    }
    rsum += __shfl_down_sync(0xffffffffu, rsum, 1);
    rsum += __shfl_down_sync(0xffffffffu, rsum, 2);
    if (q == 0) atomicAdd(&g_rs_d[b * Nn + r0 + row], rsum);
    __syncthreads();
    float csum = 0.f;
    #pragma unroll
    for (int j = 0; j < 4; j++) {
        int idx4 = q + j * 4;
        float4 v;
        v.x = sh[idx4 * 4 + 0][row];
        v.y = sh[idx4 * 4 + 1][row];
        v.z = sh[idx4 * 4 + 2][row];
        v.w = sh[idx4 * 4 + 3][row];
        csum += v.x + v.y + v.z + v.w;
        bf16 h0 = __float2bfloat16(v.x), h1 = __float2bfloat16(v.y);
        bf16 h2 = __float2bfloat16(v.z), h3 = __float2bfloat16(v.w);
        size_t o = ((size_t)b * Nn + c0 + row) * Nn + r0 + idx4 * 4;
        *(uint2*)&g_AThi[o] = make_uint2(bpack(h0, h1), bpack(h2, h3));
    }
    csum += __shfl_down_sync(0xffffffffu, csum, 1);
    csum += __shfl_down_sync(0xffffffffu, csum, 2);
    if (q == 0) atomicAdd(&g_cs_d[b * Nn + c0 + row], csum);
}

__global__ void prepS_k(const float* __restrict__ S) {
    const int r0 = blockIdx.x * 64, c0 = blockIdx.y * 64;
    const int tid = threadIdx.x;
    const int row = tid >> 2, q = tid & 3;
    float rsum = 0.f;
    #pragma unroll
    for (int j = 0; j < 4; j++) {
        int idx4 = q + j * 4;
        float4 v = *(const float4*)&S[(size_t)(r0 + row) * Nn + c0 + idx4 * 4];
        rsum += v.x + v.y + v.z + v.w;
        bf16 h0 = __float2bfloat16(v.x), h1 = __float2bfloat16(v.y);
        bf16 h2 = __float2bfloat16(v.z), h3 = __float2bfloat16(v.w);
        size_t o = (size_t)(r0 + row) * Nn + c0 + idx4 * 4;
        *(uint2*)&g_Shi[o] = make_uint2(bpack(h0, h1), bpack(h2, h3));
    }
    rsum += __shfl_down_sync(0xffffffffu, rsum, 1);
    rsum += __shfl_down_sync(0xffffffffu, rsum, 2);
    if (q == 0) atomicAdd(&g_rs_s[r0 + row], rsum);
}

__global__ void cvt_k(const float* __restrict__ A, bf16* __restrict__ hi,
                      bf16* __restrict__ lo, int n4) {
    int i = blockIdx.x * 256 + threadIdx.x;
    if (i >= n4) return;
    float4 a = ((const float4*)A)[i];
    bf16 h0, h1, h2, h3, l0, l1, l2, l3;
    bsplit(a.x, h0, l0); bsplit(a.y, h1, l1); bsplit(a.z, h2, l2); bsplit(a.w, h3, l3);
    ((uint2*)hi)[i] = make_uint2(bpack(h0, h1), bpack(h2, h3));
    ((uint2*)lo)[i] = make_uint2(bpack(l0, l1), bpack(l2, l3));
}

__global__ void embT_k(const float* __restrict__ spE, const float* __restrict__ tdE,
                       const float* __restrict__ twE) {
    int idx = blockIdx.x * 256 + threadIdx.x;
    if (idx >= Bb * 96 * (Nn / 4)) return;
    int n4 = idx % (Nn / 4);
    int rest = idx / (Nn / 4);
    int ch = rest % 96, b = rest / 96;
    const float* src = (ch < 32) ? spE : (ch < 64 ? tdE : twE);
    int c = ch & 31;
    float4 v = *(const float4*)(src + ((size_t)b * 32 + c) * Nn + n4 * 4);
    int oc = 32 + ch;
    float vv[4] = {v.x, v.y, v.z, v.w};
    size_t base = ((size_t)b * Nn + n4 * 4) * Hc + oc;
    #pragma unroll
    for (int u = 0; u < 4; u++) {
        bf16 h, l; bsplit(vv[u], h, l);
        g_in1Th[base + (size_t)u * Hc] = h;
        g_in1Tl[base + (size_t)u * Hc] = l;
    }
}

__global__ void combW_k(const float* __restrict__ W0, const float* __restrict__ W1,
                        const float* __restrict__ W2) {
    int idx = blockIdx.x * 256 + threadIdx.x;
    if (idx >= 3 * 32 * 224) return;
    int c = idx % 224;
    int m = (idx / 224) % 32;
    int i = idx / (224 * 32);
    const float* W[3] = {W0 + (size_t)i * 32 * 96, W1 + (size_t)i * 32 * 96, W2 + (size_t)i * 32 * 96};
    float v;
    if (c < 32) v = W[0][m * 96 + c] + W[1][m * 96 + c] + W[2][m * 96 + c];
    else {
        int t = c - 32, g = t >> 6, j = t & 63;
        v = W[g][m * 96 + 32 + j];
    }
    g_gWc[idx] = v;
}
__global__ void combB_k(const float* __restrict__ b0, const float* __restrict__ b1,
                        const float* __restrict__ b2) {
    int idx = threadIdx.x;
    if (idx < 96) g_gbc[idx] = b0[idx] + b1[idx] + b2[idx];
}

// ---------------- batched HMMA SpMM (A, H single-bf16) + fused epilogue ------
__global__ void __launch_bounds__(256) spmm_mma(SpmmB args) {
    __shared__ bf16 sAh[64 * AP];
    __shared__ bf16 sHh[32 * AP];

    const int tid = threadIdx.x, wid = tid >> 5, lane = tid & 31;
    const int g = lane >> 2, tg = lane & 3;
    const int vt = blockIdx.x, b = blockIdx.y, gr = blockIdx.z;
    const int v0 = vt * 64;
    const int warpV = (wid >> 1) * 16;
    const int c0w = (wid & 1) * 16;

    const bf16* Ah = args.A[gr] + (size_t)b * args.abst[gr];
    const bf16* Hh = args.H[gr] + (size_t)b * Ee * Nn;
    const float* hb = args.hin[gr] + (size_t)b * Ee * Nn;
    const float* den = args.den[gr];
    const int denB = args.denB[gr];

    const uint32_t sAh_u = smem_u32(sAh);
    const uint32_t sHh_u = smem_u32(sHh);
    const int rowA = warpV + (lane & 15);
    const int khA  = (lane >> 4) * 8;
    const uint32_t offA = (uint32_t)(rowA * AP + khA) * 2;
    const int rowB = c0w + (lane & 7) + ((lane >> 4) & 1) * 8;
    const int khB  = ((lane >> 3) & 1) * 8;
    const uint32_t offB = (uint32_t)(rowB * AP + khB) * 2;

    float4 acc[2] = {};

    int ar0 = tid >> 3,           au0 = tid & 7;
    int ar1 = (tid + 256) >> 3,   au1 = tid & 7;
    int hc  = tid >> 3,           hu = tid & 7;
    const bool doH = (tid < 256);  // H: 256 uint4 but only first 256 threads... (256 threads, all)

    uint4 pAh0, pAh1, pHh;
    {
        pAh0 = *(const uint4*)(Ah + (size_t)(v0 + ar0) * Nn + au0 * 8);
        pAh1 = *(const uint4*)(Ah + (size_t)(v0 + ar1) * Nn + au1 * 8);
        pHh  = *(const uint4*)(Hh + (size_t)hc * Nn + hu * 8);
    }

    for (int ch = 0; ch < 32; ch++) {
        __syncthreads();
        *(uint4*)&sAh[ar0 * AP + au0 * 8] = pAh0;
        *(uint4*)&sAh[ar1 * AP + au1 * 8] = pAh1;
        if (doH) *(uint4*)&sHh[hc * AP + hu * 8] = pHh;
        if (ch < 31) {
            const int w0 = (ch + 1) * 64;
            pAh0 = *(const uint4*)(Ah + (size_t)(v0 + ar0) * Nn + w0 + au0 * 8);
            pAh1 = *(const uint4*)(Ah + (size_t)(v0 + ar1) * Nn + w0 + au1 * 8);
            pHh  = *(const uint4*)(Hh + (size_t)hc * Nn + w0 + hu * 8);
        }
        __syncthreads();
        #pragma unroll
        for (int ks = 0; ks < 4; ks++) {
            const uint32_t ko = ks * 32;
            uint32_t ah0, ah1, ah2, ah3;
            uint32_t bh00, bh01, bh10, bh11;
            ldm4(ah0, ah1, ah2, ah3, sAh_u + offA + ko);
            ldm4(bh00, bh01, bh10, bh11, sHh_u + offB + ko);
            hmma(acc[0], ah0, ah1, ah2, ah3, bh00, bh01);
            hmma(acc[1], ah0, ah1, ah2, ah3, bh10, bh11);
        }
    }

    const int vlo = v0 + warpV + g;
    const int vhi = vlo + 8;
    const float dn_lo = den[denB * b + vlo];
    const float dn_hi = den[denB * b + vhi];
    const float* xb = g_x + (size_t)b * Ee * Nn;
    float* ob = args.hout[gr] + (size_t)b * Ee * Nn;
    bf16* oh = args.sOut[gr] + (size_t)b * Ee * Nn;
    #pragma unroll
    for (int nt = 0; nt < 2; nt++) {
        int c0 = c0w + nt * 8 + 2 * tg;
        float vals[4];
        size_t idxs[4];
        idxs[0] = (size_t)c0 * Nn + vlo;
        idxs[1] = (size_t)(c0 + 1) * Nn + vlo;
        idxs[2] = (size_t)c0 * Nn + vhi;
        idxs[3] = (size_t)(c0 + 1) * Nn + vhi;
        vals[0] = ALPHA * xb[idxs[0]] + (1.0f - ALPHA) * ((acc[nt].x + hb[idxs[0]]) / dn_lo);
        vals[1] = ALPHA * xb[idxs[1]] + (1.0f - ALPHA) * ((acc[nt].y + hb[idxs[1]]) / dn_lo);
        vals[2] = ALPHA * xb[idxs[2]] + (1.0f - ALPHA) * ((acc[nt].z + hb[idxs[2]]) / dn_hi);
        vals[3] = ALPHA * xb[idxs[3]] + (1.0f - ALPHA) * ((acc[nt].w + hb[idxs[3]]) / dn_hi);
        #pragma unroll
        for (int u = 0; u < 4; u++) {
            ob[idxs[u]] = vals[u];
            if (args.writeSplit) oh[idxs[u]] = __float2bfloat16(vals[u]);
        }
    }
}

// ---------------- HMMA gated conv ----------------
__global__ void __launch_bounds__(256) gated_mma(
        const bf16* __restrict__ inTh, const bf16* __restrict__ inTl,
        const bf16* __restrict__ Wfh, const bf16* __restrict__ Wfl,
        const bf16* __restrict__ Wgh, const bf16* __restrict__ Wgl,
        const float* __restrict__ bf_, const float* __restrict__ bg_,
        bf16* __restrict__ outTh, bf16* __restrict__ outTl) {
    __shared__ bf16 sWfh[Hc * CP], sWfl[Hc * CP], sWgh[Hc * CP], sWgl[Hc * CP];
    __shared__ bf16 sIh[64 * CP], sIl[64 * CP];

    const int tid = threadIdx.x, wid = tid >> 5, lane = tid & 31;
    const int g = lane >> 2, tg = lane & 3;
    const int col0 = blockIdx.x * 64;
    const int b = col0 / Nn, n0 = col0 % Nn;
    const int warpM = wid * 16;

    const uint32_t sWfh_u = smem_u32(sWfh), sWfl_u = smem_u32(sWfl);
    const uint32_t sWgh_u = smem_u32(sWgh), sWgl_u = smem_u32(sWgl);
    const uint32_t sIh_u = smem_u32(sIh), sIl_u = smem_u32(sIl);
    const uint32_t offA = (uint32_t)((warpM + (lane & 15)) * CP + (lane >> 4) * 8) * 2;
    const uint32_t offB = (uint32_t)(((lane & 7) + ((lane >> 4) & 1) * 8) * CP
                                     + ((lane >> 3) & 1) * 8) * 2;

    float4 aF[8] = {}, aG[8] = {};

    const int wrow = tid >> 1, whalf = tid & 1;
    const int it = tid & 127, iarr = tid >> 7;
    const int irow = it >> 1, ihalf = it & 1;
    const bf16* isrc = iarr ? inTl : inTh;
    bf16* idst = iarr ? sIl : sIh;

    for (int chunk = 0; chunk < 8; chunk++) {
        const int k0 = chunk * 16;
        __syncthreads();
        size_t wg = (size_t)wrow * Hc + k0 + whalf * 8;
        *(uint4*)&sWfh[wrow * CP + whalf * 8] = *(const uint4*)(Wfh + wg);
        *(uint4*)&sWfl[wrow * CP + whalf * 8] = *(const uint4*)(Wfl + wg);
        *(uint4*)&sWgh[wrow * CP + whalf * 8] = *(const uint4*)(Wgh + wg);
        *(uint4*)&sWgl[wrow * CP + whalf * 8] = *(const uint4*)(Wgl + wg);
        *(uint4*)&idst[irow * CP + ihalf * 8] =
            *(const uint4*)(isrc + ((size_t)b * Nn + n0 + irow) * Hc + k0 + ihalf * 8);
        __syncthreads();

        uint32_t fh0, fh1, fh2, fh3, fl0, fl1, fl2, fl3;
        uint32_t gh0, gh1, gh2, gh3, gl0, gl1, gl2, gl3;
        ldm4(fh0, fh1, fh2, fh3, sWfh_u + offA);
        ldm4(fl0, fl1, fl2, fl3, sWfl_u + offA);
        ldm4(gh0, gh1, gh2, gh3, sWgh_u + offA);
        ldm4(gl0, gl1, gl2, gl3, sWgl_u + offA);
        #pragma unroll
        for (int grp = 0; grp < 4; grp++) {
            const uint32_t go = (uint32_t)(grp * 16 * CP) * 2;
            uint32_t bh0, bh1, bh2, bh3, bl0, bl1, bl2, bl3;
            ldm4(bh0, bh1, bh2, bh3, sIh_u + go + offB);
            ldm4(bl0, bl1, bl2, bl3, sIl_u + go + offB);
            hmma(aF[2*grp], fh0, fh1, fh2, fh3, bh0, bh1);
            hmma(aF[2*grp], fh0, fh1, fh2, fh3, bl0, bl1);
            hmma(aF[2*grp], fl0, fl1, fl2, fl3, bh0, bh1);
            hmma(aF[2*grp+1], fh0, fh1, fh2, fh3, bh2, bh3);
            hmma(aF[2*grp+1], fh0, fh1, fh2, fh3, bl2, bl3);
            hmma(aF[2*grp+1], fl0, fl1, fl2, fl3, bh2, bh3);
            hmma(aG[2*grp], gh0, gh1, gh2, gh3, bh0, bh1);
            hmma(aG[2*grp], gh0, gh1, gh2, gh3, bl0, bl1);
            hmma(aG[2*grp], gl0, gl1, gl2, gl3, bh0, bh1);
            hmma(aG[2*grp+1], gh0, gh1, gh2, gh3, bh2, bh3);
            hmma(aG[2*grp+1], gh0, gh1, gh2, gh3, bl2, bl3);
            hmma(aG[2*grp+1], gl0, gl1, gl2, gl3, bh2, bh3);
        }
    }

    const int m_lo = warpM + g, m_hi = m_lo + 8;
    const float bflo = bf_[m_lo], bfhi = bf_[m_hi];
    const float bglo = bg_[m_lo], bghi = bg_[m_hi];
    #pragma unroll
    for (int nt = 0; nt < 8; nt++) {
        int n = n0 + nt * 8 + 2 * tg;
        size_t r0 = ((size_t)b * Nn + n) * Hc;
        size_t r1 = r0 + Hc;
        float v0 = tanhf(aF[nt].x + bflo) * (1.f / (1.f + expf(-(aG[nt].x + bglo))));
        float v1 = tanhf(aF[nt].y + bflo) * (1.f / (1.f + expf(-(aG[nt].y + bglo))));
        float v2 = tanhf(aF[nt].z + bfhi) * (1.f / (1.f + expf(-(aG[nt].z + bghi))));
        float v3 = tanhf(aF[nt].w + bfhi) * (1.f / (1.f + expf(-(aG[nt].w + bghi))));
        bf16 h, l;
        bsplit(v0, h, l); outTh[r0 + m_lo] = h; outTl[r0 + m_lo] = l;
        bsplit(v1, h, l); outTh[r1 + m_lo] = h; outTl[r1 + m_lo] = l;
        bsplit(v2, h, l); outTh[r0 + m_hi] = h; outTl[r0 + m_hi] = l;
        bsplit(v3, h, l); outTh[r1 + m_hi] = h; outTl[r1 + m_hi] = l;
    }
}

// ---------------- HMMA skip conv ----------------
__global__ void __launch_bounds__(256) skip_mma(
        const bf16* __restrict__ inTh, const bf16* __restrict__ inTl,
        const bf16* __restrict__ Wh, const bf16* __restrict__ Wl,
        const float* __restrict__ bias, float* __restrict__ out, int accFlag) {
    __shared__ bf16 sWh[Hc * CP], sWl[Hc * CP];
    __shared__ bf16 sIh[64 * CP], sIl[64 * CP];

    const int tid = threadIdx.x, wid = tid >> 5, lane = tid & 31;
    const int g = lane >> 2, tg = lane & 3;
    const int col0 = blockIdx.x * 64;
    const int b = col0 / Nn, n0 = col0 % Nn;
    const int mbase = blockIdx.y * 128;
    const int warpM = wid * 16;

    const uint32_t sWh_u = smem_u32(sWh), sWl_u = smem_u32(sWl);
    const uint32_t sIh_u = smem_u32(sIh), sIl_u = smem_u32(sIl);
    const uint32_t offA = (uint32_t)((warpM + (lane & 15)) * CP + (lane >> 4) * 8) * 2;
    const uint32_t offB = (uint32_t)(((lane & 7) + ((lane >> 4) & 1) * 8) * CP
                                     + ((lane >> 3) & 1) * 8) * 2;

    float4 acc[8] = {};

    const int wrow = tid >> 1, whalf = tid & 1;
    const int it = tid & 127, iarr = tid >> 7;
    const int irow = it >> 1, ihalf = it & 1;
    const bf16* isrc = iarr ? inTl : inTh;
    bf16* idst = iarr ? sIl : sIh;

    for (int chunk = 0; chunk < 8; chunk++) {
        const int k0 = chunk * 16;
        __syncthreads();
        size_t wg = (size_t)(mbase + wrow) * Hc + k0 + whalf * 8;
        *(uint4*)&sWh[wrow * CP + whalf * 8] = *(const uint4*)(Wh + wg);
        *(uint4*)&sWl[wrow * CP + whalf * 8] = *(const uint4*)(Wl + wg);
        *(uint4*)&idst[irow * CP + ihalf * 8] =
            *(const uint4*)(isrc + ((size_t)b * Nn + n0 + irow) * Hc + k0 + ihalf * 8);
        __syncthreads();

        uint32_t wh0, wh1, wh2, wh3, wl0, wl1, wl2, wl3;
        ldm4(wh0, wh1, wh2, wh3, sWh_u + offA);
        ldm4(wl0, wl1, wl2, wl3, sWl_u + offA);
        #pragma unroll
        for (int grp = 0; grp < 4; grp++) {
            const uint32_t go = (uint32_t)(grp * 16 * CP) * 2;
            uint32_t bh0, bh1, bh2, bh3, bl0, bl1, bl2, bl3;
            ldm4(bh0, bh1, bh2, bh3, sIh_u + go + offB);
            ldm4(bl0, bl1, bl2, bl3, sIl_u + go + offB);
            hmma(acc[2*grp], wh0, wh1, wh2, wh3, bh0, bh1);
            hmma(acc[2*grp], wh0, wh1, wh2, wh3, bl0, bl1);
            hmma(acc[2*grp], wl0, wl1, wl2, wl3, bh0, bh1);
            hmma(acc[2*grp+1], wh0, wh1, wh2, wh3, bh2, bh3);
            hmma(acc[2*grp+1], wh0, wh1, wh2, wh3, bl2, bl3);
            hmma(acc[2*grp+1], wl0, wl1, wl2, wl3, bh2, bh3);
        }
    }

    const int m_lo = mbase + warpM + g, m_hi = m_lo + 8;
    const float blo = bias[m_lo], bhi = bias[m_hi];
    #pragma unroll
    for (int nt = 0; nt < 8; nt++) {
        int n = n0 + nt * 8 + 2 * tg;
        float* d0 = &out[((size_t)b * Sc + m_lo) * Nn + n];
        float* d1 = &out[((size_t)b * Sc + m_hi) * Nn + n];
        float2 r0 = make_float2(acc[nt].x + blo, acc[nt].y + blo);
        float2 r1 = make_float2(acc[nt].z + bhi, acc[nt].w + bhi);
        if (accFlag) {
            float2 o0 = *(float2*)d0, o1 = *(float2*)d1;
            r0.x += o0.x; r0.y += o0.y; r1.x += o1.x; r1.y += o1.y;
        }
        *(float2*)d0 = r0;
        *(float2*)d1 = r1;
    }
}

// ---------------- generic 1x1 conv (f32x2 packed) with optional identity add --
__global__ void conv1x1_k(Srcs srcs, int inBStride,
                          const float* __restrict__ W, const float* __restrict__ bias,
                          int M, int K, float* __restrict__ out, int outBStride,
                          int accFlag, const float* __restrict__ iden) {
    __shared__ float Ws[16 * 68];
    __shared__ float Ins[16 * 68];
    const int tid = threadIdx.x;
    const int tx = tid & 15, ty = tid >> 4;
    const int col0 = blockIdx.x * 64;
    const int b = col0 / Nn, n0 = col0 % Nn;
    const int m0 = blockIdx.y * 64;

    u64 accP[4][2] = {};

    for (int k0 = 0; k0 < K; k0 += 16) {
        for (int t = tid; t < 1024; t += 256) {
            int m = t >> 4, kk = t & 15;
            Ws[kk * 68 + m] = (m0 + m < M) ? W[(size_t)(m0 + m) * K + k0 + kk] : 0.f;
        }
        for (int t = tid; t < 1024; t += 256) {
            int kk = t >> 6, n = t & 63;
            int c = k0 + kk;
            Ins[kk * 68 + n] = srcs.p[c >> 5][(size_t)b * inBStride + (size_t)(c & 31) * Nn + n0 + n];
        }
        __syncthreads();
        #pragma unroll
        for (int kk = 0; kk < 16; kk++) {
            float4 wv = *(const float4*)&Ws[kk * 68 + ty * 4];
            u64 ip0 = *(const u64*)&Ins[kk * 68 + tx * 4];
            u64 ip1 = *(const u64*)&Ins[kk * 68 + tx * 4 + 2];
            float wa[4] = {wv.x, wv.y, wv.z, wv.w};
            #pragma unroll
            for (int u = 0; u < 4; u++) {
                u64 wp = splat2(wa[u]);
                accP[u][0] = fma2(wp, ip0, accP[u][0]);
                accP[u][1] = fma2(wp, ip1, accP[u][1]);
            }
        }
        __syncthreads();
    }
    #pragma unroll
    for (int u = 0; u < 4; u++) {
        int m = m0 + ty * 4 + u;
        if (m >= M) break;
        float bm = bias[m];
        float4 r;
        upk2(accP[u][0], r.x, r.y);
        upk2(accP[u][1], r.z, r.w);
        r.x += bm; r.y += bm; r.z += bm; r.w += bm;
        float* dst = &out[(size_t)b * outBStride + (size_t)m * Nn + n0 + tx * 4];
        if (iden) {
            float4 o = *(const float4*)&iden[(size_t)b * outBStride + (size_t)m * Nn + n0 + tx * 4];
            r.x += o.x; r.y += o.y; r.z += o.z; r.w += o.w;
        }
        if (accFlag) {
            float4 o = *(float4*)dst;
            r.x += o.x; r.y += o.y; r.z += o.z; r.w += o.w;
        }
        *(float4*)dst = r;
    }
}

// ---------------- layernorm (two-stage) ----------------
__global__ void zero_red_k() {
    if (threadIdx.x < Bb * 2) g_red[threadIdx.x] = 0.f;
}
__global__ void ln_part_k() {
    int b = blockIdx.y, z = blockIdx.x;
    const float* xp = g_xacc + (size_t)b * Ee * Nn + (size_t)z * (Ee * Nn / 16);
    float s = 0.f, s2 = 0.f;
    for (int i = threadIdx.x; i < Ee * Nn / 16; i += 256) {
        float v = xp[i];
        s += v; s2 += v * v;
    }
    float ts = blockReduceSum(s);
    float ts2 = blockReduceSum(s2);
    if (threadIdx.x == 0) {
        atomicAdd(&g_red[b * 2], ts);
        atomicAdd(&g_red[b * 2 + 1], ts2);
    }
}

__global__ void ln_apply_k(const float* __restrict__ w, const float* __restrict__ bparm) {
    int i = blockIdx.x * 256 + threadIdx.x;
    if (i >= NEL) return;
    int b = i >> 16;
    int cn = i & (Ee * Nn - 1);
    float inv = 1.0f / (Ee * Nn);
    float mu = g_red[b * 2] * inv;
    float var = g_red[b * 2 + 1] * inv - mu * mu;
    float val = (g_xacc[i] - mu) * rsqrtf(var + EPSV) * w[cn] + bparm[cn];
    val = fmaxf(val, 0.f);
    g_x[i] = val;
    bf16 h, l; bsplit(val, h, l);
    g_sxHi[i] = h;
    int n = i & (Nn - 1);
    int c = (i >> 11) & 31;
    size_t o = ((size_t)b * Nn + n) * Hc + c;
    g_in1Th[o] = h;
    g_in1Tl[o] = l;
}

// ---------------- host orchestration ----------------
extern "C" void kernel_launch(void* const* d_in, const int* in_sizes, int n_in,
                              void* d_out, int out_size) {
    (void)in_sizes; (void)n_in; (void)out_size;
    const float* in_x  = (const float*)d_in[0];
    const float* dyG   = (const float*)d_in[1];
    const float* stG   = (const float*)d_in[2];
    const float* spE   = (const float*)d_in[3];
    const float* tdE   = (const float*)d_in[4];
    const float* twE   = (const float*)d_in[5];
    const float* encWf = (const float*)d_in[6];
    const float* encbf = (const float*)d_in[7];
    const float* encWg = (const float*)d_in[8];
    const float* encbg = (const float*)d_in[9];
    const float* skW   = (const float*)d_in[10];
    const float* skb   = (const float*)d_in[11];
    const float* nw    = (const float*)d_in[12];
    const float* nb    = (const float*)d_in[13];
    const float* gW[3] = {(const float*)d_in[14], (const float*)d_in[16], (const float*)d_in[18]};
    const float* gb[3] = {(const float*)d_in[15], (const float*)d_in[17], (const float*)d_in[19]};
    const float* seW   = (const float*)d_in[20];
    const float* seb   = (const float*)d_in[21];
    const float* eW    = (const float*)d_in[22];
    const float* eb    = (const float*)d_in[23];
    float* outp = (float*)d_out;

    float *px, *pxacc, *pskip, *prss, *prsd, *pcsd, *ph1g, *ph2g, *pgWc, *pgbc;
    cudaGetSymbolAddress((void**)&px,    g_x);
    cudaGetSymbolAddress((void**)&pxacc, g_xacc);
    cudaGetSymbolAddress((void**)&pskip, g_skip);
    cudaGetSymbolAddress((void**)&prss,  g_rs_s);
    cudaGetSymbolAddress((void**)&prsd,  g_rs_d);
    cudaGetSymbolAddress((void**)&pcsd,  g_cs_d);
    cudaGetSymbolAddress((void**)&ph1g,  g_h1g);
    cudaGetSymbolAddress((void**)&ph2g,  g_h2g);
    cudaGetSymbolAddress((void**)&pgWc,  g_gWc);
    cudaGetSymbolAddress((void**)&pgbc,  g_gbc);
    bf16 *pAhi, *pAThi, *pShi, *psxHi, *ps1Hi;
    cudaGetSymbolAddress((void**)&pAhi,  g_Ahi);
    cudaGetSymbolAddress((void**)&pAThi, g_AThi);
    cudaGetSymbolAddress((void**)&pShi,  g_Shi);
    cudaGetSymbolAddress((void**)&psxHi, g_sxHi);
    cudaGetSymbolAddress((void**)&ps1Hi, g_s1Hi);
    bf16 *pin1Th, *pin1Tl, *phidTh, *phidTl, *phid2Th, *phid2Tl;
    cudaGetSymbolAddress((void**)&pin1Th, g_in1Th);
    cudaGetSymbolAddress((void**)&pin1Tl, g_in1Tl);
    cudaGetSymbolAddress((void**)&phidTh, g_hidTh);
    cudaGetSymbolAddress((void**)&phidTl, g_hidTl);
    cudaGetSymbolAddress((void**)&phid2Th, g_hid2Th);
    cudaGetSymbolAddress((void**)&phid2Tl, g_hid2Tl);
    bf16 *peWfh, *peWfl, *peWgh, *peWgl, *pskWh, *pskWl;
    cudaGetSymbolAddress((void**)&peWfh, g_eWfh);
    cudaGetSymbolAddress((void**)&peWfl, g_eWfl);
    cudaGetSymbolAddress((void**)&peWgh, g_eWgh);
    cudaGetSymbolAddress((void**)&peWgl, g_eWgl);
    cudaGetSymbolAddress((void**)&pskWh, g_skWh);
    cudaGetSymbolAddress((void**)&pskWl, g_skWl);

    // ---- prep ----
    copy_split_k<<<(NEL / 4 + 255) / 256, 256>>>(px, in_x);
    init_den_k<<<(Bb * Nn + 255) / 256, 256>>>();
    prepA_k<<<dim3(Nn / 64, Nn / 64, Bb), 256>>>(dyG);
    prepS_k<<<dim3(Nn / 64, Nn / 64), 256>>>(stG);
    cvt_k<<<(6 * Hc * Hc / 4 + 255) / 256, 256>>>(encWf, peWfh, peWfl, 6 * Hc * Hc / 4);
    cvt_k<<<(6 * Hc * Hc / 4 + 255) / 256, 256>>>(encWg, peWgh, peWgl, 6 * Hc * Hc / 4);
    cvt_k<<<(3 * Sc * Hc / 4 + 255) / 256, 256>>>(skW, pskWh, pskWl, 3 * Sc * Hc / 4);
    embT_k<<<(Bb * 96 * (Nn / 4) + 255) / 256, 256>>>(spE, tdE, twE);
    combW_k<<<(3 * 32 * 224 + 255) / 256, 256>>>(gW[0], gW[1], gW[2]);
    combB_k<<<1, 96>>>(gb[0], gb[1], gb[2]);

    // shared SpMM arg skeleton
    SpmmB ab;
    ab.A[0] = pShi;  ab.abst[0] = 0;                   ab.den[0] = prss; ab.denB[0] = 0;
    ab.A[1] = pAhi;  ab.abst[1] = (u64)Nn * Nn;        ab.den[1] = prsd; ab.denB[1] = Nn;
    ab.A[2] = pAThi; ab.abst[2] = (u64)Nn * Nn;        ab.den[2] = pcsd; ab.denB[2] = Nn;

    const dim3 convGrid(Bb * Nn / 64, 1);
    const dim3 spmmGrid(Nn / 64, Bb, 3);
    for (int i = 0; i < 3; i++) {
        // ---- TCN chain (HMMA) ----
        gated_mma<<<Bb * Nn / 64, 256>>>(pin1Th, pin1Tl,
            peWfh + (size_t)(i * 2 + 0) * Hc * Hc, peWfl + (size_t)(i * 2 + 0) * Hc * Hc,
            peWgh + (size_t)(i * 2 + 0) * Hc * Hc, peWgl + (size_t)(i * 2 + 0) * Hc * Hc,
            encbf + (i * 2 + 0) * Hc, encbg + (i * 2 + 0) * Hc, phidTh, phidTl);
        gated_mma<<<Bb * Nn / 64, 256>>>(phidTh, phidTl,
            peWfh + (size_t)(i * 2 + 1) * Hc * Hc, peWfl + (size_t)(i * 2 + 1) * Hc * Hc,
            peWgh + (size_t)(i * 2 + 1) * Hc * Hc, peWgl + (size_t)(i * 2 + 1) * Hc * Hc,
            encbf + (i * 2 + 1) * Hc, encbg + (i * 2 + 1) * Hc, phid2Th, phid2Tl);
        // ---- skip += skip_W @ hidden (HMMA) ----
        skip_mma<<<dim3(Bb * Nn / 64, 2), 256>>>(phid2Th, phid2Tl,
            pskWh + (size_t)i * Sc * Hc, pskWl + (size_t)i * Sc * Hc,
            skb + i * Sc, pskip, i > 0);
        // ---- mixprop hops: batched over 3 graphs ----
        SpmmB a1 = ab;
        for (int g = 0; g < 3; g++) {
            a1.H[g] = psxHi;
            a1.hin[g] = px;
            a1.hout[g] = ph1g + (size_t)g * NEL;
            a1.sOut[g] = ps1Hi + (size_t)g * NEL;
        }
        a1.writeSplit = 1;
        spmm_mma<<<spmmGrid, 256>>>(a1);
        SpmmB a2 = ab;
        for (int g = 0; g < 3; g++) {
            a2.H[g] = ps1Hi + (size_t)g * NEL;
            a2.hin[g] = ph1g + (size_t)g * NEL;
            a2.hout[g] = ph2g + (size_t)g * NEL;
            a2.sOut[g] = ps1Hi + (size_t)g * NEL;  // unused
        }
        a2.writeSplit = 0;
        spmm_mma<<<spmmGrid, 256>>>(a2);
        // ---- combined mixprop MLP: xacc = x + Wc @ [x,h1g0,h2g0,...] + bc ----
        Srcs sm;
        sm.p[0] = px;
        sm.p[1] = ph1g + 0 * NEL; sm.p[2] = ph2g + 0 * NEL;
        sm.p[3] = ph1g + 1 * NEL; sm.p[4] = ph2g + 1 * NEL;
        sm.p[5] = ph1g + 2 * NEL; sm.p[6] = ph2g + 2 * NEL;
        conv1x1_k<<<convGrid, 256>>>(sm, Ee * Nn,
            pgWc + (size_t)i * 32 * 224, pgbc + i * 32, Ee, 224, pxacc, Ee * Nn, 0, px);
        // ---- layernorm + relu (two-stage stats) ----
        zero_red_k<<<1, 32>>>();
        ln_part_k<<<dim3(16, Bb), 256>>>();
        ln_apply_k<<<NEL / 256, 256>>>(nw + (size_t)i * Ee * Nn, nb + (size_t)i * Ee * Nn);
    }
    // ---- skip end + output ----
    Srcs se; se.p[0] = px;
    conv1x1_k<<<dim3(Bb * Nn / 64, 4), 256>>>(se, Ee * Nn, seW, seb, Sc, Ee, pskip, Sc * Nn, 1, nullptr);
    Srcs send; for (int s = 0; s < 8; s++) send.p[s] = pskip + (size_t)s * 32 * Nn;
    conv1x1_k<<<convGrid, 256>>>(send, Sc * Nn, eW, eb, Tt, Sc, outp, Tt * Nn, 0, nullptr);
}

// round 14
// speedup vs baseline: 3.0838x; 1.0492x over previous
#include <cuda_runtime.h>
#include <cuda_bf16.h>
#include <math.h>
#include <stdint.h>

#define Bb 8
#define Nn 2048
#define Ee 32
#define Hc 128
#define Sc 256
#define Tt 12
#define NEL (Bb*Ee*Nn)
#define ALPHA 0.05f
#define EPSV 1e-5f
#define AP 72   // spmm smem pitch bf16 (144B)
#define CP 24   // conv smem pitch bf16 (48B)

typedef unsigned long long u64;
typedef __nv_bfloat16 bf16;

// ---------------- packed fp32x2 helpers (for SIMT convs) ----------------
__device__ __forceinline__ u64 splat2(float a) {
    u64 d; asm("mov.b64 %0, {%1, %1};" : "=l"(d) : "f"(a)); return d;
}
__device__ __forceinline__ void upk2(u64 v, float& lo, float& hi) {
    asm("mov.b64 {%0, %1}, %2;" : "=f"(lo), "=f"(hi) : "l"(v));
}
__device__ __forceinline__ u64 fma2(u64 a, u64 b, u64 c) {
    u64 d; asm("fma.rn.f32x2 %0, %1, %2, %3;" : "=l"(d) : "l"(a), "l"(b), "l"(c)); return d;
}

// ---------------- warp-level bf16 MMA + ldmatrix ----------------
__device__ __forceinline__ void hmma(float4& d, uint32_t a0, uint32_t a1, uint32_t a2,
                                     uint32_t a3, uint32_t b0, uint32_t b1) {
    asm volatile(
        "mma.sync.aligned.m16n8k16.row.col.f32.bf16.bf16.f32 "
        "{%0,%1,%2,%3}, {%4,%5,%6,%7}, {%8,%9}, {%0,%1,%2,%3};"
        : "+f"(d.x), "+f"(d.y), "+f"(d.z), "+f"(d.w)
        : "r"(a0), "r"(a1), "r"(a2), "r"(a3), "r"(b0), "r"(b1));
}
__device__ __forceinline__ void ldm4(uint32_t& r0, uint32_t& r1, uint32_t& r2, uint32_t& r3,
                                     uint32_t addr) {
    asm volatile("ldmatrix.sync.aligned.m8n8.x4.shared.b16 {%0,%1,%2,%3}, [%4];"
        : "=r"(r0), "=r"(r1), "=r"(r2), "=r"(r3) : "r"(addr));
}
__device__ __forceinline__ void ldm4t(uint32_t& r0, uint32_t& r1, uint32_t& r2, uint32_t& r3,
                                      uint32_t addr) {
    asm volatile("ldmatrix.sync.aligned.m8n8.x4.trans.shared.b16 {%0,%1,%2,%3}, [%4];"
        : "=r"(r0), "=r"(r1), "=r"(r2), "=r"(r3) : "r"(addr));
}
__device__ __forceinline__ uint32_t smem_u32(const void* p) {
    uint32_t a;
    asm("{ .reg .u64 t; cvta.to.shared.u64 t, %1; cvt.u32.u64 %0, t; }" : "=r"(a) : "l"(p));
    return a;
}

// ---------------- device scratch ----------------
__device__ float g_x[NEL];
__device__ float g_xacc[NEL];
__device__ float g_h1g[3][NEL];
__device__ float g_h2g[3][NEL];
__device__ float g_skip[Bb*Sc*Nn];
__device__ float g_rs_s[Nn];
__device__ float g_rs_d[Bb*Nn];
__device__ float g_cs_d[Bb*Nn];
__device__ float g_red[Bb*2];
__device__ bf16 g_Ahi[Bb*Nn*Nn];
__device__ bf16 g_Shi[Nn*Nn];
__device__ bf16 g_sxHi[NEL];
__device__ bf16 g_s1Hi[3][NEL];
// transposed-split activations [b][n][128]
__device__ bf16 g_in1Th[Bb*Nn*Hc];
__device__ bf16 g_in1Tl[Bb*Nn*Hc];
__device__ bf16 g_hidTh[Bb*Nn*Hc];
__device__ bf16 g_hidTl[Bb*Nn*Hc];
__device__ bf16 g_hid2Th[Bb*Nn*Hc];
__device__ bf16 g_hid2Tl[Bb*Nn*Hc];
// split weights
__device__ bf16 g_eWfh[6*Hc*Hc];
__device__ bf16 g_eWfl[6*Hc*Hc];
__device__ bf16 g_eWgh[6*Hc*Hc];
__device__ bf16 g_eWgl[6*Hc*Hc];
__device__ bf16 g_skWh[3*Sc*Hc];
__device__ bf16 g_skWl[3*Sc*Hc];
// combined mixprop mlp weights
__device__ float g_gWc[3*32*224];
__device__ float g_gbc[96];

struct Srcs { const float* p[8]; };
struct SpmmB {
    const bf16* A[3];
    u64 abst[3];
    const float* den[3];
    int denB[3];
    const bf16* H[3];
    const float* hin[3];
    float* hout[3];
    bf16* sOut[3];
    int writeSplit;
};

__device__ __forceinline__ void bsplit(float a, bf16& h, bf16& l) {
    h = __float2bfloat16(a);
    l = __float2bfloat16(a - __bfloat162float(h));
}
__device__ __forceinline__ uint32_t bpack(bf16 a, bf16 b) {
    __nv_bfloat162 t; t.x = a; t.y = b;
    return *reinterpret_cast<uint32_t*>(&t);
}

// ---------------- helpers ----------------
__device__ __forceinline__ float blockReduceSum(float v) {
    __shared__ float sh[32];
    int lane = threadIdx.x & 31, wid = threadIdx.x >> 5;
    #pragma unroll
    for (int o = 16; o; o >>= 1) v += __shfl_down_sync(0xffffffffu, v, o);
    __syncthreads();
    if (lane == 0) sh[wid] = v;
    __syncthreads();
    int nw = blockDim.x >> 5;
    v = (threadIdx.x < nw) ? sh[threadIdx.x] : 0.f;
    if (wid == 0) {
        #pragma unroll
        for (int o = 16; o; o >>= 1) v += __shfl_down_sync(0xffffffffu, v, o);
    }
    return v;
}

__global__ void copy_split_k(float* __restrict__ dst, const float* __restrict__ src) {
    int i = blockIdx.x * 256 + threadIdx.x;
    if (i >= NEL / 4) return;
    float4 a = ((const float4*)src)[i];
    ((float4*)dst)[i] = a;
    bf16 h[4], l[4];
    bsplit(a.x, h[0], l[0]); bsplit(a.y, h[1], l[1]);
    bsplit(a.z, h[2], l[2]); bsplit(a.w, h[3], l[3]);
    ((uint2*)g_sxHi)[i] = make_uint2(bpack(h[0], h[1]), bpack(h[2], h[3]));
    int n4 = i % (Nn / 4);
    int c  = (i / (Nn / 4)) % Ee;
    int b  = i / (Ee * Nn / 4);
    size_t base = ((size_t)b * Nn + n4 * 4) * Hc + c;
    #pragma unroll
    for (int u = 0; u < 4; u++) {
        g_in1Th[base + (size_t)u * Hc] = h[u];
        g_in1Tl[base + (size_t)u * Hc] = l[u];
    }
}

// ---------------- fused prep ----------------
__global__ void init_den_k() {
    int i = blockIdx.x * 256 + threadIdx.x;
    if (i < Nn) g_rs_s[i] = 1.0f;
    if (i < Bb * Nn) { g_rs_d[i] = 1.0f; g_cs_d[i] = 1.0f; }
}

// one pass: Ahi (bf16), rowsum, colsum (no transposed copy)
__global__ void prepA_k(const float* __restrict__ A) {
    __shared__ float sh[64][68];
    const int b = blockIdx.z;
    const int r0 = blockIdx.x * 64, c0 = blockIdx.y * 64;
    const int tid = threadIdx.x;
    const int row = tid >> 2, q = tid & 3;

    const float* Ab = A + (size_t)b * Nn * Nn;
    float rsum = 0.f;
    #pragma unroll
    for (int j = 0; j < 4; j++) {
        int idx4 = q + j * 4;
        float4 v = *(const float4*)&Ab[(size_t)(r0 + row) * Nn + c0 + idx4 * 4];
        *(float4*)&sh[row][idx4 * 4] = v;
        rsum += v.x + v.y + v.z + v.w;
        bf16 h0 = __float2bfloat16(v.x), h1 = __float2bfloat16(v.y);
        bf16 h2 = __float2bfloat16(v.z), h3 = __float2bfloat16(v.w);
        size_t o = ((size_t)b * Nn + r0 + row) * Nn + c0 + idx4 * 4;
        *(uint2*)&g_Ahi[o] = make_uint2(bpack(h0, h1), bpack(h2, h3));
    }
    rsum += __shfl_down_sync(0xffffffffu, rsum, 1);
    rsum += __shfl_down_sync(0xffffffffu, rsum, 2);
    if (q == 0) atomicAdd(&g_rs_d[b * Nn + r0 + row], rsum);
    __syncthreads();
    float csum = 0.f;
    #pragma unroll
    for (int j = 0; j < 4; j++) {
        int idx4 = q + j * 4;
        csum += sh[idx4 * 4 + 0][row] + sh[idx4 * 4 + 1][row]
              + sh[idx4 * 4 + 2][row] + sh[idx4 * 4 + 3][row];
    }
    csum += __shfl_down_sync(0xffffffffu, csum, 1);
    csum += __shfl_down_sync(0xffffffffu, csum, 2);
    if (q == 0) atomicAdd(&g_cs_d[b * Nn + c0 + row], csum);
}

__global__ void prepS_k(const float* __restrict__ S) {
    const int r0 = blockIdx.x * 64, c0 = blockIdx.y * 64;
    const int tid = threadIdx.x;
    const int row = tid >> 2, q = tid & 3;
    float rsum = 0.f;
    #pragma unroll
    for (int j = 0; j < 4; j++) {
        int idx4 = q + j * 4;
        float4 v = *(const float4*)&S[(size_t)(r0 + row) * Nn + c0 + idx4 * 4];
        rsum += v.x + v.y + v.z + v.w;
        bf16 h0 = __float2bfloat16(v.x), h1 = __float2bfloat16(v.y);
        bf16 h2 = __float2bfloat16(v.z), h3 = __float2bfloat16(v.w);
        size_t o = (size_t)(r0 + row) * Nn + c0 + idx4 * 4;
        *(uint2*)&g_Shi[o] = make_uint2(bpack(h0, h1), bpack(h2, h3));
    }
    rsum += __shfl_down_sync(0xffffffffu, rsum, 1);
    rsum += __shfl_down_sync(0xffffffffu, rsum, 2);
    if (q == 0) atomicAdd(&g_rs_s[r0 + row], rsum);
}

__global__ void cvt_k(const float* __restrict__ A, bf16* __restrict__ hi,
                      bf16* __restrict__ lo, int n4) {
    int i = blockIdx.x * 256 + threadIdx.x;
    if (i >= n4) return;
    float4 a = ((const float4*)A)[i];
    bf16 h0, h1, h2, h3, l0, l1, l2, l3;
    bsplit(a.x, h0, l0); bsplit(a.y, h1, l1); bsplit(a.z, h2, l2); bsplit(a.w, h3, l3);
    ((uint2*)hi)[i] = make_uint2(bpack(h0, h1), bpack(h2, h3));
    ((uint2*)lo)[i] = make_uint2(bpack(l0, l1), bpack(l2, l3));
}

__global__ void embT_k(const float* __restrict__ spE, const float* __restrict__ tdE,
                       const float* __restrict__ twE) {
    int idx = blockIdx.x * 256 + threadIdx.x;
    if (idx >= Bb * 96 * (Nn / 4)) return;
    int n4 = idx % (Nn / 4);
    int rest = idx / (Nn / 4);
    int ch = rest % 96, b = rest / 96;
    const float* src = (ch < 32) ? spE : (ch < 64 ? tdE : twE);
    int c = ch & 31;
    float4 v = *(const float4*)(src + ((size_t)b * 32 + c) * Nn + n4 * 4);
    int oc = 32 + ch;
    float vv[4] = {v.x, v.y, v.z, v.w};
    size_t base = ((size_t)b * Nn + n4 * 4) * Hc + oc;
    #pragma unroll
    for (int u = 0; u < 4; u++) {
        bf16 h, l; bsplit(vv[u], h, l);
        g_in1Th[base + (size_t)u * Hc] = h;
        g_in1Tl[base + (size_t)u * Hc] = l;
    }
}

__global__ void combW_k(const float* __restrict__ W0, const float* __restrict__ W1,
                        const float* __restrict__ W2) {
    int idx = blockIdx.x * 256 + threadIdx.x;
    if (idx >= 3 * 32 * 224) return;
    int c = idx % 224;
    int m = (idx / 224) % 32;
    int i = idx / (224 * 32);
    const float* W[3] = {W0 + (size_t)i * 32 * 96, W1 + (size_t)i * 32 * 96, W2 + (size_t)i * 32 * 96};
    float v;
    if (c < 32) v = W[0][m * 96 + c] + W[1][m * 96 + c] + W[2][m * 96 + c];
    else {
        int t = c - 32, g = t >> 6, j = t & 63;
        v = W[g][m * 96 + 32 + j];
    }
    g_gWc[idx] = v;
}
__global__ void combB_k(const float* __restrict__ b0, const float* __restrict__ b1,
                        const float* __restrict__ b2) {
    int idx = threadIdx.x;
    if (idx < 96) g_gbc[idx] = b0[idx] + b1[idx] + b2[idx];
}

// ---------------- batched HMMA SpMM (A, H single-bf16) + fused epilogue ------
// gr==2 uses the SAME g_Ahi but transposed access via ldmatrix.trans.
__global__ void __launch_bounds__(256) spmm_mma(SpmmB args) {
    __shared__ bf16 sAh[64 * AP];
    __shared__ bf16 sHh[32 * AP];

    const int tid = threadIdx.x, wid = tid >> 5, lane = tid & 31;
    const int g = lane >> 2, tg = lane & 3;
    const int vt = blockIdx.x, b = blockIdx.y, gr = blockIdx.z;
    const int v0 = vt * 64;
    const int warpV = (wid >> 1) * 16;
    const int c0w = (wid & 1) * 16;
    const bool isT = (gr == 2);

    const bf16* Ah = args.A[gr] + (size_t)b * args.abst[gr];
    const bf16* Hh = args.H[gr] + (size_t)b * Ee * Nn;
    const float* hb = args.hin[gr] + (size_t)b * Ee * Nn;
    const float* den = args.den[gr];
    const int denB = args.denB[gr];

    const uint32_t sAh_u = smem_u32(sAh);
    const uint32_t sHh_u = smem_u32(sHh);
    // non-trans A fragment addresses (rows = v)
    const uint32_t offA_nt = (uint32_t)((warpV + (lane & 15)) * AP + (lane >> 4) * 8) * 2;
    // trans A fragment addresses (smem rows = w/k): lanes0-7 t0(k0,v), 8-15 t1(k0,v+8),
    // 16-23 t2(k8,v), 24-31 t3(k8,v+8)
    const uint32_t offA_t = (uint32_t)(((lane & 7) + ((lane >> 4) & 1) * 8) * AP
                                       + warpV + ((lane >> 3) & 1) * 8) * 2;
    const int rowB = c0w + (lane & 7) + ((lane >> 4) & 1) * 8;
    const int khB  = ((lane >> 3) & 1) * 8;
    const uint32_t offB = (uint32_t)(rowB * AP + khB) * 2;

    float4 acc[2] = {};

    int ar0 = tid >> 3,           au0 = tid & 7;
    int ar1 = (tid + 256) >> 3,   au1 = tid & 7;
    int hc  = tid >> 3,           hu = tid & 7;

    // staging pointers: non-trans rows are v (fixed), cols advance by w.
    // trans rows are w (advance), cols are v (fixed).
    const bf16* pA0 = isT ? (Ah + (size_t)ar0 * Nn + v0 + au0 * 8)
                          : (Ah + (size_t)(v0 + ar0) * Nn + au0 * 8);
    const bf16* pA1 = isT ? (Ah + (size_t)ar1 * Nn + v0 + au1 * 8)
                          : (Ah + (size_t)(v0 + ar1) * Nn + au1 * 8);
    const size_t chStride = isT ? (size_t)64 * Nn : 64;

    uint4 pAh0, pAh1, pHh;
    pAh0 = *(const uint4*)pA0;
    pAh1 = *(const uint4*)pA1;
    pHh  = *(const uint4*)(Hh + (size_t)hc * Nn + hu * 8);

    for (int ch = 0; ch < 32; ch++) {
        __syncthreads();
        *(uint4*)&sAh[ar0 * AP + au0 * 8] = pAh0;
        *(uint4*)&sAh[ar1 * AP + au1 * 8] = pAh1;
        *(uint4*)&sHh[hc * AP + hu * 8] = pHh;
        if (ch < 31) {
            pA0 += chStride;
            pA1 += chStride;
            pAh0 = *(const uint4*)pA0;
            pAh1 = *(const uint4*)pA1;
            pHh  = *(const uint4*)(Hh + (size_t)hc * Nn + (ch + 1) * 64 + hu * 8);
        }
        __syncthreads();
        if (isT) {
            #pragma unroll
            for (int ks = 0; ks < 4; ks++) {
                uint32_t ah0, ah1, ah2, ah3, bh00, bh01, bh10, bh11;
                ldm4t(ah0, ah1, ah2, ah3, sAh_u + offA_t + (uint32_t)ks * 16 * AP * 2);
                ldm4(bh00, bh01, bh10, bh11, sHh_u + offB + ks * 32);
                hmma(acc[0], ah0, ah1, ah2, ah3, bh00, bh01);
                hmma(acc[1], ah0, ah1, ah2, ah3, bh10, bh11);
            }
        } else {
            #pragma unroll
            for (int ks = 0; ks < 4; ks++) {
                uint32_t ah0, ah1, ah2, ah3, bh00, bh01, bh10, bh11;
                ldm4(ah0, ah1, ah2, ah3, sAh_u + offA_nt + ks * 32);
                ldm4(bh00, bh01, bh10, bh11, sHh_u + offB + ks * 32);
                hmma(acc[0], ah0, ah1, ah2, ah3, bh00, bh01);
                hmma(acc[1], ah0, ah1, ah2, ah3, bh10, bh11);
            }
        }
    }

    const int vlo = v0 + warpV + g;
    const int vhi = vlo + 8;
    const float dn_lo = den[denB * b + vlo];
    const float dn_hi = den[denB * b + vhi];
    const float* xb = g_x + (size_t)b * Ee * Nn;
    float* ob = args.hout[gr] + (size_t)b * Ee * Nn;
    bf16* oh = args.sOut[gr] + (size_t)b * Ee * Nn;
    #pragma unroll
    for (int nt = 0; nt < 2; nt++) {
        int c0 = c0w + nt * 8 + 2 * tg;
        float vals[4];
        size_t idxs[4];
        idxs[0] = (size_t)c0 * Nn + vlo;
        idxs[1] = (size_t)(c0 + 1) * Nn + vlo;
        idxs[2] = (size_t)c0 * Nn + vhi;
        idxs[3] = (size_t)(c0 + 1) * Nn + vhi;
        vals[0] = ALPHA * xb[idxs[0]] + (1.0f - ALPHA) * ((acc[nt].x + hb[idxs[0]]) / dn_lo);
        vals[1] = ALPHA * xb[idxs[1]] + (1.0f - ALPHA) * ((acc[nt].y + hb[idxs[1]]) / dn_lo);
        vals[2] = ALPHA * xb[idxs[2]] + (1.0f - ALPHA) * ((acc[nt].z + hb[idxs[2]]) / dn_hi);
        vals[3] = ALPHA * xb[idxs[3]] + (1.0f - ALPHA) * ((acc[nt].w + hb[idxs[3]]) / dn_hi);
        #pragma unroll
        for (int u = 0; u < 4; u++) {
            ob[idxs[u]] = vals[u];
            if (args.writeSplit) oh[idxs[u]] = __float2bfloat16(vals[u]);
        }
    }
}

// ---------------- HMMA gated conv ----------------
__global__ void __launch_bounds__(256) gated_mma(
        const bf16* __restrict__ inTh, const bf16* __restrict__ inTl,
        const bf16* __restrict__ Wfh, const bf16* __restrict__ Wfl,
        const bf16* __restrict__ Wgh, const bf16* __restrict__ Wgl,
        const float* __restrict__ bf_, const float* __restrict__ bg_,
        bf16* __restrict__ outTh, bf16* __restrict__ outTl) {
    __shared__ bf16 sWfh[Hc * CP], sWfl[Hc * CP], sWgh[Hc * CP], sWgl[Hc * CP];
    __shared__ bf16 sIh[64 * CP], sIl[64 * CP];

    const int tid = threadIdx.x, wid = tid >> 5, lane = tid & 31;
    const int g = lane >> 2, tg = lane & 3;
    const int col0 = blockIdx.x * 64;
    const int b = col0 / Nn, n0 = col0 % Nn;
    const int warpM = wid * 16;

    const uint32_t sWfh_u = smem_u32(sWfh), sWfl_u = smem_u32(sWfl);
    const uint32_t sWgh_u = smem_u32(sWgh), sWgl_u = smem_u32(sWgl);
    const uint32_t sIh_u = smem_u32(sIh), sIl_u = smem_u32(sIl);
    const uint32_t offA = (uint32_t)((warpM + (lane & 15)) * CP + (lane >> 4) * 8) * 2;
    const uint32_t offB = (uint32_t)(((lane & 7) + ((lane >> 4) & 1) * 8) * CP
                                     + ((lane >> 3) & 1) * 8) * 2;

    float4 aF[8] = {}, aG[8] = {};

    const int wrow = tid >> 1, whalf = tid & 1;
    const int it = tid & 127, iarr = tid >> 7;
    const int irow = it >> 1, ihalf = it & 1;
    const bf16* isrc = iarr ? inTl : inTh;
    bf16* idst = iarr ? sIl : sIh;

    for (int chunk = 0; chunk < 8; chunk++) {
        const int k0 = chunk * 16;
        __syncthreads();
        size_t wg = (size_t)wrow * Hc + k0 + whalf * 8;
        *(uint4*)&sWfh[wrow * CP + whalf * 8] = *(const uint4*)(Wfh + wg);
        *(uint4*)&sWfl[wrow * CP + whalf * 8] = *(const uint4*)(Wfl + wg);
        *(uint4*)&sWgh[wrow * CP + whalf * 8] = *(const uint4*)(Wgh + wg);
        *(uint4*)&sWgl[wrow * CP + whalf * 8] = *(const uint4*)(Wgl + wg);
        *(uint4*)&idst[irow * CP + ihalf * 8] =
            *(const uint4*)(isrc + ((size_t)b * Nn + n0 + irow) * Hc + k0 + ihalf * 8);
        __syncthreads();

        uint32_t fh0, fh1, fh2, fh3, fl0, fl1, fl2, fl3;
        uint32_t gh0, gh1, gh2, gh3, gl0, gl1, gl2, gl3;
        ldm4(fh0, fh1, fh2, fh3, sWfh_u + offA);
        ldm4(fl0, fl1, fl2, fl3, sWfl_u + offA);
        ldm4(gh0, gh1, gh2, gh3, sWgh_u + offA);
        ldm4(gl0, gl1, gl2, gl3, sWgl_u + offA);
        #pragma unroll
        for (int grp = 0; grp < 4; grp++) {
            const uint32_t go = (uint32_t)(grp * 16 * CP) * 2;
            uint32_t bh0, bh1, bh2, bh3, bl0, bl1, bl2, bl3;
            ldm4(bh0, bh1, bh2, bh3, sIh_u + go + offB);
            ldm4(bl0, bl1, bl2, bl3, sIl_u + go + offB);
            hmma(aF[2*grp], fh0, fh1, fh2, fh3, bh0, bh1);
            hmma(aF[2*grp], fh0, fh1, fh2, fh3, bl0, bl1);
            hmma(aF[2*grp], fl0, fl1, fl2, fl3, bh0, bh1);
            hmma(aF[2*grp+1], fh0, fh1, fh2, fh3, bh2, bh3);
            hmma(aF[2*grp+1], fh0, fh1, fh2, fh3, bl2, bl3);
            hmma(aF[2*grp+1], fl0, fl1, fl2, fl3, bh2, bh3);
            hmma(aG[2*grp], gh0, gh1, gh2, gh3, bh0, bh1);
            hmma(aG[2*grp], gh0, gh1, gh2, gh3, bl0, bl1);
            hmma(aG[2*grp], gl0, gl1, gl2, gl3, bh0, bh1);
            hmma(aG[2*grp+1], gh0, gh1, gh2, gh3, bh2, bh3);
            hmma(aG[2*grp+1], gh0, gh1, gh2, gh3, bl2, bl3);
            hmma(aG[2*grp+1], gl0, gl1, gl2, gl3, bh2, bh3);
        }
    }

    const int m_lo = warpM + g, m_hi = m_lo + 8;
    const float bflo = bf_[m_lo], bfhi = bf_[m_hi];
    const float bglo = bg_[m_lo], bghi = bg_[m_hi];
    #pragma unroll
    for (int nt = 0; nt < 8; nt++) {
        int n = n0 + nt * 8 + 2 * tg;
        size_t r0 = ((size_t)b * Nn + n) * Hc;
        size_t r1 = r0 + Hc;
        float v0 = tanhf(aF[nt].x + bflo) * (1.f / (1.f + expf(-(aG[nt].x + bglo))));
        float v1 = tanhf(aF[nt].y + bflo) * (1.f / (1.f + expf(-(aG[nt].y + bglo))));
        float v2 = tanhf(aF[nt].z + bfhi) * (1.f / (1.f + expf(-(aG[nt].z + bghi))));
        float v3 = tanhf(aF[nt].w + bfhi) * (1.f / (1.f + expf(-(aG[nt].w + bghi))));
        bf16 h, l;
        bsplit(v0, h, l); outTh[r0 + m_lo] = h; outTl[r0 + m_lo] = l;
        bsplit(v1, h, l); outTh[r1 + m_lo] = h; outTl[r1 + m_lo] = l;
        bsplit(v2, h, l); outTh[r0 + m_hi] = h; outTl[r0 + m_hi] = l;
        bsplit(v3, h, l); outTh[r1 + m_hi] = h; outTl[r1 + m_hi] = l;
    }
}

// ---------------- HMMA skip conv ----------------
__global__ void __launch_bounds__(256) skip_mma(
        const bf16* __restrict__ inTh, const bf16* __restrict__ inTl,
        const bf16* __restrict__ Wh, const bf16* __restrict__ Wl,
        const float* __restrict__ bias, float* __restrict__ out, int accFlag) {
    __shared__ bf16 sWh[Hc * CP], sWl[Hc * CP];
    __shared__ bf16 sIh[64 * CP], sIl[64 * CP];

    const int tid = threadIdx.x, wid = tid >> 5, lane = tid & 31;
    const int g = lane >> 2, tg = lane & 3;
    const int col0 = blockIdx.x * 64;
    const int b = col0 / Nn, n0 = col0 % Nn;
    const int mbase = blockIdx.y * 128;
    const int warpM = wid * 16;

    const uint32_t sWh_u = smem_u32(sWh), sWl_u = smem_u32(sWl);
    const uint32_t sIh_u = smem_u32(sIh), sIl_u = smem_u32(sIl);
    const uint32_t offA = (uint32_t)((warpM + (lane & 15)) * CP + (lane >> 4) * 8) * 2;
    const uint32_t offB = (uint32_t)(((lane & 7) + ((lane >> 4) & 1) * 8) * CP
                                     + ((lane >> 3) & 1) * 8) * 2;

    float4 acc[8] = {};

    const int wrow = tid >> 1, whalf = tid & 1;
    const int it = tid & 127, iarr = tid >> 7;
    const int irow = it >> 1, ihalf = it & 1;
    const bf16* isrc = iarr ? inTl : inTh;
    bf16* idst = iarr ? sIl : sIh;

    for (int chunk = 0; chunk < 8; chunk++) {
        const int k0 = chunk * 16;
        __syncthreads();
        size_t wg = (size_t)(mbase + wrow) * Hc + k0 + whalf * 8;
        *(uint4*)&sWh[wrow * CP + whalf * 8] = *(const uint4*)(Wh + wg);
        *(uint4*)&sWl[wrow * CP + whalf * 8] = *(const uint4*)(Wl + wg);
        *(uint4*)&idst[irow * CP + ihalf * 8] =
            *(const uint4*)(isrc + ((size_t)b * Nn + n0 + irow) * Hc + k0 + ihalf * 8);
        __syncthreads();

        uint32_t wh0, wh1, wh2, wh3, wl0, wl1, wl2, wl3;
        ldm4(wh0, wh1, wh2, wh3, sWh_u + offA);
        ldm4(wl0, wl1, wl2, wl3, sWl_u + offA);
        #pragma unroll
        for (int grp = 0; grp < 4; grp++) {
            const uint32_t go = (uint32_t)(grp * 16 * CP) * 2;
            uint32_t bh0, bh1, bh2, bh3, bl0, bl1, bl2, bl3;
            ldm4(bh0, bh1, bh2, bh3, sIh_u + go + offB);
            ldm4(bl0, bl1, bl2, bl3, sIl_u + go + offB);
            hmma(acc[2*grp], wh0, wh1, wh2, wh3, bh0, bh1);
            hmma(acc[2*grp], wh0, wh1, wh2, wh3, bl0, bl1);
            hmma(acc[2*grp], wl0, wl1, wl2, wl3, bh0, bh1);
            hmma(acc[2*grp+1], wh0, wh1, wh2, wh3, bh2, bh3);
            hmma(acc[2*grp+1], wh0, wh1, wh2, wh3, bl2, bl3);
            hmma(acc[2*grp+1], wl0, wl1, wl2, wl3, bh2, bh3);
        }
    }

    const int m_lo = mbase + warpM + g, m_hi = m_lo + 8;
    const float blo = bias[m_lo], bhi = bias[m_hi];
    #pragma unroll
    for (int nt = 0; nt < 8; nt++) {
        int n = n0 + nt * 8 + 2 * tg;
        float* d0 = &out[((size_t)b * Sc + m_lo) * Nn + n];
        float* d1 = &out[((size_t)b * Sc + m_hi) * Nn + n];
        float2 r0 = make_float2(acc[nt].x + blo, acc[nt].y + blo);
        float2 r1 = make_float2(acc[nt].z + bhi, acc[nt].w + bhi);
        if (accFlag) {
            float2 o0 = *(float2*)d0, o1 = *(float2*)d1;
            r0.x += o0.x; r0.y += o0.y; r1.x += o1.x; r1.y += o1.y;
        }
        *(float2*)d0 = r0;
        *(float2*)d1 = r1;
    }
}

// ---------------- generic 1x1 conv (f32x2 packed) with optional identity add --
__global__ void conv1x1_k(Srcs srcs, int inBStride,
                          const float* __restrict__ W, const float* __restrict__ bias,
                          int M, int K, float* __restrict__ out, int outBStride,
                          int accFlag, const float* __restrict__ iden) {
    __shared__ float Ws[16 * 68];
    __shared__ float Ins[16 * 68];
    const int tid = threadIdx.x;
    const int tx = tid & 15, ty = tid >> 4;
    const int col0 = blockIdx.x * 64;
    const int b = col0 / Nn, n0 = col0 % Nn;
    const int m0 = blockIdx.y * 64;

    u64 accP[4][2] = {};

    for (int k0 = 0; k0 < K; k0 += 16) {
        for (int t = tid; t < 1024; t += 256) {
            int m = t >> 4, kk = t & 15;
            Ws[kk * 68 + m] = (m0 + m < M) ? W[(size_t)(m0 + m) * K + k0 + kk] : 0.f;
        }
        for (int t = tid; t < 1024; t += 256) {
            int kk = t >> 6, n = t & 63;
            int c = k0 + kk;
            Ins[kk * 68 + n] = srcs.p[c >> 5][(size_t)b * inBStride + (size_t)(c & 31) * Nn + n0 + n];
        }
        __syncthreads();
        #pragma unroll
        for (int kk = 0; kk < 16; kk++) {
            float4 wv = *(const float4*)&Ws[kk * 68 + ty * 4];
            u64 ip0 = *(const u64*)&Ins[kk * 68 + tx * 4];
            u64 ip1 = *(const u64*)&Ins[kk * 68 + tx * 4 + 2];
            float wa[4] = {wv.x, wv.y, wv.z, wv.w};
            #pragma unroll
            for (int u = 0; u < 4; u++) {
                u64 wp = splat2(wa[u]);
                accP[u][0] = fma2(wp, ip0, accP[u][0]);
                accP[u][1] = fma2(wp, ip1, accP[u][1]);
            }
        }
        __syncthreads();
    }
    #pragma unroll
    for (int u = 0; u < 4; u++) {
        int m = m0 + ty * 4 + u;
        if (m >= M) break;
        float bm = bias[m];
        float4 r;
        upk2(accP[u][0], r.x, r.y);
        upk2(accP[u][1], r.z, r.w);
        r.x += bm; r.y += bm; r.z += bm; r.w += bm;
        float* dst = &out[(size_t)b * outBStride + (size_t)m * Nn + n0 + tx * 4];
        if (iden) {
            float4 o = *(const float4*)&iden[(size_t)b * outBStride + (size_t)m * Nn + n0 + tx * 4];
            r.x += o.x; r.y += o.y; r.z += o.z; r.w += o.w;
        }
        if (accFlag) {
            float4 o = *(float4*)dst;
            r.x += o.x; r.y += o.y; r.z += o.z; r.w += o.w;
        }
        *(float4*)dst = r;
    }
}

// ---------------- layernorm (two-stage) ----------------
__global__ void zero_red_k() {
    if (threadIdx.x < Bb * 2) g_red[threadIdx.x] = 0.f;
}
__global__ void ln_part_k() {
    int b = blockIdx.y, z = blockIdx.x;
    const float* xp = g_xacc + (size_t)b * Ee * Nn + (size_t)z * (Ee * Nn / 16);
    float s = 0.f, s2 = 0.f;
    for (int i = threadIdx.x; i < Ee * Nn / 16; i += 256) {
        float v = xp[i];
        s += v; s2 += v * v;
    }
    float ts = blockReduceSum(s);
    float ts2 = blockReduceSum(s2);
    if (threadIdx.x == 0) {
        atomicAdd(&g_red[b * 2], ts);
        atomicAdd(&g_red[b * 2 + 1], ts2);
    }
}

__global__ void ln_apply_k(const float* __restrict__ w, const float* __restrict__ bparm) {
    int i = blockIdx.x * 256 + threadIdx.x;
    if (i >= NEL) return;
    int b = i >> 16;
    int cn = i & (Ee * Nn - 1);
    float inv = 1.0f / (Ee * Nn);
    float mu = g_red[b * 2] * inv;
    float var = g_red[b * 2 + 1] * inv - mu * mu;
    float val = (g_xacc[i] - mu) * rsqrtf(var + EPSV) * w[cn] + bparm[cn];
    val = fmaxf(val, 0.f);
    g_x[i] = val;
    bf16 h, l; bsplit(val, h, l);
    g_sxHi[i] = h;
    int n = i & (Nn - 1);
    int c = (i >> 11) & 31;
    size_t o = ((size_t)b * Nn + n) * Hc + c;
    g_in1Th[o] = h;
    g_in1Tl[o] = l;
}

// ---------------- host orchestration ----------------
extern "C" void kernel_launch(void* const* d_in, const int* in_sizes, int n_in,
                              void* d_out, int out_size) {
    (void)in_sizes; (void)n_in; (void)out_size;
    const float* in_x  = (const float*)d_in[0];
    const float* dyG   = (const float*)d_in[1];
    const float* stG   = (const float*)d_in[2];
    const float* spE   = (const float*)d_in[3];
    const float* tdE   = (const float*)d_in[4];
    const float* twE   = (const float*)d_in[5];
    const float* encWf = (const float*)d_in[6];
    const float* encbf = (const float*)d_in[7];
    const float* encWg = (const float*)d_in[8];
    const float* encbg = (const float*)d_in[9];
    const float* skW   = (const float*)d_in[10];
    const float* skb   = (const float*)d_in[11];
    const float* nw    = (const float*)d_in[12];
    const float* nb    = (const float*)d_in[13];
    const float* gW[3] = {(const float*)d_in[14], (const float*)d_in[16], (const float*)d_in[18]};
    const float* gb[3] = {(const float*)d_in[15], (const float*)d_in[17], (const float*)d_in[19]};
    const float* seW   = (const float*)d_in[20];
    const float* seb   = (const float*)d_in[21];
    const float* eW    = (const float*)d_in[22];
    const float* eb    = (const float*)d_in[23];
    float* outp = (float*)d_out;

    float *px, *pxacc, *pskip, *prss, *prsd, *pcsd, *ph1g, *ph2g, *pgWc, *pgbc;
    cudaGetSymbolAddress((void**)&px,    g_x);
    cudaGetSymbolAddress((void**)&pxacc, g_xacc);
    cudaGetSymbolAddress((void**)&pskip, g_skip);
    cudaGetSymbolAddress((void**)&prss,  g_rs_s);
    cudaGetSymbolAddress((void**)&prsd,  g_rs_d);
    cudaGetSymbolAddress((void**)&pcsd,  g_cs_d);
    cudaGetSymbolAddress((void**)&ph1g,  g_h1g);
    cudaGetSymbolAddress((void**)&ph2g,  g_h2g);
    cudaGetSymbolAddress((void**)&pgWc,  g_gWc);
    cudaGetSymbolAddress((void**)&pgbc,  g_gbc);
    bf16 *pAhi, *pShi, *psxHi, *ps1Hi;
    cudaGetSymbolAddress((void**)&pAhi,  g_Ahi);
    cudaGetSymbolAddress((void**)&pShi,  g_Shi);
    cudaGetSymbolAddress((void**)&psxHi, g_sxHi);
    cudaGetSymbolAddress((void**)&ps1Hi, g_s1Hi);
    bf16 *pin1Th, *pin1Tl, *phidTh, *phidTl, *phid2Th, *phid2Tl;
    cudaGetSymbolAddress((void**)&pin1Th, g_in1Th);
    cudaGetSymbolAddress((void**)&pin1Tl, g_in1Tl);
    cudaGetSymbolAddress((void**)&phidTh, g_hidTh);
    cudaGetSymbolAddress((void**)&phidTl, g_hidTl);
    cudaGetSymbolAddress((void**)&phid2Th, g_hid2Th);
    cudaGetSymbolAddress((void**)&phid2Tl, g_hid2Tl);
    bf16 *peWfh, *peWfl, *peWgh, *peWgl, *pskWh, *pskWl;
    cudaGetSymbolAddress((void**)&peWfh, g_eWfh);
    cudaGetSymbolAddress((void**)&peWfl, g_eWfl);
    cudaGetSymbolAddress((void**)&peWgh, g_eWgh);
    cudaGetSymbolAddress((void**)&peWgl, g_eWgl);
    cudaGetSymbolAddress((void**)&pskWh, g_skWh);
    cudaGetSymbolAddress((void**)&pskWl, g_skWl);

    // ---- prep ----
    copy_split_k<<<(NEL / 4 + 255) / 256, 256>>>(px, in_x);
    init_den_k<<<(Bb * Nn + 255) / 256, 256>>>();
    prepA_k<<<dim3(Nn / 64, Nn / 64, Bb), 256>>>(dyG);
    prepS_k<<<dim3(Nn / 64, Nn / 64), 256>>>(stG);
    cvt_k<<<(6 * Hc * Hc / 4 + 255) / 256, 256>>>(encWf, peWfh, peWfl, 6 * Hc * Hc / 4);
    cvt_k<<<(6 * Hc * Hc / 4 + 255) / 256, 256>>>(encWg, peWgh, peWgl, 6 * Hc * Hc / 4);
    cvt_k<<<(3 * Sc * Hc / 4 + 255) / 256, 256>>>(skW, pskWh, pskWl, 3 * Sc * Hc / 4);
    embT_k<<<(Bb * 96 * (Nn / 4) + 255) / 256, 256>>>(spE, tdE, twE);
    combW_k<<<(3 * 32 * 224 + 255) / 256, 256>>>(gW[0], gW[1], gW[2]);
    combB_k<<<1, 96>>>(gb[0], gb[1], gb[2]);

    // shared SpMM arg skeleton (gr==2 reads g_Ahi transposed via ldmatrix.trans)
    SpmmB ab;
    ab.A[0] = pShi; ab.abst[0] = 0;            ab.den[0] = prss; ab.denB[0] = 0;
    ab.A[1] = pAhi; ab.abst[1] = (u64)Nn * Nn; ab.den[1] = prsd; ab.denB[1] = Nn;
    ab.A[2] = pAhi; ab.abst[2] = (u64)Nn * Nn; ab.den[2] = pcsd; ab.denB[2] = Nn;

    const dim3 convGrid(Bb * Nn / 64, 1);
    const dim3 spmmGrid(Nn / 64, Bb, 3);
    for (int i = 0; i < 3; i++) {
        // ---- TCN chain (HMMA) ----
        gated_mma<<<Bb * Nn / 64, 256>>>(pin1Th, pin1Tl,
            peWfh + (size_t)(i * 2 + 0) * Hc * Hc, peWfl + (size_t)(i * 2 + 0) * Hc * Hc,
            peWgh + (size_t)(i * 2 + 0) * Hc * Hc, peWgl + (size_t)(i * 2 + 0) * Hc * Hc,
            encbf + (i * 2 + 0) * Hc, encbg + (i * 2 + 0) * Hc, phidTh, phidTl);
        gated_mma<<<Bb * Nn / 64, 256>>>(phidTh, phidTl,
            peWfh + (size_t)(i * 2 + 1) * Hc * Hc, peWfl + (size_t)(i * 2 + 1) * Hc * Hc,
            peWgh + (size_t)(i * 2 + 1) * Hc * Hc, peWgl + (size_t)(i * 2 + 1) * Hc * Hc,
            encbf + (i * 2 + 1) * Hc, encbg + (i * 2 + 1) * Hc, phid2Th, phid2Tl);
        // ---- skip += skip_W @ hidden (HMMA) ----
        skip_mma<<<dim3(Bb * Nn / 64, 2), 256>>>(phid2Th, phid2Tl,
            pskWh + (size_t)i * Sc * Hc, pskWl + (size_t)i * Sc * Hc,
            skb + i * Sc, pskip, i > 0);
        // ---- mixprop hops: batched over 3 graphs ----
        SpmmB a1 = ab;
        for (int g = 0; g < 3; g++) {
            a1.H[g] = psxHi;
            a1.hin[g] = px;
            a1.hout[g] = ph1g + (size_t)g * NEL;
            a1.sOut[g] = ps1Hi + (size_t)g * NEL;
        }
        a1.writeSplit = 1;
        spmm_mma<<<spmmGrid, 256>>>(a1);
        SpmmB a2 = ab;
        for (int g = 0; g < 3; g++) {
            a2.H[g] = ps1Hi + (size_t)g * NEL;
            a2.hin[g] = ph1g + (size_t)g * NEL;
            a2.hout[g] = ph2g + (size_t)g * NEL;
            a2.sOut[g] = ps1Hi + (size_t)g * NEL;  // unused
        }
        a2.writeSplit = 0;
        spmm_mma<<<spmmGrid, 256>>>(a2);
        // ---- combined mixprop MLP: xacc = x + Wc @ [x,h1g0,h2g0,...] + bc ----
        Srcs sm;
        sm.p[0] = px;
        sm.p[1] = ph1g + 0 * NEL; sm.p[2] = ph2g + 0 * NEL;
        sm.p[3] = ph1g + 1 * NEL; sm.p[4] = ph2g + 1 * NEL;
        sm.p[5] = ph1g + 2 * NEL; sm.p[6] = ph2g + 2 * NEL;
        conv1x1_k<<<convGrid, 256>>>(sm, Ee * Nn,
            pgWc + (size_t)i * 32 * 224, pgbc + i * 32, Ee, 224, pxacc, Ee * Nn, 0, px);
        // ---- layernorm + relu (two-stage stats) ----
        zero_red_k<<<1, 32>>>();
        ln_part_k<<<dim3(16, Bb), 256>>>();
        ln_apply_k<<<NEL / 256, 256>>>(nw + (size_t)i * Ee * Nn, nb + (size_t)i * Ee * Nn);
    }
    // ---- skip end + output ----
    Srcs se; se.p[0] = px;
    conv1x1_k<<<dim3(Bb * Nn / 64, 4), 256>>>(se, Ee * Nn, seW, seb, Sc, Ee, pskip, Sc * Nn, 1, nullptr);
    Srcs send; for (int s = 0; s < 8; s++) send.p[s] = pskip + (size_t)s * 32 * Nn;
    conv1x1_k<<<convGrid, 256>>>(send, Sc * Nn, eW, eb, Tt, Sc, outp, Tt * Nn, 0, nullptr);
}

// round 15
// speedup vs baseline: 3.1374x; 1.0174x over previous
#include <cuda_runtime.h>
#include <cuda_bf16.h>
#include <math.h>
#include <stdint.h>

#define Bb 8
#define Nn 2048
#define Ee 32
#define Hc 128
#define Sc 256
#define Tt 12
#define NEL (Bb*Ee*Nn)
#define ALPHA 0.05f
#define EPSV 1e-5f
#define AP 72   // spmm smem pitch bf16 (144B)
#define CP 24   // conv smem pitch bf16 (48B)

typedef unsigned long long u64;
typedef __nv_bfloat16 bf16;

// ---------------- packed fp32x2 helpers ----------------
__device__ __forceinline__ u64 splat2(float a) {
    u64 d; asm("mov.b64 %0, {%1, %1};" : "=l"(d) : "f"(a)); return d;
}
__device__ __forceinline__ void upk2(u64 v, float& lo, float& hi) {
    asm("mov.b64 {%0, %1}, %2;" : "=f"(lo), "=f"(hi) : "l"(v));
}
__device__ __forceinline__ u64 fma2(u64 a, u64 b, u64 c) {
    u64 d; asm("fma.rn.f32x2 %0, %1, %2, %3;" : "=l"(d) : "l"(a), "l"(b), "l"(c)); return d;
}

// ---------------- warp-level bf16 MMA + ldmatrix ----------------
__device__ __forceinline__ void hmma(float4& d, uint32_t a0, uint32_t a1, uint32_t a2,
                                     uint32_t a3, uint32_t b0, uint32_t b1) {
    asm volatile(
        "mma.sync.aligned.m16n8k16.row.col.f32.bf16.bf16.f32 "
        "{%0,%1,%2,%3}, {%4,%5,%6,%7}, {%8,%9}, {%0,%1,%2,%3};"
        : "+f"(d.x), "+f"(d.y), "+f"(d.z), "+f"(d.w)
        : "r"(a0), "r"(a1), "r"(a2), "r"(a3), "r"(b0), "r"(b1));
}
__device__ __forceinline__ void ldm4(uint32_t& r0, uint32_t& r1, uint32_t& r2, uint32_t& r3,
                                     uint32_t addr) {
    asm volatile("ldmatrix.sync.aligned.m8n8.x4.shared.b16 {%0,%1,%2,%3}, [%4];"
        : "=r"(r0), "=r"(r1), "=r"(r2), "=r"(r3) : "r"(addr));
}
__device__ __forceinline__ void ldm4t(uint32_t& r0, uint32_t& r1, uint32_t& r2, uint32_t& r3,
                                      uint32_t addr) {
    asm volatile("ldmatrix.sync.aligned.m8n8.x4.trans.shared.b16 {%0,%1,%2,%3}, [%4];"
        : "=r"(r0), "=r"(r1), "=r"(r2), "=r"(r3) : "r"(addr));
}
__device__ __forceinline__ uint32_t smem_u32(const void* p) {
    uint32_t a;
    asm("{ .reg .u64 t; cvta.to.shared.u64 t, %1; cvt.u32.u64 %0, t; }" : "=r"(a) : "l"(p));
    return a;
}

// ---------------- device scratch ----------------
__device__ float g_x[NEL];
__device__ float g_xacc[NEL];
__device__ float g_h1g[3][NEL];
__device__ float g_h2g[3][NEL];
__device__ float g_skip[Bb*Sc*Nn];
__device__ float g_rs_s[Nn];
__device__ float g_rs_d[Bb*Nn];
__device__ float g_cs_d[Bb*Nn];
__device__ float g_redL[3][Bb*2];
__device__ bf16 g_Ahi[Bb*Nn*Nn];   // stores A + I (self-loop folded)
__device__ bf16 g_Shi[Nn*Nn];      // stores S + I
__device__ bf16 g_sxHi[NEL];
__device__ bf16 g_s1Hi[3][NEL];
// transposed-split activations [b][n][128]
__device__ bf16 g_in1Th[Bb*Nn*Hc];
__device__ bf16 g_in1Tl[Bb*Nn*Hc];
__device__ bf16 g_hidTh[Bb*Nn*Hc];
__device__ bf16 g_hidTl[Bb*Nn*Hc];
__device__ bf16 g_hid2Th[Bb*Nn*Hc];
__device__ bf16 g_hid2Tl[Bb*Nn*Hc];
// split weights
__device__ bf16 g_eWfh[6*Hc*Hc];
__device__ bf16 g_eWfl[6*Hc*Hc];
__device__ bf16 g_eWgh[6*Hc*Hc];
__device__ bf16 g_eWgl[6*Hc*Hc];
__device__ bf16 g_skWh[3*Sc*Hc];
__device__ bf16 g_skWl[3*Sc*Hc];
// combined mixprop mlp weights
__device__ float g_gWc[3*32*224];
__device__ float g_gbc[96];

struct Srcs { const float* p[8]; };
struct SpmmB {
    const bf16* A[3];
    u64 abst[3];
    const float* den[3];
    int denB[3];
    const bf16* H[3];
    float* hout[3];
    bf16* sOut[3];
    int writeSplit;
};

__device__ __forceinline__ void bsplit(float a, bf16& h, bf16& l) {
    h = __float2bfloat16(a);
    l = __float2bfloat16(a - __bfloat162float(h));
}
__device__ __forceinline__ uint32_t bpack(bf16 a, bf16 b) {
    __nv_bfloat162 t; t.x = a; t.y = b;
    return *reinterpret_cast<uint32_t*>(&t);
}

// ---------------- helpers ----------------
__device__ __forceinline__ float blockReduceSum(float v) {
    __shared__ float sh[32];
    int lane = threadIdx.x & 31, wid = threadIdx.x >> 5;
    #pragma unroll
    for (int o = 16; o; o >>= 1) v += __shfl_down_sync(0xffffffffu, v, o);
    __syncthreads();
    if (lane == 0) sh[wid] = v;
    __syncthreads();
    int nw = blockDim.x >> 5;
    v = (threadIdx.x < nw) ? sh[threadIdx.x] : 0.f;
    if (wid == 0) {
        #pragma unroll
        for (int o = 16; o; o >>= 1) v += __shfl_down_sync(0xffffffffu, v, o);
    }
    return v;
}

__global__ void copy_split_k(float* __restrict__ dst, const float* __restrict__ src) {
    int i = blockIdx.x * 256 + threadIdx.x;
    if (i >= NEL / 4) return;
    float4 a = ((const float4*)src)[i];
    ((float4*)dst)[i] = a;
    bf16 h[4], l[4];
    bsplit(a.x, h[0], l[0]); bsplit(a.y, h[1], l[1]);
    bsplit(a.z, h[2], l[2]); bsplit(a.w, h[3], l[3]);
    ((uint2*)g_sxHi)[i] = make_uint2(bpack(h[0], h[1]), bpack(h[2], h[3]));
    int n4 = i % (Nn / 4);
    int c  = (i / (Nn / 4)) % Ee;
    int b  = i / (Ee * Nn / 4);
    size_t base = ((size_t)b * Nn + n4 * 4) * Hc + c;
    #pragma unroll
    for (int u = 0; u < 4; u++) {
        g_in1Th[base + (size_t)u * Hc] = h[u];
        g_in1Tl[base + (size_t)u * Hc] = l[u];
    }
}

// ---------------- fused prep ----------------
__global__ void init_den_k() {
    int i = blockIdx.x * 256 + threadIdx.x;
    if (i < Nn) g_rs_s[i] = 1.0f;
    if (i < Bb * Nn) { g_rs_d[i] = 1.0f; g_cs_d[i] = 1.0f; }
    if (i < 3 * Bb * 2) ((float*)g_redL)[i] = 0.f;
}

// one pass over dyG: bf16 (A+I), rowsum, colsum
__global__ void prepA_k(const float* __restrict__ A) {
    __shared__ float sh[64][68];
    const int b = blockIdx.z;
    const int r0 = blockIdx.x * 64, c0 = blockIdx.y * 64;
    const int tid = threadIdx.x;
    const int row = tid >> 2, q = tid & 3;

    const float* Ab = A + (size_t)b * Nn * Nn;
    float rsum = 0.f;
    #pragma unroll
    for (int j = 0; j < 4; j++) {
        int idx4 = q + j * 4;
        float4 v = *(const float4*)&Ab[(size_t)(r0 + row) * Nn + c0 + idx4 * 4];
        *(float4*)&sh[row][idx4 * 4] = v;
        rsum += v.x + v.y + v.z + v.w;
        int gr = r0 + row, gc = c0 + idx4 * 4;
        float vv[4] = {v.x, v.y, v.z, v.w};
        #pragma unroll
        for (int u = 0; u < 4; u++) if (gr == gc + u) vv[u] += 1.0f;
        bf16 h0 = __float2bfloat16(vv[0]), h1 = __float2bfloat16(vv[1]);
        bf16 h2 = __float2bfloat16(vv[2]), h3 = __float2bfloat16(vv[3]);
        size_t o = ((size_t)b * Nn + gr) * Nn + gc;
        *(uint2*)&g_Ahi[o] = make_uint2(bpack(h0, h1), bpack(h2, h3));
    }
    rsum += __shfl_down_sync(0xffffffffu, rsum, 1);
    rsum += __shfl_down_sync(0xffffffffu, rsum, 2);
    if (q == 0) atomicAdd(&g_rs_d[b * Nn + r0 + row], rsum);
    __syncthreads();
    float csum = 0.f;
    #pragma unroll
    for (int j = 0; j < 4; j++) {
        int idx4 = q + j * 4;
        csum += sh[idx4 * 4 + 0][row] + sh[idx4 * 4 + 1][row]
              + sh[idx4 * 4 + 2][row] + sh[idx4 * 4 + 3][row];
    }
    csum += __shfl_down_sync(0xffffffffu, csum, 1);
    csum += __shfl_down_sync(0xffffffffu, csum, 2);
    if (q == 0) atomicAdd(&g_cs_d[b * Nn + c0 + row], csum);
}

__global__ void prepS_k(const float* __restrict__ S) {
    const int r0 = blockIdx.x * 64, c0 = blockIdx.y * 64;
    const int tid = threadIdx.x;
    const int row = tid >> 2, q = tid & 3;
    float rsum = 0.f;
    #pragma unroll
    for (int j = 0; j < 4; j++) {
        int idx4 = q + j * 4;
        float4 v = *(const float4*)&S[(size_t)(r0 + row) * Nn + c0 + idx4 * 4];
        rsum += v.x + v.y + v.z + v.w;
        int gr = r0 + row, gc = c0 + idx4 * 4;
        float vv[4] = {v.x, v.y, v.z, v.w};
        #pragma unroll
        for (int u = 0; u < 4; u++) if (gr == gc + u) vv[u] += 1.0f;
        bf16 h0 = __float2bfloat16(vv[0]), h1 = __float2bfloat16(vv[1]);
        bf16 h2 = __float2bfloat16(vv[2]), h3 = __float2bfloat16(vv[3]);
        size_t o = (size_t)gr * Nn + gc;
        *(uint2*)&g_Shi[o] = make_uint2(bpack(h0, h1), bpack(h2, h3));
    }
    rsum += __shfl_down_sync(0xffffffffu, rsum, 1);
    rsum += __shfl_down_sync(0xffffffffu, rsum, 2);
    if (q == 0) atomicAdd(&g_rs_s[r0 + row], rsum);
}

__global__ void cvt_k(const float* __restrict__ A, bf16* __restrict__ hi,
                      bf16* __restrict__ lo, int n4) {
    int i = blockIdx.x * 256 + threadIdx.x;
    if (i >= n4) return;
    float4 a = ((const float4*)A)[i];
    bf16 h0, h1, h2, h3, l0, l1, l2, l3;
    bsplit(a.x, h0, l0); bsplit(a.y, h1, l1); bsplit(a.z, h2, l2); bsplit(a.w, h3, l3);
    ((uint2*)hi)[i] = make_uint2(bpack(h0, h1), bpack(h2, h3));
    ((uint2*)lo)[i] = make_uint2(bpack(l0, l1), bpack(l2, l3));
}

__global__ void embT_k(const float* __restrict__ spE, const float* __restrict__ tdE,
                       const float* __restrict__ twE) {
    int idx = blockIdx.x * 256 + threadIdx.x;
    if (idx >= Bb * 96 * (Nn / 4)) return;
    int n4 = idx % (Nn / 4);
    int rest = idx / (Nn / 4);
    int ch = rest % 96, b = rest / 96;
    const float* src = (ch < 32) ? spE : (ch < 64 ? tdE : twE);
    int c = ch & 31;
    float4 v = *(const float4*)(src + ((size_t)b * 32 + c) * Nn + n4 * 4);
    int oc = 32 + ch;
    float vv[4] = {v.x, v.y, v.z, v.w};
    size_t base = ((size_t)b * Nn + n4 * 4) * Hc + oc;
    #pragma unroll
    for (int u = 0; u < 4; u++) {
        bf16 h, l; bsplit(vv[u], h, l);
        g_in1Th[base + (size_t)u * Hc] = h;
        g_in1Tl[base + (size_t)u * Hc] = l;
    }
}

__global__ void combW_k(const float* __restrict__ W0, const float* __restrict__ W1,
                        const float* __restrict__ W2) {
    int idx = blockIdx.x * 256 + threadIdx.x;
    if (idx >= 3 * 32 * 224) return;
    int c = idx % 224;
    int m = (idx / 224) % 32;
    int i = idx / (224 * 32);
    const float* W[3] = {W0 + (size_t)i * 32 * 96, W1 + (size_t)i * 32 * 96, W2 + (size_t)i * 32 * 96};
    float v;
    if (c < 32) v = W[0][m * 96 + c] + W[1][m * 96 + c] + W[2][m * 96 + c];
    else {
        int t = c - 32, g = t >> 6, j = t & 63;
        v = W[g][m * 96 + 32 + j];
    }
    g_gWc[idx] = v;
}
__global__ void combB_k(const float* __restrict__ b0, const float* __restrict__ b1,
                        const float* __restrict__ b2) {
    int idx = threadIdx.x;
    if (idx < 96) g_gbc[idx] = b0[idx] + b1[idx] + b2[idx];
}

// ---------------- batched HMMA SpMM with A+I folded ------
// gr==2 reads the same g_Ahi transposed via ldmatrix.trans.
// D = (A+I) h; hout = ALPHA*x + (1-ALPHA)*D/den.
__global__ void __launch_bounds__(256) spmm_mma(SpmmB args) {
    __shared__ bf16 sAh[64 * AP];
    __shared__ bf16 sHh[32 * AP];

    const int tid = threadIdx.x, wid = tid >> 5, lane = tid & 31;
    const int g = lane >> 2, tg = lane & 3;
    const int vt = blockIdx.x, b = blockIdx.y, gr = blockIdx.z;
    const int v0 = vt * 64;
    const int warpV = (wid >> 1) * 16;
    const int c0w = (wid & 1) * 16;
    const bool isT = (gr == 2);

    const bf16* Ah = args.A[gr] + (size_t)b * args.abst[gr];
    const bf16* Hh = args.H[gr] + (size_t)b * Ee * Nn;
    const float* den = args.den[gr];
    const int denB = args.denB[gr];

    const uint32_t sAh_u = smem_u32(sAh);
    const uint32_t sHh_u = smem_u32(sHh);
    const uint32_t offA_nt = (uint32_t)((warpV + (lane & 15)) * AP + (lane >> 4) * 8) * 2;
    const uint32_t offA_t = (uint32_t)(((lane & 7) + ((lane >> 4) & 1) * 8) * AP
                                       + warpV + ((lane >> 3) & 1) * 8) * 2;
    const int rowB = c0w + (lane & 7) + ((lane >> 4) & 1) * 8;
    const int khB  = ((lane >> 3) & 1) * 8;
    const uint32_t offB = (uint32_t)(rowB * AP + khB) * 2;

    float4 acc[2] = {};

    int ar0 = tid >> 3,           au0 = tid & 7;
    int ar1 = (tid + 256) >> 3,   au1 = tid & 7;
    int hc  = tid >> 3,           hu = tid & 7;

    const bf16* pA0 = isT ? (Ah + (size_t)ar0 * Nn + v0 + au0 * 8)
                          : (Ah + (size_t)(v0 + ar0) * Nn + au0 * 8);
    const bf16* pA1 = isT ? (Ah + (size_t)ar1 * Nn + v0 + au1 * 8)
                          : (Ah + (size_t)(v0 + ar1) * Nn + au1 * 8);
    const size_t chStride = isT ? (size_t)64 * Nn : 64;

    uint4 pAh0, pAh1, pHh;
    pAh0 = *(const uint4*)pA0;
    pAh1 = *(const uint4*)pA1;
    pHh  = *(const uint4*)(Hh + (size_t)hc * Nn + hu * 8);

    for (int ch = 0; ch < 32; ch++) {
        __syncthreads();
        *(uint4*)&sAh[ar0 * AP + au0 * 8] = pAh0;
        *(uint4*)&sAh[ar1 * AP + au1 * 8] = pAh1;
        *(uint4*)&sHh[hc * AP + hu * 8] = pHh;
        if (ch < 31) {
            pA0 += chStride;
            pA1 += chStride;
            pAh0 = *(const uint4*)pA0;
            pAh1 = *(const uint4*)pA1;
            pHh  = *(const uint4*)(Hh + (size_t)hc * Nn + (ch + 1) * 64 + hu * 8);
        }
        __syncthreads();
        if (isT) {
            #pragma unroll
            for (int ks = 0; ks < 4; ks++) {
                uint32_t ah0, ah1, ah2, ah3, bh00, bh01, bh10, bh11;
                ldm4t(ah0, ah1, ah2, ah3, sAh_u + offA_t + (uint32_t)ks * 16 * AP * 2);
                ldm4(bh00, bh01, bh10, bh11, sHh_u + offB + ks * 32);
                hmma(acc[0], ah0, ah1, ah2, ah3, bh00, bh01);
                hmma(acc[1], ah0, ah1, ah2, ah3, bh10, bh11);
            }
        } else {
            #pragma unroll
            for (int ks = 0; ks < 4; ks++) {
                uint32_t ah0, ah1, ah2, ah3, bh00, bh01, bh10, bh11;
                ldm4(ah0, ah1, ah2, ah3, sAh_u + offA_nt + ks * 32);
                ldm4(bh00, bh01, bh10, bh11, sHh_u + offB + ks * 32);
                hmma(acc[0], ah0, ah1, ah2, ah3, bh00, bh01);
                hmma(acc[1], ah0, ah1, ah2, ah3, bh10, bh11);
            }
        }
    }

    const int vlo = v0 + warpV + g;
    const int vhi = vlo + 8;
    const float rd_lo = (1.0f - ALPHA) / den[denB * b + vlo];
    const float rd_hi = (1.0f - ALPHA) / den[denB * b + vhi];
    const float* xb = g_x + (size_t)b * Ee * Nn;
    float* ob = args.hout[gr] + (size_t)b * Ee * Nn;
    bf16* oh = args.sOut[gr] + (size_t)b * Ee * Nn;
    #pragma unroll
    for (int nt = 0; nt < 2; nt++) {
        int c0 = c0w + nt * 8 + 2 * tg;
        float vals[4];
        size_t idxs[4];
        idxs[0] = (size_t)c0 * Nn + vlo;
        idxs[1] = (size_t)(c0 + 1) * Nn + vlo;
        idxs[2] = (size_t)c0 * Nn + vhi;
        idxs[3] = (size_t)(c0 + 1) * Nn + vhi;
        vals[0] = ALPHA * xb[idxs[0]] + acc[nt].x * rd_lo;
        vals[1] = ALPHA * xb[idxs[1]] + acc[nt].y * rd_lo;
        vals[2] = ALPHA * xb[idxs[2]] + acc[nt].z * rd_hi;
        vals[3] = ALPHA * xb[idxs[3]] + acc[nt].w * rd_hi;
        #pragma unroll
        for (int u = 0; u < 4; u++) {
            ob[idxs[u]] = vals[u];
            if (args.writeSplit) oh[idxs[u]] = __float2bfloat16(vals[u]);
        }
    }
}

// ---------------- HMMA gated conv ----------------
__global__ void __launch_bounds__(256) gated_mma(
        const bf16* __restrict__ inTh, const bf16* __restrict__ inTl,
        const bf16* __restrict__ Wfh, const bf16* __restrict__ Wfl,
        const bf16* __restrict__ Wgh, const bf16* __restrict__ Wgl,
        const float* __restrict__ bf_, const float* __restrict__ bg_,
        bf16* __restrict__ outTh, bf16* __restrict__ outTl) {
    __shared__ bf16 sWfh[Hc * CP], sWfl[Hc * CP], sWgh[Hc * CP], sWgl[Hc * CP];
    __shared__ bf16 sIh[64 * CP], sIl[64 * CP];

    const int tid = threadIdx.x, wid = tid >> 5, lane = tid & 31;
    const int g = lane >> 2, tg = lane & 3;
    const int col0 = blockIdx.x * 64;
    const int b = col0 / Nn, n0 = col0 % Nn;
    const int warpM = wid * 16;

    const uint32_t sWfh_u = smem_u32(sWfh), sWfl_u = smem_u32(sWfl);
    const uint32_t sWgh_u = smem_u32(sWgh), sWgl_u = smem_u32(sWgl);
    const uint32_t sIh_u = smem_u32(sIh), sIl_u = smem_u32(sIl);
    const uint32_t offA = (uint32_t)((warpM + (lane & 15)) * CP + (lane >> 4) * 8) * 2;
    const uint32_t offB = (uint32_t)(((lane & 7) + ((lane >> 4) & 1) * 8) * CP
                                     + ((lane >> 3) & 1) * 8) * 2;

    float4 aF[8] = {}, aG[8] = {};

    const int wrow = tid >> 1, whalf = tid & 1;
    const int it = tid & 127, iarr = tid >> 7;
    const int irow = it >> 1, ihalf = it & 1;
    const bf16* isrc = iarr ? inTl : inTh;
    bf16* idst = iarr ? sIl : sIh;

    for (int chunk = 0; chunk < 8; chunk++) {
        const int k0 = chunk * 16;
        __syncthreads();
        size_t wg = (size_t)wrow * Hc + k0 + whalf * 8;
        *(uint4*)&sWfh[wrow * CP + whalf * 8] = *(const uint4*)(Wfh + wg);
        *(uint4*)&sWfl[wrow * CP + whalf * 8] = *(const uint4*)(Wfl + wg);
        *(uint4*)&sWgh[wrow * CP + whalf * 8] = *(const uint4*)(Wgh + wg);
        *(uint4*)&sWgl[wrow * CP + whalf * 8] = *(const uint4*)(Wgl + wg);
        *(uint4*)&idst[irow * CP + ihalf * 8] =
            *(const uint4*)(isrc + ((size_t)b * Nn + n0 + irow) * Hc + k0 + ihalf * 8);
        __syncthreads();

        uint32_t fh0, fh1, fh2, fh3, fl0, fl1, fl2, fl3;
        uint32_t gh0, gh1, gh2, gh3, gl0, gl1, gl2, gl3;
        ldm4(fh0, fh1, fh2, fh3, sWfh_u + offA);
        ldm4(fl0, fl1, fl2, fl3, sWfl_u + offA);
        ldm4(gh0, gh1, gh2, gh3, sWgh_u + offA);
        ldm4(gl0, gl1, gl2, gl3, sWgl_u + offA);
        #pragma unroll
        for (int grp = 0; grp < 4; grp++) {
            const uint32_t go = (uint32_t)(grp * 16 * CP) * 2;
            uint32_t bh0, bh1, bh2, bh3, bl0, bl1, bl2, bl3;
            ldm4(bh0, bh1, bh2, bh3, sIh_u + go + offB);
            ldm4(bl0, bl1, bl2, bl3, sIl_u + go + offB);
            hmma(aF[2*grp], fh0, fh1, fh2, fh3, bh0, bh1);
            hmma(aF[2*grp], fh0, fh1, fh2, fh3, bl0, bl1);
            hmma(aF[2*grp], fl0, fl1, fl2, fl3, bh0, bh1);
            hmma(aF[2*grp+1], fh0, fh1, fh2, fh3, bh2, bh3);
            hmma(aF[2*grp+1], fh0, fh1, fh2, fh3, bl2, bl3);
            hmma(aF[2*grp+1], fl0, fl1, fl2, fl3, bh2, bh3);
            hmma(aG[2*grp], gh0, gh1, gh2, gh3, bh0, bh1);
            hmma(aG[2*grp], gh0, gh1, gh2, gh3, bl0, bl1);
            hmma(aG[2*grp], gl0, gl1, gl2, gl3, bh0, bh1);
            hmma(aG[2*grp+1], gh0, gh1, gh2, gh3, bh2, bh3);
            hmma(aG[2*grp+1], gh0, gh1, gh2, gh3, bl2, bl3);
            hmma(aG[2*grp+1], gl0, gl1, gl2, gl3, bh2, bh3);
        }
    }

    const int m_lo = warpM + g, m_hi = m_lo + 8;
    const float bflo = bf_[m_lo], bfhi = bf_[m_hi];
    const float bglo = bg_[m_lo], bghi = bg_[m_hi];
    #pragma unroll
    for (int nt = 0; nt < 8; nt++) {
        int n = n0 + nt * 8 + 2 * tg;
        size_t r0 = ((size_t)b * Nn + n) * Hc;
        size_t r1 = r0 + Hc;
        float v0 = tanhf(aF[nt].x + bflo) * (1.f / (1.f + expf(-(aG[nt].x + bglo))));
        float v1 = tanhf(aF[nt].y + bflo) * (1.f / (1.f + expf(-(aG[nt].y + bglo))));
        float v2 = tanhf(aF[nt].z + bfhi) * (1.f / (1.f + expf(-(aG[nt].z + bghi))));
        float v3 = tanhf(aF[nt].w + bfhi) * (1.f / (1.f + expf(-(aG[nt].w + bghi))));
        bf16 h, l;
        bsplit(v0, h, l); outTh[r0 + m_lo] = h; outTl[r0 + m_lo] = l;
        bsplit(v1, h, l); outTh[r1 + m_lo] = h; outTl[r1 + m_lo] = l;
        bsplit(v2, h, l); outTh[r0 + m_hi] = h; outTl[r0 + m_hi] = l;
        bsplit(v3, h, l); outTh[r1 + m_hi] = h; outTl[r1 + m_hi] = l;
    }
}

// ---------------- HMMA skip conv ----------------
__global__ void __launch_bounds__(256) skip_mma(
        const bf16* __restrict__ inTh, const bf16* __restrict__ inTl,
        const bf16* __restrict__ Wh, const bf16* __restrict__ Wl,
        const float* __restrict__ bias, float* __restrict__ out, int accFlag) {
    __shared__ bf16 sWh[Hc * CP], sWl[Hc * CP];
    __shared__ bf16 sIh[64 * CP], sIl[64 * CP];

    const int tid = threadIdx.x, wid = tid >> 5, lane = tid & 31;
    const int g = lane >> 2, tg = lane & 3;
    const int col0 = blockIdx.x * 64;
    const int b = col0 / Nn, n0 = col0 % Nn;
    const int mbase = blockIdx.y * 128;
    const int warpM = wid * 16;

    const uint32_t sWh_u = smem_u32(sWh), sWl_u = smem_u32(sWl);
    const uint32_t sIh_u = smem_u32(sIh), sIl_u = smem_u32(sIl);
    const uint32_t offA = (uint32_t)((warpM + (lane & 15)) * CP + (lane >> 4) * 8) * 2;
    const uint32_t offB = (uint32_t)(((lane & 7) + ((lane >> 4) & 1) * 8) * CP
                                     + ((lane >> 3) & 1) * 8) * 2;

    float4 acc[8] = {};

    const int wrow = tid >> 1, whalf = tid & 1;
    const int it = tid & 127, iarr = tid >> 7;
    const int irow = it >> 1, ihalf = it & 1;
    const bf16* isrc = iarr ? inTl : inTh;
    bf16* idst = iarr ? sIl : sIh;

    for (int chunk = 0; chunk < 8; chunk++) {
        const int k0 = chunk * 16;
        __syncthreads();
        size_t wg = (size_t)(mbase + wrow) * Hc + k0 + whalf * 8;
        *(uint4*)&sWh[wrow * CP + whalf * 8] = *(const uint4*)(Wh + wg);
        *(uint4*)&sWl[wrow * CP + whalf * 8] = *(const uint4*)(Wl + wg);
        *(uint4*)&idst[irow * CP + ihalf * 8] =
            *(const uint4*)(isrc + ((size_t)b * Nn + n0 + irow) * Hc + k0 + ihalf * 8);
        __syncthreads();

        uint32_t wh0, wh1, wh2, wh3, wl0, wl1, wl2, wl3;
        ldm4(wh0, wh1, wh2, wh3, sWh_u + offA);
        ldm4(wl0, wl1, wl2, wl3, sWl_u + offA);
        #pragma unroll
        for (int grp = 0; grp < 4; grp++) {
            const uint32_t go = (uint32_t)(grp * 16 * CP) * 2;
            uint32_t bh0, bh1, bh2, bh3, bl0, bl1, bl2, bl3;
            ldm4(bh0, bh1, bh2, bh3, sIh_u + go + offB);
            ldm4(bl0, bl1, bl2, bl3, sIl_u + go + offB);
            hmma(acc[2*grp], wh0, wh1, wh2, wh3, bh0, bh1);
            hmma(acc[2*grp], wh0, wh1, wh2, wh3, bl0, bl1);
            hmma(acc[2*grp], wl0, wl1, wl2, wl3, bh0, bh1);
            hmma(acc[2*grp+1], wh0, wh1, wh2, wh3, bh2, bh3);
            hmma(acc[2*grp+1], wh0, wh1, wh2, wh3, bl2, bl3);
            hmma(acc[2*grp+1], wl0, wl1, wl2, wl3, bh2, bh3);
        }
    }

    const int m_lo = mbase + warpM + g, m_hi = m_lo + 8;
    const float blo = bias[m_lo], bhi = bias[m_hi];
    #pragma unroll
    for (int nt = 0; nt < 8; nt++) {
        int n = n0 + nt * 8 + 2 * tg;
        float* d0 = &out[((size_t)b * Sc + m_lo) * Nn + n];
        float* d1 = &out[((size_t)b * Sc + m_hi) * Nn + n];
        float2 r0 = make_float2(acc[nt].x + blo, acc[nt].y + blo);
        float2 r1 = make_float2(acc[nt].z + bhi, acc[nt].w + bhi);
        if (accFlag) {
            float2 o0 = *(float2*)d0, o1 = *(float2*)d1;
            r0.x += o0.x; r0.y += o0.y; r1.x += o1.x; r1.y += o1.y;
        }
        *(float2*)d0 = r0;
        *(float2*)d1 = r1;
    }
}

// ------- generic 1x1 conv (f32x2) with identity add + fused LN partial stats -
__global__ void conv1x1_k(Srcs srcs, int inBStride,
                          const float* __restrict__ W, const float* __restrict__ bias,
                          int M, int K, float* __restrict__ out, int outBStride,
                          int accFlag, const float* __restrict__ iden,
                          float* __restrict__ redOut) {
    __shared__ float Ws[16 * 68];
    __shared__ float Ins[16 * 68];
    const int tid = threadIdx.x;
    const int tx = tid & 15, ty = tid >> 4;
    const int col0 = blockIdx.x * 64;
    const int b = col0 / Nn, n0 = col0 % Nn;
    const int m0 = blockIdx.y * 64;

    u64 accP[4][2] = {};

    for (int k0 = 0; k0 < K; k0 += 16) {
        for (int t = tid; t < 1024; t += 256) {
            int m = t >> 4, kk = t & 15;
            Ws[kk * 68 + m] = (m0 + m < M) ? W[(size_t)(m0 + m) * K + k0 + kk] : 0.f;
        }
        for (int t = tid; t < 1024; t += 256) {
            int kk = t >> 6, n = t & 63;
            int c = k0 + kk;
            Ins[kk * 68 + n] = srcs.p[c >> 5][(size_t)b * inBStride + (size_t)(c & 31) * Nn + n0 + n];
        }
        __syncthreads();
        #pragma unroll
        for (int kk = 0; kk < 16; kk++) {
            float4 wv = *(const float4*)&Ws[kk * 68 + ty * 4];
            u64 ip0 = *(const u64*)&Ins[kk * 68 + tx * 4];
            u64 ip1 = *(const u64*)&Ins[kk * 68 + tx * 4 + 2];
            float wa[4] = {wv.x, wv.y, wv.z, wv.w};
            #pragma unroll
            for (int u = 0; u < 4; u++) {
                u64 wp = splat2(wa[u]);
                accP[u][0] = fma2(wp, ip0, accP[u][0]);
                accP[u][1] = fma2(wp, ip1, accP[u][1]);
            }
        }
        __syncthreads();
    }
    float lsum = 0.f, lsum2 = 0.f;
    #pragma unroll
    for (int u = 0; u < 4; u++) {
        int m = m0 + ty * 4 + u;
        if (m >= M) break;
        float bm = bias[m];
        float4 r;
        upk2(accP[u][0], r.x, r.y);
        upk2(accP[u][1], r.z, r.w);
        r.x += bm; r.y += bm; r.z += bm; r.w += bm;
        float* dst = &out[(size_t)b * outBStride + (size_t)m * Nn + n0 + tx * 4];
        if (iden) {
            float4 o = *(const float4*)&iden[(size_t)b * outBStride + (size_t)m * Nn + n0 + tx * 4];
            r.x += o.x; r.y += o.y; r.z += o.z; r.w += o.w;
        }
        if (accFlag) {
            float4 o = *(float4*)dst;
            r.x += o.x; r.y += o.y; r.z += o.z; r.w += o.w;
        }
        *(float4*)dst = r;
        if (redOut) {
            lsum += r.x + r.y + r.z + r.w;
            lsum2 += r.x * r.x + r.y * r.y + r.z * r.z + r.w * r.w;
        }
    }
    if (redOut) {
        float ts = blockReduceSum(lsum);
        __syncthreads();
        float ts2 = blockReduceSum(lsum2);
        if (tid == 0) {
            atomicAdd(&redOut[b * 2], ts);
            atomicAdd(&redOut[b * 2 + 1], ts2);
        }
    }
}

// ---------------- layernorm apply ----------------
__global__ void ln_apply_k(const float* __restrict__ w, const float* __restrict__ bparm,
                           const float* __restrict__ red) {
    int i = blockIdx.x * 256 + threadIdx.x;
    if (i >= NEL) return;
    int b = i >> 16;
    int cn = i & (Ee * Nn - 1);
    float inv = 1.0f / (Ee * Nn);
    float mu = red[b * 2] * inv;
    float var = red[b * 2 + 1] * inv - mu * mu;
    float val = (g_xacc[i] - mu) * rsqrtf(var + EPSV) * w[cn] + bparm[cn];
    val = fmaxf(val, 0.f);
    g_x[i] = val;
    bf16 h, l; bsplit(val, h, l);
    g_sxHi[i] = h;
    int n = i & (Nn - 1);
    int c = (i >> 11) & 31;
    size_t o = ((size_t)b * Nn + n) * Hc + c;
    g_in1Th[o] = h;
    g_in1Tl[o] = l;
}

// ---------------- host orchestration ----------------
extern "C" void kernel_launch(void* const* d_in, const int* in_sizes, int n_in,
                              void* d_out, int out_size) {
    (void)in_sizes; (void)n_in; (void)out_size;
    const float* in_x  = (const float*)d_in[0];
    const float* dyG   = (const float*)d_in[1];
    const float* stG   = (const float*)d_in[2];
    const float* spE   = (const float*)d_in[3];
    const float* tdE   = (const float*)d_in[4];
    const float* twE   = (const float*)d_in[5];
    const float* encWf = (const float*)d_in[6];
    const float* encbf = (const float*)d_in[7];
    const float* encWg = (const float*)d_in[8];
    const float* encbg = (const float*)d_in[9];
    const float* skW   = (const float*)d_in[10];
    const float* skb   = (const float*)d_in[11];
    const float* nw    = (const float*)d_in[12];
    const float* nb    = (const float*)d_in[13];
    const float* gW[3] = {(const float*)d_in[14], (const float*)d_in[16], (const float*)d_in[18]};
    const float* gb[3] = {(const float*)d_in[15], (const float*)d_in[17], (const float*)d_in[19]};
    const float* seW   = (const float*)d_in[20];
    const float* seb   = (const float*)d_in[21];
    const float* eW    = (const float*)d_in[22];
    const float* eb    = (const float*)d_in[23];
    float* outp = (float*)d_out;

    float *px, *pxacc, *pskip, *prss, *prsd, *pcsd, *ph1g, *ph2g, *pgWc, *pgbc, *predL;
    cudaGetSymbolAddress((void**)&px,    g_x);
    cudaGetSymbolAddress((void**)&pxacc, g_xacc);
    cudaGetSymbolAddress((void**)&pskip, g_skip);
    cudaGetSymbolAddress((void**)&prss,  g_rs_s);
    cudaGetSymbolAddress((void**)&prsd,  g_rs_d);
    cudaGetSymbolAddress((void**)&pcsd,  g_cs_d);
    cudaGetSymbolAddress((void**)&ph1g,  g_h1g);
    cudaGetSymbolAddress((void**)&ph2g,  g_h2g);
    cudaGetSymbolAddress((void**)&pgWc,  g_gWc);
    cudaGetSymbolAddress((void**)&pgbc,  g_gbc);
    cudaGetSymbolAddress((void**)&predL, g_redL);
    bf16 *pAhi, *pShi, *psxHi, *ps1Hi;
    cudaGetSymbolAddress((void**)&pAhi,  g_Ahi);
    cudaGetSymbolAddress((void**)&pShi,  g_Shi);
    cudaGetSymbolAddress((void**)&psxHi, g_sxHi);
    cudaGetSymbolAddress((void**)&ps1Hi, g_s1Hi);
    bf16 *pin1Th, *pin1Tl, *phidTh, *phidTl, *phid2Th, *phid2Tl;
    cudaGetSymbolAddress((void**)&pin1Th, g_in1Th);
    cudaGetSymbolAddress((void**)&pin1Tl, g_in1Tl);
    cudaGetSymbolAddress((void**)&phidTh, g_hidTh);
    cudaGetSymbolAddress((void**)&phidTl, g_hidTl);
    cudaGetSymbolAddress((void**)&phid2Th, g_hid2Th);
    cudaGetSymbolAddress((void**)&phid2Tl, g_hid2Tl);
    bf16 *peWfh, *peWfl, *peWgh, *peWgl, *pskWh, *pskWl;
    cudaGetSymbolAddress((void**)&peWfh, g_eWfh);
    cudaGetSymbolAddress((void**)&peWfl, g_eWfl);
    cudaGetSymbolAddress((void**)&peWgh, g_eWgh);
    cudaGetSymbolAddress((void**)&peWgl, g_eWgl);
    cudaGetSymbolAddress((void**)&pskWh, g_skWh);
    cudaGetSymbolAddress((void**)&pskWl, g_skWl);

    // ---- prep ----
    copy_split_k<<<(NEL / 4 + 255) / 256, 256>>>(px, in_x);
    init_den_k<<<(Bb * Nn + 255) / 256, 256>>>();
    prepA_k<<<dim3(Nn / 64, Nn / 64, Bb), 256>>>(dyG);
    prepS_k<<<dim3(Nn / 64, Nn / 64), 256>>>(stG);
    cvt_k<<<(6 * Hc * Hc / 4 + 255) / 256, 256>>>(encWf, peWfh, peWfl, 6 * Hc * Hc / 4);
    cvt_k<<<(6 * Hc * Hc / 4 + 255) / 256, 256>>>(encWg, peWgh, peWgl, 6 * Hc * Hc / 4);
    cvt_k<<<(3 * Sc * Hc / 4 + 255) / 256, 256>>>(skW, pskWh, pskWl, 3 * Sc * Hc / 4);
    embT_k<<<(Bb * 96 * (Nn / 4) + 255) / 256, 256>>>(spE, tdE, twE);
    combW_k<<<(3 * 32 * 224 + 255) / 256, 256>>>(gW[0], gW[1], gW[2]);
    combB_k<<<1, 96>>>(gb[0], gb[1], gb[2]);

    // shared SpMM arg skeleton (gr==2 reads g_Ahi transposed via ldmatrix.trans)
    SpmmB ab;
    ab.A[0] = pShi; ab.abst[0] = 0;            ab.den[0] = prss; ab.denB[0] = 0;
    ab.A[1] = pAhi; ab.abst[1] = (u64)Nn * Nn; ab.den[1] = prsd; ab.denB[1] = Nn;
    ab.A[2] = pAhi; ab.abst[2] = (u64)Nn * Nn; ab.den[2] = pcsd; ab.denB[2] = Nn;

    const dim3 convGrid(Bb * Nn / 64, 1);
    const dim3 spmmGrid(Nn / 64, Bb, 3);
    for (int i = 0; i < 3; i++) {
        // ---- TCN chain (HMMA) ----
        gated_mma<<<Bb * Nn / 64, 256>>>(pin1Th, pin1Tl,
            peWfh + (size_t)(i * 2 + 0) * Hc * Hc, peWfl + (size_t)(i * 2 + 0) * Hc * Hc,
            peWgh + (size_t)(i * 2 + 0) * Hc * Hc, peWgl + (size_t)(i * 2 + 0) * Hc * Hc,
            encbf + (i * 2 + 0) * Hc, encbg + (i * 2 + 0) * Hc, phidTh, phidTl);
        gated_mma<<<Bb * Nn / 64, 256>>>(phidTh, phidTl,
            peWfh + (size_t)(i * 2 + 1) * Hc * Hc, peWfl + (size_t)(i * 2 + 1) * Hc * Hc,
            peWgh + (size_t)(i * 2 + 1) * Hc * Hc, peWgl + (size_t)(i * 2 + 1) * Hc * Hc,
            encbf + (i * 2 + 1) * Hc, encbg + (i * 2 + 1) * Hc, phid2Th, phid2Tl);
        // ---- skip += skip_W @ hidden (HMMA) ----
        skip_mma<<<dim3(Bb * Nn / 64, 2), 256>>>(phid2Th, phid2Tl,
            pskWh + (size_t)i * Sc * Hc, pskWl + (size_t)i * Sc * Hc,
            skb + i * Sc, pskip, i > 0);
        // ---- mixprop hops: batched over 3 graphs, A+I folded ----
        SpmmB a1 = ab;
        for (int g = 0; g < 3; g++) {
            a1.H[g] = psxHi;
            a1.hout[g] = ph1g + (size_t)g * NEL;
            a1.sOut[g] = ps1Hi + (size_t)g * NEL;
        }
        a1.writeSplit = 1;
        spmm_mma<<<spmmGrid, 256>>>(a1);
        SpmmB a2 = ab;
        for (int g = 0; g < 3; g++) {
            a2.H[g] = ps1Hi + (size_t)g * NEL;
            a2.hout[g] = ph2g + (size_t)g * NEL;
            a2.sOut[g] = ps1Hi + (size_t)g * NEL;  // unused
        }
        a2.writeSplit = 0;
        spmm_mma<<<spmmGrid, 256>>>(a2);
        // ---- combined mixprop MLP + fused LN stats ----
        Srcs sm;
        sm.p[0] = px;
        sm.p[1] = ph1g + 0 * NEL; sm.p[2] = ph2g + 0 * NEL;
        sm.p[3] = ph1g + 1 * NEL; sm.p[4] = ph2g + 1 * NEL;
        sm.p[5] = ph1g + 2 * NEL; sm.p[6] = ph2g + 2 * NEL;
        conv1x1_k<<<convGrid, 256>>>(sm, Ee * Nn,
            pgWc + (size_t)i * 32 * 224, pgbc + i * 32, Ee, 224, pxacc, Ee * Nn, 0, px,
            predL + i * Bb * 2);
        // ---- layernorm + relu ----
        ln_apply_k<<<NEL / 256, 256>>>(nw + (size_t)i * Ee * Nn, nb + (size_t)i * Ee * Nn,
                                       predL + i * Bb * 2);
    }
    // ---- skip end + output ----
    Srcs se; se.p[0] = px;
    conv1x1_k<<<dim3(Bb * Nn / 64, 4), 256>>>(se, Ee * Nn, seW, seb, Sc, Ee, pskip, Sc * Nn, 1,
                                              nullptr, nullptr);
    Srcs send; for (int s = 0; s < 8; s++) send.p[s] = pskip + (size_t)s * 32 * Nn;
    conv1x1_k<<<convGrid, 256>>>(send, Sc * Nn, eW, eb, Tt, Sc, outp, Tt * Nn, 0,
                                 nullptr, nullptr);
}